// round 1
// baseline (speedup 1.0000x reference)
#include <cuda_runtime.h>
#include <math.h>

#define Dv    128
#define Mv    128
#define KTABv 64
#define Kv    32
#define Bv    2048
#define FEWv  5
#define DMv   256
#define HIDv  512
#define NSYMv 100000
#define NROWS (Bv + FEWv)   /* 2053 */
#define GWID  2048          /* 4*HID */

// ---------------- scratch (device globals; no runtime allocation) ----------
__device__ float g_X [NROWS * DMv];     // qn/sn, later overwritten by encoded E
__device__ float g_O [NROWS * DMv];     // support-encoder MLP output
__device__ float g_H [NROWS * HIDv];    // support-encoder hidden
__device__ float g_G0[(size_t)Bv * GWID]; // constant part of LSTM gates
__device__ float g_Gt[(size_t)Bv * GWID]; // per-step gates
__device__ float g_C [Bv * HIDv];       // LSTM cell state
__device__ float g_h [Bv * DMv];        // LSTM h
__device__ float g_sg [DMv];            // support_g
__device__ float g_sgn[DMv];            // l2-normalized support_g
__device__ float g_rterm[GWID];         // w_hh[:,256:] @ support_g

__device__ __forceinline__ float sigm(float x) { return 1.f / (1.f + expf(-x)); }

// ---------------- neighbor encoder -----------------------------------------
// one block (128 threads) per row
__global__ void ne_kernel(const int* __restrict__ conn,        // [N, M, 2]
                          const int* __restrict__ ids, int ids_stride, int ids_off,
                          const int* __restrict__ knn,         // [NSYM+1, KTAB]
                          const float* __restrict__ emb,
                          const float* __restrict__ gcn_w,     // [128,256]
                          const float* __restrict__ gcn_wb,
                          const float* __restrict__ gcn_b,
                          const float* __restrict__ gate_w,    // [256]
                          const float* __restrict__ gate_b,
                          float* __restrict__ outp, int out_col)
{
    __shared__ float s_center[Dv];
    __shared__ float s_pad[Dv];
    __shared__ float s_sims[Mv];
    __shared__ float s_sims2[KTABv];
    __shared__ int   s_rel[Mv], s_ent[Mv], s_kid[KTABv];
    __shared__ unsigned char s_sel[Mv], s_sel2[KTABv];
    __shared__ float s_mr[Dv], s_me[Dv], s_mk[Dv];
    __shared__ float s_st[Dv], s_kn[Dv];
    __shared__ float s_red[8];
    __shared__ float s_cn;

    const int row  = blockIdx.x;
    const int tid  = threadIdx.x;
    const int lane = tid & 31, wid = tid >> 5;

    const int id = ids[row * ids_stride + ids_off];
    const float cv = emb[(size_t)id * Dv + tid];
    s_center[tid] = cv;
    s_pad[tid]    = emb[(size_t)NSYMv * Dv + tid];

    // center norm (block reduce over 4 warps)
    float v = cv * cv;
    #pragma unroll
    for (int o = 16; o; o >>= 1) v += __shfl_xor_sync(0xffffffffu, v, o);
    if (lane == 0) s_red[wid] = v;
    if (tid < KTABv) s_kid[tid] = knn[(size_t)id * KTABv + tid];
    __syncthreads();
    if (tid == 0) s_cn = sqrtf(s_red[0] + s_red[1] + s_red[2] + s_red[3]);
    __syncthreads();
    const float cn = s_cn;

    // cosine sims vs conn entities (warp per m)
    for (int m = wid * 32; m < wid * 32 + 32; ++m) {
        int rel = conn[((size_t)row * Mv + m) * 2 + 0];
        int ent = conn[((size_t)row * Mv + m) * 2 + 1];
        if (lane == 0) { s_rel[m] = rel; s_ent[m] = ent; }
        const float* ev = emb + (size_t)ent * Dv;
        float dot = 0.f, nn = 0.f;
        #pragma unroll
        for (int q = 0; q < 4; ++q) {
            float e = ev[lane + q * 32];
            dot += s_center[lane + q * 32] * e;
            nn  += e * e;
        }
        #pragma unroll
        for (int o = 16; o; o >>= 1) {
            dot += __shfl_xor_sync(0xffffffffu, dot, o);
            nn  += __shfl_xor_sync(0xffffffffu, nn,  o);
        }
        if (lane == 0) s_sims[m] = dot / fmaxf(cn * sqrtf(nn), 1e-8f);
    }
    // cosine sims vs knn table entities
    for (int m = wid * 16; m < wid * 16 + 16; ++m) {
        const float* ev = emb + (size_t)s_kid[m] * Dv;
        float dot = 0.f, nn = 0.f;
        #pragma unroll
        for (int q = 0; q < 4; ++q) {
            float e = ev[lane + q * 32];
            dot += s_center[lane + q * 32] * e;
            nn  += e * e;
        }
        #pragma unroll
        for (int o = 16; o; o >>= 1) {
            dot += __shfl_xor_sync(0xffffffffu, dot, o);
            nn  += __shfl_xor_sync(0xffffffffu, nn,  o);
        }
        if (lane == 0) s_sims2[m] = dot / fmaxf(cn * sqrtf(nn), 1e-8f);
    }
    __syncthreads();

    // stable top-K selection (matches jax.lax.top_k tie-breaking)
    {
        float my = s_sims[tid];
        int cnt = 0;
        #pragma unroll 4
        for (int j = 0; j < Mv; ++j) {
            float o = s_sims[j];
            cnt += (o > my) || (o == my && j < tid);
        }
        s_sel[tid] = (cnt < Kv) ? 1 : 0;
    }
    if (tid < KTABv) {
        float my = s_sims2[tid];
        int cnt = 0;
        #pragma unroll 4
        for (int j = 0; j < KTABv; ++j) {
            float o = s_sims2[j];
            cnt += (o > my) || (o == my && j < tid);
        }
        s_sel2[tid] = (cnt < Kv) ? 1 : 0;
    }
    __syncthreads();

    // means over selected neighbors (tid = feature dim d; coalesced gathers)
    {
        float ar = 0.f, ae = 0.f, ak = 0.f;
        for (int m = 0; m < Mv; ++m) {
            if (s_sel[m]) {
                ar += emb[(size_t)s_rel[m] * Dv + tid];
                ae += emb[(size_t)s_ent[m] * Dv + tid];
            }
        }
        for (int m = 0; m < KTABv; ++m)
            if (s_sel2[m]) ak += emb[(size_t)s_kid[m] * Dv + tid];
        const float inv = 1.f / (float)Kv;
        s_mr[tid] = ar * inv; s_me[tid] = ae * inv; s_mk[tid] = ak * inv;
    }
    __syncthreads();

    // matvec: mean commutes with the linear layer
    {
        const float* wr = gcn_w + (size_t)tid * (2 * Dv);
        float b0 = gcn_wb[tid] + gcn_b[tid];
        float h1 = b0, h2 = b0;
        #pragma unroll 4
        for (int j = 0; j < Dv; ++j) {
            float w0 = wr[j], w1 = wr[Dv + j];
            h1 += s_mr[j]  * w0 + s_me[j] * w1;
            h2 += s_pad[j] * w0 + s_mk[j] * w1;
        }
        s_st[tid] = tanhf(h1);
        s_kn[tid] = tanhf(h2);
    }
    __syncthreads();

    // gate
    float gv = s_st[tid] * gate_w[tid] + s_kn[tid] * gate_w[Dv + tid];
    #pragma unroll
    for (int o = 16; o; o >>= 1) gv += __shfl_xor_sync(0xffffffffu, gv, o);
    if (lane == 0) s_red[wid] = gv;
    __syncthreads();
    float alpha = 1.f / (1.f + expf(-(s_red[0] + s_red[1] + s_red[2] + s_red[3] + gate_b[0])));

    outp[(size_t)row * DMv + out_col + tid] = (1.f - alpha) * s_st[tid] + alpha * s_kn[tid];
}

// ---------------- generic fp32 GEMM: C = A @ B^T (+ biases/add/relu) -------
// 128x128 tile, 256 threads, 8x8 microtile, K-chunk 16
__global__ void gemm_nt(const float* __restrict__ A, int lda,
                        const float* __restrict__ Bw, int ldb,
                        float* __restrict__ C, int ldc,
                        int Nr, int Nc, int Kd,
                        const float* __restrict__ bias1,
                        const float* __restrict__ bias2,
                        const float* __restrict__ addM,
                        const float* __restrict__ addRow,
                        int do_relu)
{
    __shared__ float As[16][132];
    __shared__ float Bs[16][132];
    const int tid = threadIdx.x;
    const int tx = tid & 15, ty = tid >> 4;
    const int rowBase = blockIdx.y * 128;
    const int colBase = blockIdx.x * 128;

    float acc[8][8];
    #pragma unroll
    for (int i = 0; i < 8; ++i)
        #pragma unroll
        for (int j = 0; j < 8; ++j) acc[i][j] = 0.f;

    const int lm = tid >> 1;          // 0..127
    const int lk = (tid & 1) * 8;     // 0 or 8

    for (int k0 = 0; k0 < Kd; k0 += 16) {
        {
            int r = rowBase + lm;
            float4 v0 = make_float4(0,0,0,0), v1 = v0;
            if (r < Nr) {
                const float* p = A + (size_t)r * lda + k0 + lk;
                v0 = *(const float4*)p;
                v1 = *(const float4*)(p + 4);
            }
            As[lk+0][lm]=v0.x; As[lk+1][lm]=v0.y; As[lk+2][lm]=v0.z; As[lk+3][lm]=v0.w;
            As[lk+4][lm]=v1.x; As[lk+5][lm]=v1.y; As[lk+6][lm]=v1.z; As[lk+7][lm]=v1.w;
        }
        {
            int r = colBase + lm;
            float4 v0 = make_float4(0,0,0,0), v1 = v0;
            if (r < Nc) {
                const float* p = Bw + (size_t)r * ldb + k0 + lk;
                v0 = *(const float4*)p;
                v1 = *(const float4*)(p + 4);
            }
            Bs[lk+0][lm]=v0.x; Bs[lk+1][lm]=v0.y; Bs[lk+2][lm]=v0.z; Bs[lk+3][lm]=v0.w;
            Bs[lk+4][lm]=v1.x; Bs[lk+5][lm]=v1.y; Bs[lk+6][lm]=v1.z; Bs[lk+7][lm]=v1.w;
        }
        __syncthreads();
        #pragma unroll
        for (int k = 0; k < 16; ++k) {
            float av[8], bv[8];
            float4 a0 = *(const float4*)&As[k][ty * 8];
            float4 a1 = *(const float4*)&As[k][ty * 8 + 4];
            float4 b0 = *(const float4*)&Bs[k][tx * 8];
            float4 b1 = *(const float4*)&Bs[k][tx * 8 + 4];
            av[0]=a0.x; av[1]=a0.y; av[2]=a0.z; av[3]=a0.w;
            av[4]=a1.x; av[5]=a1.y; av[6]=a1.z; av[7]=a1.w;
            bv[0]=b0.x; bv[1]=b0.y; bv[2]=b0.z; bv[3]=b0.w;
            bv[4]=b1.x; bv[5]=b1.y; bv[6]=b1.z; bv[7]=b1.w;
            #pragma unroll
            for (int i = 0; i < 8; ++i)
                #pragma unroll
                for (int j = 0; j < 8; ++j) acc[i][j] += av[i] * bv[j];
        }
        __syncthreads();
    }

    #pragma unroll
    for (int i = 0; i < 8; ++i) {
        int r = rowBase + ty * 8 + i;
        if (r >= Nr) continue;
        #pragma unroll
        for (int j = 0; j < 8; ++j) {
            int cx = colBase + tx * 8 + j;
            if (cx >= Nc) continue;
            float vv = acc[i][j];
            if (bias1)  vv += bias1[cx];
            if (bias2)  vv += bias2[cx];
            if (addRow) vv += addRow[cx];
            if (addM)   vv += addM[(size_t)r * ldc + cx];
            if (do_relu) vv = fmaxf(vv, 0.f);
            C[(size_t)r * ldc + cx] = vv;
        }
    }
}

// ---------------- residual + layernorm (unbiased std, eps on sigma) --------
__global__ void posln_kernel(const float* __restrict__ O, float* __restrict__ X,
                             const float* __restrict__ g, const float* __restrict__ b)
{
    __shared__ float s_red[8];
    const int r = blockIdx.x, t = threadIdx.x;
    const int lane = t & 31, wid = t >> 5;
    float z = O[(size_t)r * DMv + t] + X[(size_t)r * DMv + t];
    float v = z;
    #pragma unroll
    for (int o = 16; o; o >>= 1) v += __shfl_xor_sync(0xffffffffu, v, o);
    if (lane == 0) s_red[wid] = v;
    __syncthreads();
    float mu = 0.f;
    #pragma unroll
    for (int i = 0; i < 8; ++i) mu += s_red[i];
    mu *= (1.f / 256.f);
    __syncthreads();
    float d = z - mu;
    v = d * d;
    #pragma unroll
    for (int o = 16; o; o >>= 1) v += __shfl_xor_sync(0xffffffffu, v, o);
    if (lane == 0) s_red[wid] = v;
    __syncthreads();
    float var = 0.f;
    #pragma unroll
    for (int i = 0; i < 8; ++i) var += s_red[i];
    var *= (1.f / 255.f);
    X[(size_t)r * DMv + t] = d / (sqrtf(var) + 1e-3f) * g[t] + b[t];
}

// ---------------- support_g + its l2-normalization --------------------------
__global__ void sg_kernel(const float* __restrict__ X)
{
    __shared__ float s_red[8];
    const int t = threadIdx.x, lane = t & 31, wid = t >> 5;
    float s = 0.f;
    #pragma unroll
    for (int i = 0; i < FEWv; ++i) s += X[(size_t)(Bv + i) * DMv + t];
    s *= (1.f / (float)FEWv);
    g_sg[t] = s;
    float v = s * s;
    #pragma unroll
    for (int o = 16; o; o >>= 1) v += __shfl_xor_sync(0xffffffffu, v, o);
    if (lane == 0) s_red[wid] = v;
    __syncthreads();
    float nn = 0.f;
    #pragma unroll
    for (int i = 0; i < 8; ++i) nn += s_red[i];
    g_sgn[t] = s / fmaxf(sqrtf(nn), 1e-12f);
}

// ---------------- rterm = w_hh[:,256:512] @ support_g ----------------------
__global__ void rterm_kernel(const float* __restrict__ w_hh)
{
    const int t = threadIdx.x, lane = t & 31, wid = t >> 5;
    const int o = blockIdx.x * 8 + wid;   // 0..2047
    const float* wr = w_hh + (size_t)o * HIDv + DMv;
    float s = 0.f;
    #pragma unroll
    for (int q = 0; q < 8; ++q) s += g_sg[lane + q * 32] * wr[lane + q * 32];
    #pragma unroll
    for (int off = 16; off; off >>= 1) s += __shfl_xor_sync(0xffffffffu, s, off);
    if (lane == 0) g_rterm[o] = s;
}

// ---------------- LSTM cell elementwise ------------------------------------
__global__ void cell_kernel(const float* __restrict__ g, int first)
{
    const int idx = blockIdx.x * blockDim.x + threadIdx.x;   // over Bv*HIDv
    const int b = idx >> 9, j = idx & 511;
    const float* gr = g + (size_t)b * GWID;
    float gi = gr[j], gf = gr[512 + j], gG = gr[1024 + j], go = gr[1536 + j];
    float cv = first ? 0.f : g_C[idx];
    cv = sigm(gf) * cv + sigm(gi) * tanhf(gG);
    g_C[idx] = cv;
    float hh = sigm(go) * tanhf(cv);
    if (j < DMv) g_h[(size_t)b * DMv + j] = g_X[(size_t)b * DMv + j] + hh;
}

// ---------------- final cosine against normalized support_g ----------------
__global__ void final_kernel(float* __restrict__ out)
{
    __shared__ float s_red[16];
    const int b = blockIdx.x, t = threadIdx.x, lane = t & 31, wid = t >> 5;
    float hv = g_h[(size_t)b * DMv + t];
    float d = hv * g_sgn[t];
    float ss = hv * hv;
    #pragma unroll
    for (int o = 16; o; o >>= 1) {
        d  += __shfl_xor_sync(0xffffffffu, d,  o);
        ss += __shfl_xor_sync(0xffffffffu, ss, o);
    }
    if (lane == 0) { s_red[wid] = d; s_red[8 + wid] = ss; }
    __syncthreads();
    if (t == 0) {
        float Dd = 0.f, S = 0.f;
        #pragma unroll
        for (int i = 0; i < 8; ++i) { Dd += s_red[i]; S += s_red[8 + i]; }
        out[b] = Dd / fmaxf(sqrtf(S), 1e-12f);
    }
}

// ---------------- launcher ---------------------------------------------------
extern "C" void kernel_launch(void* const* d_in, const int* in_sizes, int n_in,
                              void* d_out, int out_size)
{
    const int*   query    = (const int*)  d_in[0];
    const int*   support  = (const int*)  d_in[1];
    const int*   q_l_conn = (const int*)  d_in[2];
    const int*   q_r_conn = (const int*)  d_in[4];
    const int*   s_l_conn = (const int*)  d_in[6];
    const int*   s_r_conn = (const int*)  d_in[8];
    const int*   knn      = (const int*)  d_in[10];
    const float* emb      = (const float*)d_in[11];
    const float* gcn_w    = (const float*)d_in[12];
    const float* gcn_wb   = (const float*)d_in[13];
    const float* gcn_b    = (const float*)d_in[14];
    const float* gate_w   = (const float*)d_in[15];
    const float* gate_b   = (const float*)d_in[16];
    const float* p1_w     = (const float*)d_in[17];
    const float* p1_b     = (const float*)d_in[18];
    const float* p2_w     = (const float*)d_in[19];
    const float* p2_b     = (const float*)d_in[20];
    const float* ln_g     = (const float*)d_in[21];
    const float* ln_b     = (const float*)d_in[22];
    const float* w_ih     = (const float*)d_in[23];
    const float* w_hh     = (const float*)d_in[24];
    const float* b_ih     = (const float*)d_in[25];
    const float* b_hh     = (const float*)d_in[26];

    float *pX, *pO, *pH, *pG0, *pGt, *ph, *prt;
    cudaGetSymbolAddress((void**)&pX,  g_X);
    cudaGetSymbolAddress((void**)&pO,  g_O);
    cudaGetSymbolAddress((void**)&pH,  g_H);
    cudaGetSymbolAddress((void**)&pG0, g_G0);
    cudaGetSymbolAddress((void**)&pGt, g_Gt);
    cudaGetSymbolAddress((void**)&ph,  g_h);
    cudaGetSymbolAddress((void**)&prt, g_rterm);

    // 1) neighbor encoders -> X [2053, 256]
    ne_kernel<<<Bv, 128>>>(q_l_conn, query,   2, 0, knn, emb, gcn_w, gcn_wb, gcn_b, gate_w, gate_b, pX, 0);
    ne_kernel<<<Bv, 128>>>(q_r_conn, query,   2, 1, knn, emb, gcn_w, gcn_wb, gcn_b, gate_w, gate_b, pX, Dv);
    ne_kernel<<<FEWv,128>>>(s_l_conn, support, 2, 0, knn, emb, gcn_w, gcn_wb, gcn_b, gate_w, gate_b, pX + (size_t)Bv * DMv, 0);
    ne_kernel<<<FEWv,128>>>(s_r_conn, support, 2, 1, knn, emb, gcn_w, gcn_wb, gcn_b, gate_w, gate_b, pX + (size_t)Bv * DMv, Dv);

    // 2) support encoder: H = relu(X@p1^T+b1); O = H@p2^T+b2; X = LN(O+X)
    gemm_nt<<<dim3(HIDv/128, (NROWS+127)/128), 256>>>(pX, DMv, p1_w, DMv, pH, HIDv,
                                                      NROWS, HIDv, DMv, p1_b, nullptr, nullptr, nullptr, 1);
    gemm_nt<<<dim3(DMv/128, (NROWS+127)/128), 256>>>(pH, HIDv, p2_w, HIDv, pO, DMv,
                                                      NROWS, DMv, HIDv, p2_b, nullptr, nullptr, nullptr, 0);
    posln_kernel<<<NROWS, 256>>>(pO, pX, ln_g, ln_b);

    // 3) support_g, its normalization, and the constant r-term
    sg_kernel<<<1, 256>>>(pX);
    rterm_kernel<<<GWID/8, 256>>>(w_hh);

    // 4) G0 = query_g @ w_ih^T + b_ih + b_hh
    gemm_nt<<<dim3(GWID/128, Bv/128), 256>>>(pX, DMv, w_ih, DMv, pG0, GWID,
                                             Bv, GWID, DMv, b_ih, b_hh, nullptr, nullptr, 0);

    // 5) LSTM steps: step 1 uses G0 directly (h_r = 0); steps 2-4 add h@w_hh_L^T
    cell_kernel<<<(Bv * HIDv) / 256, 256>>>(pG0, 1);
    for (int s = 0; s < 3; ++s) {
        gemm_nt<<<dim3(GWID/128, Bv/128), 256>>>(ph, DMv, w_hh, HIDv, pGt, GWID,
                                                 Bv, GWID, DMv, nullptr, nullptr, pG0, prt, 0);
        cell_kernel<<<(Bv * HIDv) / 256, 256>>>(pGt, 0);
    }

    // 6) out[b] = l2n(h[b]) . l2n(support_g)
    final_kernel<<<Bv, 256>>>((float*)d_out);

    (void)in_sizes; (void)n_in; (void)out_size;
}

// round 2
// speedup vs baseline: 2.3111x; 2.3111x over previous
#include <cuda_runtime.h>
#include <math.h>

#define Dv    128
#define Mv    128
#define KTABv 64
#define Kv    32
#define Bv    2048
#define FEWv  5
#define DMv   256
#define HIDv  512
#define NSYMv 100000
#define NROWS (Bv + FEWv)   /* 2053 */
#define NUNIT (2*Bv + 2*FEWv) /* 4106 */
#define GWID  2048          /* 4*HID */

// ---------------- scratch (device globals; no runtime allocation) ----------
__device__ float g_X [NROWS * DMv];          // qn/sn, later encoded
__device__ float g_NA[(size_t)2 * NUNIT * DMv]; // neighbor-mean GEMM A matrix
__device__ float g_NH[(size_t)2 * NUNIT * Dv];  // neighbor-mean GEMM output
__device__ float g_O [NROWS * DMv];
__device__ float g_H [NROWS * HIDv];
__device__ float g_G0[(size_t)Bv * GWID];
__device__ float g_Gt[(size_t)Bv * GWID];
__device__ float g_C [Bv * HIDv];
__device__ float g_h [Bv * DMv];
__device__ float g_sg [DMv];
__device__ float g_sgn[DMv];
__device__ float g_rterm[GWID];

__device__ __forceinline__ float sigm(float x) { return 1.f / (1.f + expf(-x)); }

// ================= neighbor encoder: sims + topk + means ====================
// one block (256 threads) per unit; unit = {ql rows, qr rows, sl rows, sr rows}
__global__ __launch_bounds__(256) void ne_sims(
    const int* __restrict__ query, const int* __restrict__ support,
    const int* __restrict__ q_l_conn, const int* __restrict__ q_r_conn,
    const int* __restrict__ s_l_conn, const int* __restrict__ s_r_conn,
    const int* __restrict__ knn, const float* __restrict__ emb,
    float* __restrict__ NA)
{
    __shared__ float s_center[Dv];
    __shared__ float s_pad[Dv];
    __shared__ float s_sims[Mv];
    __shared__ float s_sims2[KTABv];
    __shared__ int   s_rel[Mv], s_ent[Mv], s_kid[KTABv];
    __shared__ int   s_lst1[Kv], s_lst2[Kv];
    __shared__ float s_p0[Dv], s_p1[Dv], s_p2[Dv];
    __shared__ float s_red[4];
    __shared__ float s_cn;

    const int u   = blockIdx.x;
    const int tid = threadIdx.x;
    const int lane = tid & 31, w = tid >> 5;

    const int* conn; int id;
    if (u < Bv)            { conn = q_l_conn + (size_t)u * (Mv*2);            id = query[u*2+0]; }
    else if (u < 2*Bv)     { int v = u - Bv;    conn = q_r_conn + (size_t)v*(Mv*2); id = query[v*2+1]; }
    else if (u < 2*Bv+FEWv){ int v = u - 2*Bv;  conn = s_l_conn + (size_t)v*(Mv*2); id = support[v*2+0]; }
    else                   { int v = u - (2*Bv+FEWv); conn = s_r_conn + (size_t)v*(Mv*2); id = support[v*2+1]; }

    if (tid < Dv) {
        float cv = emb[(size_t)id * Dv + tid];
        s_center[tid] = cv;
        float v = cv * cv;
        #pragma unroll
        for (int o = 16; o; o >>= 1) v += __shfl_xor_sync(0xffffffffu, v, o);
        if (lane == 0) s_red[w] = v;
        int2 rc = ((const int2*)conn)[tid];
        s_rel[tid] = rc.x; s_ent[tid] = rc.y;
    } else {
        int t2 = tid - Dv;
        s_pad[t2] = emb[(size_t)NSYMv * Dv + t2];
        if (t2 < KTABv) s_kid[t2] = knn[(size_t)id * KTABv + t2];
    }
    __syncthreads();
    if (tid == 0) s_cn = sqrtf(s_red[0] + s_red[1] + s_red[2] + s_red[3]);
    __syncthreads();
    const float cn = s_cn;

    // cosine sims vs conn entities: warp w handles m in [w*16, w*16+16), unroll x2
    #pragma unroll
    for (int i = 0; i < 16; i += 2) {
        int m0 = w * 16 + i, m1 = m0 + 1;
        const float* e0 = emb + (size_t)s_ent[m0] * Dv;
        const float* e1 = emb + (size_t)s_ent[m1] * Dv;
        float d0 = 0.f, n0 = 0.f, d1 = 0.f, n1 = 0.f;
        #pragma unroll
        for (int q = 0; q < 4; ++q) {
            float c  = s_center[lane + q * 32];
            float x0 = e0[lane + q * 32];
            float x1 = e1[lane + q * 32];
            d0 += c * x0; n0 += x0 * x0;
            d1 += c * x1; n1 += x1 * x1;
        }
        #pragma unroll
        for (int o = 16; o; o >>= 1) {
            d0 += __shfl_xor_sync(0xffffffffu, d0, o);
            n0 += __shfl_xor_sync(0xffffffffu, n0, o);
            d1 += __shfl_xor_sync(0xffffffffu, d1, o);
            n1 += __shfl_xor_sync(0xffffffffu, n1, o);
        }
        if (lane == 0) {
            s_sims[m0] = d0 / fmaxf(cn * sqrtf(n0), 1e-8f);
            s_sims[m1] = d1 / fmaxf(cn * sqrtf(n1), 1e-8f);
        }
    }
    // cosine sims vs knn entities: warp w handles m in [w*8, w*8+8), unroll x2
    #pragma unroll
    for (int i = 0; i < 8; i += 2) {
        int m0 = w * 8 + i, m1 = m0 + 1;
        const float* e0 = emb + (size_t)s_kid[m0] * Dv;
        const float* e1 = emb + (size_t)s_kid[m1] * Dv;
        float d0 = 0.f, n0 = 0.f, d1 = 0.f, n1 = 0.f;
        #pragma unroll
        for (int q = 0; q < 4; ++q) {
            float c  = s_center[lane + q * 32];
            float x0 = e0[lane + q * 32];
            float x1 = e1[lane + q * 32];
            d0 += c * x0; n0 += x0 * x0;
            d1 += c * x1; n1 += x1 * x1;
        }
        #pragma unroll
        for (int o = 16; o; o >>= 1) {
            d0 += __shfl_xor_sync(0xffffffffu, d0, o);
            n0 += __shfl_xor_sync(0xffffffffu, n0, o);
            d1 += __shfl_xor_sync(0xffffffffu, d1, o);
            n1 += __shfl_xor_sync(0xffffffffu, n1, o);
        }
        if (lane == 0) {
            s_sims2[m0] = d0 / fmaxf(cn * sqrtf(n0), 1e-8f);
            s_sims2[m1] = d1 / fmaxf(cn * sqrtf(n1), 1e-8f);
        }
    }
    __syncthreads();

    // stable top-K (jax.lax.top_k tie-break) with rank-scatter compaction
    if (tid < Mv) {
        float my = s_sims[tid];
        int cnt = 0;
        #pragma unroll 8
        for (int j = 0; j < Mv; ++j) {
            float o = s_sims[j];
            cnt += (o > my) || (o == my && j < tid);
        }
        if (cnt < Kv) s_lst1[cnt] = tid;
    } else if (tid < Mv + KTABv) {
        int m = tid - Mv;
        float my = s_sims2[m];
        int cnt = 0;
        #pragma unroll 8
        for (int j = 0; j < KTABv; ++j) {
            float o = s_sims2[j];
            cnt += (o > my) || (o == my && j < m);
        }
        if (cnt < Kv) s_lst2[cnt] = m;
    }
    __syncthreads();

    // gather means over compacted top-32 lists: split across two thread halves
    const int d = tid & (Dv - 1), half = tid >> 7;
    float ar = 0.f, ae = 0.f, ak = 0.f;
    #pragma unroll 4
    for (int e = half * 16; e < half * 16 + 16; ++e) {
        int m1 = s_lst1[e];
        int m2 = s_lst2[e];
        ar += emb[(size_t)s_rel[m1] * Dv + d];
        ae += emb[(size_t)s_ent[m1] * Dv + d];
        ak += emb[(size_t)s_kid[m2] * Dv + d];
    }
    if (half == 1) { s_p0[d] = ar; s_p1[d] = ae; s_p2[d] = ak; }
    __syncthreads();
    if (half == 0) {
        const float inv = 1.f / (float)Kv;
        float mr = (ar + s_p0[d]) * inv;
        float me = (ae + s_p1[d]) * inv;
        float mk = (ak + s_p2[d]) * inv;
        NA[(size_t)u * DMv + d]            = mr;
        NA[(size_t)u * DMv + Dv + d]       = me;
        NA[(size_t)(NUNIT + u) * DMv + d]      = s_pad[d];
        NA[(size_t)(NUNIT + u) * DMv + Dv + d] = mk;
    }
}

// ================= neighbor encoder: gate + combine ========================
__global__ void ne_fin(const float* __restrict__ NH,
                       const float* __restrict__ gate_w,
                       const float* __restrict__ gate_b,
                       float* __restrict__ X)
{
    __shared__ float s_red[4];
    __shared__ float s_alpha;
    const int u = blockIdx.x, tid = threadIdx.x;
    const int lane = tid & 31, w = tid >> 5;
    float st = NH[(size_t)u * Dv + tid];
    float kn = NH[(size_t)(NUNIT + u) * Dv + tid];
    float gv = st * gate_w[tid] + kn * gate_w[Dv + tid];
    #pragma unroll
    for (int o = 16; o; o >>= 1) gv += __shfl_xor_sync(0xffffffffu, gv, o);
    if (lane == 0) s_red[w] = gv;
    __syncthreads();
    if (tid == 0) s_alpha = sigm(s_red[0] + s_red[1] + s_red[2] + s_red[3] + gate_b[0]);
    __syncthreads();
    float alpha = s_alpha;
    int row, col;
    if (u < Bv)             { row = u;                 col = 0; }
    else if (u < 2*Bv)      { row = u - Bv;            col = Dv; }
    else if (u < 2*Bv+FEWv) { row = Bv + (u - 2*Bv);   col = 0; }
    else                    { row = Bv + (u - 2*Bv - FEWv); col = Dv; }
    X[(size_t)row * DMv + col + tid] = (1.f - alpha) * st + alpha * kn;
}

// ================= fp32x2 GEMM: C = A @ B^T (+epilogue) =====================
// 64x128 tile, 256 threads, 4x8 microtile via packed fma.rn.f32x2
// column mapping: thread covers cols {tx*2 + 32*j2, +1} -> conflict-free LDS.64
__global__ __launch_bounds__(256) void gemm_nt(
    const float* __restrict__ A, int lda,
    const float* __restrict__ Bw, int ldb,
    float* __restrict__ C, int ldc,
    int Nr, int Nc, int Kd,
    const float* __restrict__ bias1,
    const float* __restrict__ bias2,
    const float* __restrict__ addM,
    const float* __restrict__ addRow,
    int act)  // 0 none, 1 relu, 2 tanh
{
    __shared__ float As[16][68];
    __shared__ float Bs[16][132];
    const int tid = threadIdx.x;
    const int tx = tid & 15, ty = tid >> 4;
    const int rowBase = blockIdx.y * 64;
    const int colBase = blockIdx.x * 128;

    unsigned long long acc[4][4];
    #pragma unroll
    for (int i = 0; i < 4; ++i)
        #pragma unroll
        for (int j = 0; j < 4; ++j) acc[i][j] = 0ull;

    const int arow = tid >> 2, akoff = (tid & 3) * 4;
    const int brow = tid >> 1, bkoff = (tid & 1) * 8;

    for (int k0 = 0; k0 < Kd; k0 += 16) {
        {
            int r = rowBase + arow;
            float4 v = make_float4(0.f, 0.f, 0.f, 0.f);
            if (r < Nr) v = *(const float4*)(A + (size_t)r * lda + k0 + akoff);
            As[akoff + 0][arow] = v.x; As[akoff + 1][arow] = v.y;
            As[akoff + 2][arow] = v.z; As[akoff + 3][arow] = v.w;
        }
        {
            int r = colBase + brow;
            const float* p = Bw + (size_t)r * ldb + k0 + bkoff;
            float4 v0 = *(const float4*)p;
            float4 v1 = *(const float4*)(p + 4);
            Bs[bkoff + 0][brow] = v0.x; Bs[bkoff + 1][brow] = v0.y;
            Bs[bkoff + 2][brow] = v0.z; Bs[bkoff + 3][brow] = v0.w;
            Bs[bkoff + 4][brow] = v1.x; Bs[bkoff + 5][brow] = v1.y;
            Bs[bkoff + 6][brow] = v1.z; Bs[bkoff + 7][brow] = v1.w;
        }
        __syncthreads();
        #pragma unroll
        for (int k = 0; k < 16; ++k) {
            float4 a = *(const float4*)&As[k][ty * 4];
            unsigned long long av[4];
            {
                unsigned u0 = __float_as_uint(a.x), u1 = __float_as_uint(a.y);
                unsigned u2 = __float_as_uint(a.z), u3 = __float_as_uint(a.w);
                asm("mov.b64 %0, {%1, %1};" : "=l"(av[0]) : "r"(u0));
                asm("mov.b64 %0, {%1, %1};" : "=l"(av[1]) : "r"(u1));
                asm("mov.b64 %0, {%1, %1};" : "=l"(av[2]) : "r"(u2));
                asm("mov.b64 %0, {%1, %1};" : "=l"(av[3]) : "r"(u3));
            }
            unsigned long long bv[4];
            #pragma unroll
            for (int j2 = 0; j2 < 4; ++j2)
                bv[j2] = *(const unsigned long long*)&Bs[k][tx * 2 + 32 * j2];
            #pragma unroll
            for (int i = 0; i < 4; ++i)
                #pragma unroll
                for (int j2 = 0; j2 < 4; ++j2)
                    asm("fma.rn.f32x2 %0, %1, %2, %0;" : "+l"(acc[i][j2]) : "l"(av[i]), "l"(bv[j2]));
        }
        __syncthreads();
    }

    #pragma unroll
    for (int i = 0; i < 4; ++i) {
        int r = rowBase + ty * 4 + i;
        if (r >= Nr) continue;
        #pragma unroll
        for (int j2 = 0; j2 < 4; ++j2) {
            unsigned ulo, uhi;
            asm("mov.b64 {%0, %1}, %2;" : "=r"(ulo), "=r"(uhi) : "l"(acc[i][j2]));
            float lo = __uint_as_float(ulo), hi = __uint_as_float(uhi);
            int c0 = colBase + tx * 2 + 32 * j2;   // Nc always multiple of 128
            int c1 = c0 + 1;
            if (bias1)  { lo += bias1[c0];  hi += bias1[c1]; }
            if (bias2)  { lo += bias2[c0];  hi += bias2[c1]; }
            if (addRow) { lo += addRow[c0]; hi += addRow[c1]; }
            if (addM)   { lo += addM[(size_t)r * ldc + c0]; hi += addM[(size_t)r * ldc + c1]; }
            if (act == 1) { lo = fmaxf(lo, 0.f); hi = fmaxf(hi, 0.f); }
            else if (act == 2) { lo = tanhf(lo); hi = tanhf(hi); }
            *(float2*)(C + (size_t)r * ldc + c0) = make_float2(lo, hi);
        }
    }
}

// ---------------- residual + layernorm (unbiased std, eps on sigma) --------
__global__ void posln_kernel(const float* __restrict__ O, float* __restrict__ X,
                             const float* __restrict__ g, const float* __restrict__ b)
{
    __shared__ float s_red[8];
    const int r = blockIdx.x, t = threadIdx.x;
    const int lane = t & 31, w = t >> 5;
    float z = O[(size_t)r * DMv + t] + X[(size_t)r * DMv + t];
    float v = z;
    #pragma unroll
    for (int o = 16; o; o >>= 1) v += __shfl_xor_sync(0xffffffffu, v, o);
    if (lane == 0) s_red[w] = v;
    __syncthreads();
    float mu = 0.f;
    #pragma unroll
    for (int i = 0; i < 8; ++i) mu += s_red[i];
    mu *= (1.f / 256.f);
    __syncthreads();
    float d = z - mu;
    v = d * d;
    #pragma unroll
    for (int o = 16; o; o >>= 1) v += __shfl_xor_sync(0xffffffffu, v, o);
    if (lane == 0) s_red[w] = v;
    __syncthreads();
    float var = 0.f;
    #pragma unroll
    for (int i = 0; i < 8; ++i) var += s_red[i];
    var *= (1.f / 255.f);
    X[(size_t)r * DMv + t] = d / (sqrtf(var) + 1e-3f) * g[t] + b[t];
}

// ---------------- support_g + l2 normalization ------------------------------
__global__ void sg_kernel(const float* __restrict__ X)
{
    __shared__ float s_red[8];
    const int t = threadIdx.x, lane = t & 31, w = t >> 5;
    float s = 0.f;
    #pragma unroll
    for (int i = 0; i < FEWv; ++i) s += X[(size_t)(Bv + i) * DMv + t];
    s *= (1.f / (float)FEWv);
    g_sg[t] = s;
    float v = s * s;
    #pragma unroll
    for (int o = 16; o; o >>= 1) v += __shfl_xor_sync(0xffffffffu, v, o);
    if (lane == 0) s_red[w] = v;
    __syncthreads();
    float nn = 0.f;
    #pragma unroll
    for (int i = 0; i < 8; ++i) nn += s_red[i];
    g_sgn[t] = s / fmaxf(sqrtf(nn), 1e-12f);
}

// ---------------- rterm = w_hh[:,256:512] @ support_g ----------------------
__global__ void rterm_kernel(const float* __restrict__ w_hh)
{
    const int t = threadIdx.x, lane = t & 31, w = t >> 5;
    const int o = blockIdx.x * 8 + w;
    const float* wr = w_hh + (size_t)o * HIDv + DMv;
    float s = 0.f;
    #pragma unroll
    for (int q = 0; q < 8; ++q) s += g_sg[lane + q * 32] * wr[lane + q * 32];
    #pragma unroll
    for (int off = 16; off; off >>= 1) s += __shfl_xor_sync(0xffffffffu, s, off);
    if (lane == 0) g_rterm[o] = s;
}

// ---------------- LSTM cell elementwise ------------------------------------
__global__ void cell_kernel(const float* __restrict__ g, int first)
{
    const int idx = blockIdx.x * blockDim.x + threadIdx.x;
    const int b = idx >> 9, j = idx & 511;
    const float* gr = g + (size_t)b * GWID;
    float gi = gr[j], gf = gr[512 + j], gG = gr[1024 + j], go = gr[1536 + j];
    float cv = first ? 0.f : g_C[idx];
    cv = sigm(gf) * cv + sigm(gi) * tanhf(gG);
    g_C[idx] = cv;
    float hh = sigm(go) * tanhf(cv);
    if (j < DMv) g_h[(size_t)b * DMv + j] = g_X[(size_t)b * DMv + j] + hh;
}

// ---------------- final cosine against normalized support_g ----------------
__global__ void final_kernel(float* __restrict__ out)
{
    __shared__ float s_red[16];
    const int b = blockIdx.x, t = threadIdx.x, lane = t & 31, w = t >> 5;
    float hv = g_h[(size_t)b * DMv + t];
    float d = hv * g_sgn[t];
    float ss = hv * hv;
    #pragma unroll
    for (int o = 16; o; o >>= 1) {
        d  += __shfl_xor_sync(0xffffffffu, d,  o);
        ss += __shfl_xor_sync(0xffffffffu, ss, o);
    }
    if (lane == 0) { s_red[w] = d; s_red[8 + w] = ss; }
    __syncthreads();
    if (t == 0) {
        float Dd = 0.f, S = 0.f;
        #pragma unroll
        for (int i = 0; i < 8; ++i) { Dd += s_red[i]; S += s_red[8 + i]; }
        out[b] = Dd / fmaxf(sqrtf(S), 1e-12f);
    }
}

// ---------------- launcher ---------------------------------------------------
extern "C" void kernel_launch(void* const* d_in, const int* in_sizes, int n_in,
                              void* d_out, int out_size)
{
    const int*   query    = (const int*)  d_in[0];
    const int*   support  = (const int*)  d_in[1];
    const int*   q_l_conn = (const int*)  d_in[2];
    const int*   q_r_conn = (const int*)  d_in[4];
    const int*   s_l_conn = (const int*)  d_in[6];
    const int*   s_r_conn = (const int*)  d_in[8];
    const int*   knn      = (const int*)  d_in[10];
    const float* emb      = (const float*)d_in[11];
    const float* gcn_w    = (const float*)d_in[12];
    const float* gcn_wb   = (const float*)d_in[13];
    const float* gcn_b    = (const float*)d_in[14];
    const float* gate_w   = (const float*)d_in[15];
    const float* gate_b   = (const float*)d_in[16];
    const float* p1_w     = (const float*)d_in[17];
    const float* p1_b     = (const float*)d_in[18];
    const float* p2_w     = (const float*)d_in[19];
    const float* p2_b     = (const float*)d_in[20];
    const float* ln_g     = (const float*)d_in[21];
    const float* ln_b     = (const float*)d_in[22];
    const float* w_ih     = (const float*)d_in[23];
    const float* w_hh     = (const float*)d_in[24];
    const float* b_ih     = (const float*)d_in[25];
    const float* b_hh     = (const float*)d_in[26];

    float *pX, *pNA, *pNH, *pO, *pH, *pG0, *pGt, *ph, *prt;
    cudaGetSymbolAddress((void**)&pX,  g_X);
    cudaGetSymbolAddress((void**)&pNA, g_NA);
    cudaGetSymbolAddress((void**)&pNH, g_NH);
    cudaGetSymbolAddress((void**)&pO,  g_O);
    cudaGetSymbolAddress((void**)&pH,  g_H);
    cudaGetSymbolAddress((void**)&pG0, g_G0);
    cudaGetSymbolAddress((void**)&pGt, g_Gt);
    cudaGetSymbolAddress((void**)&ph,  g_h);
    cudaGetSymbolAddress((void**)&prt, g_rterm);

    // 1) neighbor encoder: sims/topk/means -> NA [2*4106, 256]
    ne_sims<<<NUNIT, 256>>>(query, support, q_l_conn, q_r_conn, s_l_conn, s_r_conn,
                            knn, emb, pNA);
    // 2) batched GCN matvec as GEMM: NH = tanh(NA @ gcn_w^T + wb + b)  [8212,128]
    gemm_nt<<<dim3(1, (2*NUNIT + 63)/64), 256>>>(pNA, DMv, gcn_w, DMv, pNH, Dv,
                                                 2*NUNIT, Dv, DMv, gcn_wb, gcn_b,
                                                 nullptr, nullptr, 2);
    // 3) gate + combine -> X [2053, 256]
    ne_fin<<<NUNIT, 128>>>(pNH, gate_w, gate_b, pX);

    // 4) support encoder
    gemm_nt<<<dim3(HIDv/128, (NROWS + 63)/64), 256>>>(pX, DMv, p1_w, DMv, pH, HIDv,
                                                      NROWS, HIDv, DMv, p1_b, nullptr,
                                                      nullptr, nullptr, 1);
    gemm_nt<<<dim3(DMv/128, (NROWS + 63)/64), 256>>>(pH, HIDv, p2_w, HIDv, pO, DMv,
                                                     NROWS, DMv, HIDv, p2_b, nullptr,
                                                     nullptr, nullptr, 0);
    posln_kernel<<<NROWS, 256>>>(pO, pX, ln_g, ln_b);

    // 5) support_g, normalization, constant r-term
    sg_kernel<<<1, 256>>>(pX);
    rterm_kernel<<<GWID/8, 256>>>(w_hh);

    // 6) G0 = query_g @ w_ih^T + b_ih + b_hh
    gemm_nt<<<dim3(GWID/128, Bv/64), 256>>>(pX, DMv, w_ih, DMv, pG0, GWID,
                                            Bv, GWID, DMv, b_ih, b_hh,
                                            nullptr, nullptr, 0);

    // 7) LSTM: step 1 uses G0 (h_r = 0); steps 2-4 add h @ w_hh[:, :256]^T
    cell_kernel<<<(Bv * HIDv) / 256, 256>>>(pG0, 1);
    for (int s = 0; s < 3; ++s) {
        gemm_nt<<<dim3(GWID/128, Bv/64), 256>>>(ph, DMv, w_hh, HIDv, pGt, GWID,
                                                Bv, GWID, DMv, nullptr, nullptr,
                                                pG0, prt, 0);
        cell_kernel<<<(Bv * HIDv) / 256, 256>>>(pGt, 0);
    }

    // 8) out[b] = l2n(h[b]) . l2n(support_g)
    final_kernel<<<Bv, 256>>>((float*)d_out);

    (void)in_sizes; (void)n_in; (void)out_size;
}

// round 3
// speedup vs baseline: 3.0722x; 1.3294x over previous
#include <cuda_runtime.h>
#include <math.h>

#define Dv    128
#define Mv    128
#define KTABv 64
#define Kv    32
#define Bv    2048
#define FEWv  5
#define DMv   256
#define HIDv  512
#define NSYMv 100000
#define NROWS (Bv + FEWv)     /* 2053 */
#define NUNIT (2*Bv + 2*FEWv) /* 4106 */
#define G4    1024            /* packed gate width: 4 * 256 */

// ---------------- scratch (device globals; no runtime allocation) ----------
__device__ float g_X [NROWS * DMv];
__device__ float g_NA[(size_t)2 * NUNIT * DMv];
__device__ float g_NH[(size_t)2 * NUNIT * Dv];
__device__ float g_O [NROWS * DMv];
__device__ float g_H [NROWS * HIDv];
__device__ float g_G0[(size_t)Bv * G4];
__device__ float g_Gt[(size_t)Bv * G4];
__device__ float g_C [Bv * DMv];
__device__ float g_h [Bv * DMv];
__device__ float g_sg [DMv];
__device__ float g_sgn[DMv];
__device__ float g_rt4[G4];
__device__ float g_Wih4[G4 * DMv];
__device__ float g_Whh4[G4 * DMv];
__device__ float g_b4[G4];

__device__ __forceinline__ float sigm(float x) { return 1.f / (1.f + expf(-x)); }
__device__ __forceinline__ int gmap(int r) { return ((r >> 8) << 9) + (r & 255); }

// ================= pack reduced gate weights ================================
__global__ void pack_w(const float* __restrict__ w_ih, const float* __restrict__ w_hh,
                       const float* __restrict__ b_ih, const float* __restrict__ b_hh)
{
    const int r = blockIdx.x, t = threadIdx.x;
    const int m = gmap(r);
    g_Wih4[(size_t)r * DMv + t] = w_ih[(size_t)m * DMv + t];
    g_Whh4[(size_t)r * DMv + t] = w_hh[(size_t)m * HIDv + t];
    if (t == 0) g_b4[r] = b_ih[m] + b_hh[m];
}

// ================= neighbor encoder: sims + topk + means ====================
__global__ __launch_bounds__(256) void ne_sims(
    const int* __restrict__ query, const int* __restrict__ support,
    const int* __restrict__ q_l_conn, const int* __restrict__ q_r_conn,
    const int* __restrict__ s_l_conn, const int* __restrict__ s_r_conn,
    const int* __restrict__ knn, const float* __restrict__ emb,
    float* __restrict__ NA)
{
    __shared__ float s_center[Dv];
    __shared__ float s_pad[Dv];
    __shared__ float s_sims[Mv];
    __shared__ float s_sims2[KTABv];
    __shared__ int   s_rel[Mv], s_ent[Mv], s_kid[KTABv];
    __shared__ int   s_lst1[Kv], s_lst2[Kv];
    __shared__ float s_p0[Dv], s_p1[Dv], s_p2[Dv];
    __shared__ float s_red[4];
    __shared__ float s_cn;

    const int u   = blockIdx.x;
    const int tid = threadIdx.x;
    const int lane = tid & 31, w = tid >> 5;

    const int* conn; int id;
    if (u < Bv)            { conn = q_l_conn + (size_t)u * (Mv*2);            id = query[u*2+0]; }
    else if (u < 2*Bv)     { int v = u - Bv;    conn = q_r_conn + (size_t)v*(Mv*2); id = query[v*2+1]; }
    else if (u < 2*Bv+FEWv){ int v = u - 2*Bv;  conn = s_l_conn + (size_t)v*(Mv*2); id = support[v*2+0]; }
    else                   { int v = u - (2*Bv+FEWv); conn = s_r_conn + (size_t)v*(Mv*2); id = support[v*2+1]; }

    if (tid < Dv) {
        float cv = emb[(size_t)id * Dv + tid];
        s_center[tid] = cv;
        float v = cv * cv;
        #pragma unroll
        for (int o = 16; o; o >>= 1) v += __shfl_xor_sync(0xffffffffu, v, o);
        if (lane == 0) s_red[w] = v;
        int2 rc = ((const int2*)conn)[tid];
        s_rel[tid] = rc.x; s_ent[tid] = rc.y;
    } else {
        int t2 = tid - Dv;
        s_pad[t2] = emb[(size_t)NSYMv * Dv + t2];
        if (t2 < KTABv) s_kid[t2] = knn[(size_t)id * KTABv + t2];
    }
    __syncthreads();
    if (tid == 0) s_cn = sqrtf(s_red[0] + s_red[1] + s_red[2] + s_red[3]);
    __syncthreads();
    const float cn = s_cn;

    #pragma unroll
    for (int i = 0; i < 16; i += 2) {
        int m0 = w * 16 + i, m1 = m0 + 1;
        const float* e0 = emb + (size_t)s_ent[m0] * Dv;
        const float* e1 = emb + (size_t)s_ent[m1] * Dv;
        float d0 = 0.f, n0 = 0.f, d1 = 0.f, n1 = 0.f;
        #pragma unroll
        for (int q = 0; q < 4; ++q) {
            float c  = s_center[lane + q * 32];
            float x0 = e0[lane + q * 32];
            float x1 = e1[lane + q * 32];
            d0 += c * x0; n0 += x0 * x0;
            d1 += c * x1; n1 += x1 * x1;
        }
        #pragma unroll
        for (int o = 16; o; o >>= 1) {
            d0 += __shfl_xor_sync(0xffffffffu, d0, o);
            n0 += __shfl_xor_sync(0xffffffffu, n0, o);
            d1 += __shfl_xor_sync(0xffffffffu, d1, o);
            n1 += __shfl_xor_sync(0xffffffffu, n1, o);
        }
        if (lane == 0) {
            s_sims[m0] = d0 / fmaxf(cn * sqrtf(n0), 1e-8f);
            s_sims[m1] = d1 / fmaxf(cn * sqrtf(n1), 1e-8f);
        }
    }
    #pragma unroll
    for (int i = 0; i < 8; i += 2) {
        int m0 = w * 8 + i, m1 = m0 + 1;
        const float* e0 = emb + (size_t)s_kid[m0] * Dv;
        const float* e1 = emb + (size_t)s_kid[m1] * Dv;
        float d0 = 0.f, n0 = 0.f, d1 = 0.f, n1 = 0.f;
        #pragma unroll
        for (int q = 0; q < 4; ++q) {
            float c  = s_center[lane + q * 32];
            float x0 = e0[lane + q * 32];
            float x1 = e1[lane + q * 32];
            d0 += c * x0; n0 += x0 * x0;
            d1 += c * x1; n1 += x1 * x1;
        }
        #pragma unroll
        for (int o = 16; o; o >>= 1) {
            d0 += __shfl_xor_sync(0xffffffffu, d0, o);
            n0 += __shfl_xor_sync(0xffffffffu, n0, o);
            d1 += __shfl_xor_sync(0xffffffffu, d1, o);
            n1 += __shfl_xor_sync(0xffffffffu, n1, o);
        }
        if (lane == 0) {
            s_sims2[m0] = d0 / fmaxf(cn * sqrtf(n0), 1e-8f);
            s_sims2[m1] = d1 / fmaxf(cn * sqrtf(n1), 1e-8f);
        }
    }
    __syncthreads();

    if (tid < Mv) {
        float my = s_sims[tid];
        int cnt = 0;
        #pragma unroll 8
        for (int j = 0; j < Mv; ++j) {
            float o = s_sims[j];
            cnt += (o > my) || (o == my && j < tid);
        }
        if (cnt < Kv) s_lst1[cnt] = tid;
    } else if (tid < Mv + KTABv) {
        int m = tid - Mv;
        float my = s_sims2[m];
        int cnt = 0;
        #pragma unroll 8
        for (int j = 0; j < KTABv; ++j) {
            float o = s_sims2[j];
            cnt += (o > my) || (o == my && j < m);
        }
        if (cnt < Kv) s_lst2[cnt] = m;
    }
    __syncthreads();

    const int d = tid & (Dv - 1), half = tid >> 7;
    float ar = 0.f, ae = 0.f, ak = 0.f;
    #pragma unroll 4
    for (int e = half * 16; e < half * 16 + 16; ++e) {
        int m1 = s_lst1[e];
        int m2 = s_lst2[e];
        ar += emb[(size_t)s_rel[m1] * Dv + d];
        ae += emb[(size_t)s_ent[m1] * Dv + d];
        ak += emb[(size_t)s_kid[m2] * Dv + d];
    }
    if (half == 1) { s_p0[d] = ar; s_p1[d] = ae; s_p2[d] = ak; }
    __syncthreads();
    if (half == 0) {
        const float inv = 1.f / (float)Kv;
        float mr = (ar + s_p0[d]) * inv;
        float me = (ae + s_p1[d]) * inv;
        float mk = (ak + s_p2[d]) * inv;
        NA[(size_t)u * DMv + d]            = mr;
        NA[(size_t)u * DMv + Dv + d]       = me;
        NA[(size_t)(NUNIT + u) * DMv + d]      = s_pad[d];
        NA[(size_t)(NUNIT + u) * DMv + Dv + d] = mk;
    }
}

// ================= neighbor encoder: gate + combine ========================
__global__ void ne_fin(const float* __restrict__ NH,
                       const float* __restrict__ gate_w,
                       const float* __restrict__ gate_b,
                       float* __restrict__ X)
{
    __shared__ float s_red[4];
    __shared__ float s_alpha;
    const int u = blockIdx.x, tid = threadIdx.x;
    const int lane = tid & 31, w = tid >> 5;
    float st = NH[(size_t)u * Dv + tid];
    float kn = NH[(size_t)(NUNIT + u) * Dv + tid];
    float gv = st * gate_w[tid] + kn * gate_w[Dv + tid];
    #pragma unroll
    for (int o = 16; o; o >>= 1) gv += __shfl_xor_sync(0xffffffffu, gv, o);
    if (lane == 0) s_red[w] = gv;
    __syncthreads();
    if (tid == 0) s_alpha = sigm(s_red[0] + s_red[1] + s_red[2] + s_red[3] + gate_b[0]);
    __syncthreads();
    float alpha = s_alpha;
    int row, col;
    if (u < Bv)             { row = u;                 col = 0; }
    else if (u < 2*Bv)      { row = u - Bv;            col = Dv; }
    else if (u < 2*Bv+FEWv) { row = Bv + (u - 2*Bv);   col = 0; }
    else                    { row = Bv + (u - 2*Bv - FEWv); col = Dv; }
    X[(size_t)row * DMv + col + tid] = (1.f - alpha) * st + alpha * kn;
}

// ================= fp32x2 GEMM, double-buffered: C = A @ B^T (+epilogue) ====
// 64x128 tile, 256 threads, 4x8 microtile via packed fma.rn.f32x2
__global__ __launch_bounds__(256) void gemm_nt(
    const float* __restrict__ A, int lda,
    const float* __restrict__ Bw, int ldb,
    float* __restrict__ C, int ldc,
    int Nr, int Nc, int Kd,
    const float* __restrict__ bias1,
    const float* __restrict__ bias2,
    const float* __restrict__ addM,
    const float* __restrict__ addRow,
    int act)  // 0 none, 1 relu, 2 tanh
{
    __shared__ float As[2][16][68];
    __shared__ float Bs[2][16][132];
    const int tid = threadIdx.x;
    const int tx = tid & 15, ty = tid >> 4;
    const int rowBase = blockIdx.y * 64;
    const int colBase = blockIdx.x * 128;

    unsigned long long acc[4][4];
    #pragma unroll
    for (int i = 0; i < 4; ++i)
        #pragma unroll
        for (int j = 0; j < 4; ++j) acc[i][j] = 0ull;

    const int arow = tid >> 2, akoff = (tid & 3) * 4;
    const int brow = tid >> 1, bkoff = (tid & 1) * 8;
    const int nk = Kd >> 4;

    float4 pa, pb0, pb1;
    // prologue: load chunk 0 directly to smem buffer 0
    {
        int r = rowBase + arow;
        float4 v = make_float4(0.f, 0.f, 0.f, 0.f);
        if (r < Nr) v = *(const float4*)(A + (size_t)r * lda + akoff);
        As[0][akoff + 0][arow] = v.x; As[0][akoff + 1][arow] = v.y;
        As[0][akoff + 2][arow] = v.z; As[0][akoff + 3][arow] = v.w;
        const float* p = Bw + (size_t)(colBase + brow) * ldb + bkoff;
        float4 v0 = *(const float4*)p;
        float4 v1 = *(const float4*)(p + 4);
        Bs[0][bkoff + 0][brow] = v0.x; Bs[0][bkoff + 1][brow] = v0.y;
        Bs[0][bkoff + 2][brow] = v0.z; Bs[0][bkoff + 3][brow] = v0.w;
        Bs[0][bkoff + 4][brow] = v1.x; Bs[0][bkoff + 5][brow] = v1.y;
        Bs[0][bkoff + 6][brow] = v1.z; Bs[0][bkoff + 7][brow] = v1.w;
    }
    __syncthreads();

    int buf = 0;
    for (int it = 0; it < nk; ++it) {
        if (it + 1 < nk) {
            int k0 = (it + 1) << 4;
            int r = rowBase + arow;
            pa = make_float4(0.f, 0.f, 0.f, 0.f);
            if (r < Nr) pa = *(const float4*)(A + (size_t)r * lda + k0 + akoff);
            const float* p = Bw + (size_t)(colBase + brow) * ldb + k0 + bkoff;
            pb0 = *(const float4*)p;
            pb1 = *(const float4*)(p + 4);
        }
        #pragma unroll
        for (int k = 0; k < 16; ++k) {
            float4 a = *(const float4*)&As[buf][k][ty * 4];
            unsigned long long av[4];
            {
                unsigned u0 = __float_as_uint(a.x), u1 = __float_as_uint(a.y);
                unsigned u2 = __float_as_uint(a.z), u3 = __float_as_uint(a.w);
                asm("mov.b64 %0, {%1, %1};" : "=l"(av[0]) : "r"(u0));
                asm("mov.b64 %0, {%1, %1};" : "=l"(av[1]) : "r"(u1));
                asm("mov.b64 %0, {%1, %1};" : "=l"(av[2]) : "r"(u2));
                asm("mov.b64 %0, {%1, %1};" : "=l"(av[3]) : "r"(u3));
            }
            unsigned long long bv[4];
            #pragma unroll
            for (int j2 = 0; j2 < 4; ++j2)
                bv[j2] = *(const unsigned long long*)&Bs[buf][k][tx * 2 + 32 * j2];
            #pragma unroll
            for (int i = 0; i < 4; ++i)
                #pragma unroll
                for (int j2 = 0; j2 < 4; ++j2)
                    asm("fma.rn.f32x2 %0, %1, %2, %0;" : "+l"(acc[i][j2]) : "l"(av[i]), "l"(bv[j2]));
        }
        if (it + 1 < nk) {
            int nb = buf ^ 1;
            As[nb][akoff + 0][arow] = pa.x; As[nb][akoff + 1][arow] = pa.y;
            As[nb][akoff + 2][arow] = pa.z; As[nb][akoff + 3][arow] = pa.w;
            Bs[nb][bkoff + 0][brow] = pb0.x; Bs[nb][bkoff + 1][brow] = pb0.y;
            Bs[nb][bkoff + 2][brow] = pb0.z; Bs[nb][bkoff + 3][brow] = pb0.w;
            Bs[nb][bkoff + 4][brow] = pb1.x; Bs[nb][bkoff + 5][brow] = pb1.y;
            Bs[nb][bkoff + 6][brow] = pb1.z; Bs[nb][bkoff + 7][brow] = pb1.w;
            __syncthreads();
            buf = nb;
        }
    }

    #pragma unroll
    for (int i = 0; i < 4; ++i) {
        int r = rowBase + ty * 4 + i;
        if (r >= Nr) continue;
        #pragma unroll
        for (int j2 = 0; j2 < 4; ++j2) {
            unsigned ulo, uhi;
            asm("mov.b64 {%0, %1}, %2;" : "=r"(ulo), "=r"(uhi) : "l"(acc[i][j2]));
            float lo = __uint_as_float(ulo), hi = __uint_as_float(uhi);
            int c0 = colBase + tx * 2 + 32 * j2;
            int c1 = c0 + 1;
            if (bias1)  { lo += bias1[c0];  hi += bias1[c1]; }
            if (bias2)  { lo += bias2[c0];  hi += bias2[c1]; }
            if (addRow) { lo += addRow[c0]; hi += addRow[c1]; }
            if (addM)   { lo += addM[(size_t)r * ldc + c0]; hi += addM[(size_t)r * ldc + c1]; }
            if (act == 1) { lo = fmaxf(lo, 0.f); hi = fmaxf(hi, 0.f); }
            else if (act == 2) { lo = tanhf(lo); hi = tanhf(hi); }
            *(float2*)(C + (size_t)r * ldc + c0) = make_float2(lo, hi);
        }
    }
}

// ---------------- residual + layernorm --------------------------------------
__global__ void posln_kernel(const float* __restrict__ O, float* __restrict__ X,
                             const float* __restrict__ g, const float* __restrict__ b)
{
    __shared__ float s_red[8];
    const int r = blockIdx.x, t = threadIdx.x;
    const int lane = t & 31, w = t >> 5;
    float z = O[(size_t)r * DMv + t] + X[(size_t)r * DMv + t];
    float v = z;
    #pragma unroll
    for (int o = 16; o; o >>= 1) v += __shfl_xor_sync(0xffffffffu, v, o);
    if (lane == 0) s_red[w] = v;
    __syncthreads();
    float mu = 0.f;
    #pragma unroll
    for (int i = 0; i < 8; ++i) mu += s_red[i];
    mu *= (1.f / 256.f);
    __syncthreads();
    float d = z - mu;
    v = d * d;
    #pragma unroll
    for (int o = 16; o; o >>= 1) v += __shfl_xor_sync(0xffffffffu, v, o);
    if (lane == 0) s_red[w] = v;
    __syncthreads();
    float var = 0.f;
    #pragma unroll
    for (int i = 0; i < 8; ++i) var += s_red[i];
    var *= (1.f / 255.f);
    X[(size_t)r * DMv + t] = d / (sqrtf(var) + 1e-3f) * g[t] + b[t];
}

// ---------------- support_g + l2 normalization ------------------------------
__global__ void sg_kernel(const float* __restrict__ X)
{
    __shared__ float s_red[8];
    const int t = threadIdx.x, lane = t & 31, w = t >> 5;
    float s = 0.f;
    #pragma unroll
    for (int i = 0; i < FEWv; ++i) s += X[(size_t)(Bv + i) * DMv + t];
    s *= (1.f / (float)FEWv);
    g_sg[t] = s;
    float v = s * s;
    #pragma unroll
    for (int o = 16; o; o >>= 1) v += __shfl_xor_sync(0xffffffffu, v, o);
    if (lane == 0) s_red[w] = v;
    __syncthreads();
    float nn = 0.f;
    #pragma unroll
    for (int i = 0; i < 8; ++i) nn += s_red[i];
    g_sgn[t] = s / fmaxf(sqrtf(nn), 1e-12f);
}

// ---------------- rt4 = w_hh[gmap(r), 256:512] @ support_g -----------------
__global__ void rterm_kernel(const float* __restrict__ w_hh)
{
    const int t = threadIdx.x, lane = t & 31, w = t >> 5;
    const int o = blockIdx.x * 8 + w;     // 0..1023
    const float* wr = w_hh + (size_t)gmap(o) * HIDv + DMv;
    float s = 0.f;
    #pragma unroll
    for (int q = 0; q < 8; ++q) s += g_sg[lane + q * 32] * wr[lane + q * 32];
    #pragma unroll
    for (int off = 16; off; off >>= 1) s += __shfl_xor_sync(0xffffffffu, s, off);
    if (lane == 0) g_rt4[o] = s;
}

// ---------------- LSTM cell elementwise (reduced to 256 hidden) ------------
__global__ void cell_kernel(const float* __restrict__ g, int first)
{
    const int idx = blockIdx.x * blockDim.x + threadIdx.x;  // over Bv*256
    const int b = idx >> 8, j = idx & 255;
    const float* gr = g + (size_t)b * G4;
    float gi = gr[j], gf = gr[256 + j], gG = gr[512 + j], go = gr[768 + j];
    float cv = first ? 0.f : g_C[idx];
    cv = sigm(gf) * cv + sigm(gi) * tanhf(gG);
    g_C[idx] = cv;
    g_h[(size_t)b * DMv + j] = g_X[(size_t)b * DMv + j] + sigm(go) * tanhf(cv);
}

// ---------------- final cosine against normalized support_g ----------------
__global__ void final_kernel(float* __restrict__ out)
{
    __shared__ float s_red[16];
    const int b = blockIdx.x, t = threadIdx.x, lane = t & 31, w = t >> 5;
    float hv = g_h[(size_t)b * DMv + t];
    float d = hv * g_sgn[t];
    float ss = hv * hv;
    #pragma unroll
    for (int o = 16; o; o >>= 1) {
        d  += __shfl_xor_sync(0xffffffffu, d,  o);
        ss += __shfl_xor_sync(0xffffffffu, ss, o);
    }
    if (lane == 0) { s_red[w] = d; s_red[8 + w] = ss; }
    __syncthreads();
    if (t == 0) {
        float Dd = 0.f, S = 0.f;
        #pragma unroll
        for (int i = 0; i < 8; ++i) { Dd += s_red[i]; S += s_red[8 + i]; }
        out[b] = Dd / fmaxf(sqrtf(S), 1e-12f);
    }
}

// ---------------- launcher ---------------------------------------------------
extern "C" void kernel_launch(void* const* d_in, const int* in_sizes, int n_in,
                              void* d_out, int out_size)
{
    const int*   query    = (const int*)  d_in[0];
    const int*   support  = (const int*)  d_in[1];
    const int*   q_l_conn = (const int*)  d_in[2];
    const int*   q_r_conn = (const int*)  d_in[4];
    const int*   s_l_conn = (const int*)  d_in[6];
    const int*   s_r_conn = (const int*)  d_in[8];
    const int*   knn      = (const int*)  d_in[10];
    const float* emb      = (const float*)d_in[11];
    const float* gcn_w    = (const float*)d_in[12];
    const float* gcn_wb   = (const float*)d_in[13];
    const float* gcn_b    = (const float*)d_in[14];
    const float* gate_w   = (const float*)d_in[15];
    const float* gate_b   = (const float*)d_in[16];
    const float* p1_w     = (const float*)d_in[17];
    const float* p1_b     = (const float*)d_in[18];
    const float* p2_w     = (const float*)d_in[19];
    const float* p2_b     = (const float*)d_in[20];
    const float* ln_g     = (const float*)d_in[21];
    const float* ln_b     = (const float*)d_in[22];
    const float* w_ih     = (const float*)d_in[23];
    const float* w_hh     = (const float*)d_in[24];
    const float* b_ih     = (const float*)d_in[25];
    const float* b_hh     = (const float*)d_in[26];

    float *pX, *pNA, *pNH, *pO, *pH, *pG0, *pGt, *ph, *prt, *pWih4, *pWhh4, *pb4;
    cudaGetSymbolAddress((void**)&pX,  g_X);
    cudaGetSymbolAddress((void**)&pNA, g_NA);
    cudaGetSymbolAddress((void**)&pNH, g_NH);
    cudaGetSymbolAddress((void**)&pO,  g_O);
    cudaGetSymbolAddress((void**)&pH,  g_H);
    cudaGetSymbolAddress((void**)&pG0, g_G0);
    cudaGetSymbolAddress((void**)&pGt, g_Gt);
    cudaGetSymbolAddress((void**)&ph,  g_h);
    cudaGetSymbolAddress((void**)&prt, g_rt4);
    cudaGetSymbolAddress((void**)&pWih4, g_Wih4);
    cudaGetSymbolAddress((void**)&pWhh4, g_Whh4);
    cudaGetSymbolAddress((void**)&pb4, g_b4);

    // 0) pack reduced gate weights (independent of everything else)
    pack_w<<<G4, 256>>>(w_ih, w_hh, b_ih, b_hh);

    // 1) neighbor encoder
    ne_sims<<<NUNIT, 256>>>(query, support, q_l_conn, q_r_conn, s_l_conn, s_r_conn,
                            knn, emb, pNA);
    gemm_nt<<<dim3(1, (2*NUNIT + 63)/64), 256>>>(pNA, DMv, gcn_w, DMv, pNH, Dv,
                                                 2*NUNIT, Dv, DMv, gcn_wb, gcn_b,
                                                 nullptr, nullptr, 2);
    ne_fin<<<NUNIT, 128>>>(pNH, gate_w, gate_b, pX);

    // 2) support encoder
    gemm_nt<<<dim3(HIDv/128, (NROWS + 63)/64), 256>>>(pX, DMv, p1_w, DMv, pH, HIDv,
                                                      NROWS, HIDv, DMv, p1_b, nullptr,
                                                      nullptr, nullptr, 1);
    gemm_nt<<<dim3(DMv/128, (NROWS + 63)/64), 256>>>(pH, HIDv, p2_w, HIDv, pO, DMv,
                                                     NROWS, DMv, HIDv, p2_b, nullptr,
                                                     nullptr, nullptr, 0);
    posln_kernel<<<NROWS, 256>>>(pO, pX, ln_g, ln_b);

    // 3) support_g, normalization, reduced r-term
    sg_kernel<<<1, 256>>>(pX);
    rterm_kernel<<<G4/8, 256>>>(w_hh);

    // 4) G0 = query_g @ Wih4^T + b4   [2048, 1024]
    gemm_nt<<<dim3(G4/128, Bv/64), 256>>>(pX, DMv, pWih4, DMv, pG0, G4,
                                          Bv, G4, DMv, pb4, nullptr,
                                          nullptr, nullptr, 0);

    // 5) LSTM: step 1 uses G0 (h_r = 0); steps 2-4 add h @ Whh4^T + rt4
    cell_kernel<<<(Bv * DMv) / 256, 256>>>(pG0, 1);
    for (int s = 0; s < 3; ++s) {
        gemm_nt<<<dim3(G4/128, Bv/64), 256>>>(ph, DMv, pWhh4, DMv, pGt, G4,
                                              Bv, G4, DMv, nullptr, nullptr,
                                              pG0, prt, 0);
        cell_kernel<<<(Bv * DMv) / 256, 256>>>(pGt, 0);
    }

    // 6) out[b] = l2n(h[b]) . l2n(support_g)
    final_kernel<<<Bv, 256>>>((float*)d_out);

    (void)in_sizes; (void)n_in; (void)out_size;
}

// round 5
// speedup vs baseline: 3.5294x; 1.1488x over previous
#include <cuda_runtime.h>
#include <math.h>

#define Dv    128
#define Mv    128
#define KTABv 64
#define Kv    32
#define Bv    2048
#define FEWv  5
#define DMv   256
#define HIDv  512
#define NSYMv 100000
#define NROWS (Bv + FEWv)     /* 2053 */
#define NUNIT (2*Bv + 2*FEWv) /* 4106 */
#define G4    1024            /* packed gate width: 4 gates x 256 */

// ---------------- scratch (device globals) ----------------------------------
__device__ float g_X [NROWS * DMv];
__device__ float g_NA[(size_t)2 * NUNIT * DMv];
__device__ float g_O [NROWS * DMv];
__device__ float g_H [NROWS * HIDv];
__device__ float g_G0[(size_t)Bv * G4];
__device__ float g_C [Bv * DMv];
__device__ float g_h [Bv * DMv];
__device__ float g_sg [DMv];
__device__ float g_sgn[DMv];
__device__ float g_rt4[G4];
__device__ float g_Wih4[G4 * DMv];
__device__ float g_Whh4[G4 * DMv];
__device__ float g_b4[G4];

__device__ __forceinline__ float sigm(float x) { return 1.f / (1.f + expf(-x)); }

// ================= pack interleaved gate weights =============================
// packed row r = 4*j + gate  <-  original row m = gate*512 + j (reduced j<256)
__global__ void pack_w(const float* __restrict__ w_ih, const float* __restrict__ w_hh,
                       const float* __restrict__ b_ih, const float* __restrict__ b_hh)
{
    const int r = blockIdx.x, t = threadIdx.x;
    const int j = r >> 2, gate = r & 3;
    const int m = gate * 512 + j;
    g_Wih4[(size_t)r * DMv + t] = w_ih[(size_t)m * DMv + t];
    g_Whh4[(size_t)r * DMv + t] = w_hh[(size_t)m * HIDv + t];
    if (t == 0) g_b4[r] = b_ih[m] + b_hh[m];
}

// ================= neighbor encoder: sims + topk + means (float4) ===========
__global__ __launch_bounds__(256) void ne_sims(
    const int* __restrict__ query, const int* __restrict__ support,
    const int* __restrict__ q_l_conn, const int* __restrict__ q_r_conn,
    const int* __restrict__ s_l_conn, const int* __restrict__ s_r_conn,
    const int* __restrict__ knn, const float* __restrict__ emb,
    float* __restrict__ NA)
{
    __shared__ float4 s_center4[32];
    __shared__ float4 s_pad4[32];
    __shared__ float  s_sims[Mv];
    __shared__ float  s_sims2[KTABv];
    __shared__ int    s_rel[Mv], s_ent[Mv], s_kid[KTABv];
    __shared__ int    s_lst1[Kv], s_lst2[Kv];
    __shared__ float4 s_par[12][32];
    __shared__ float  s_cn;

    const int u   = blockIdx.x;
    const int tid = threadIdx.x;
    const int lane = tid & 31, w = tid >> 5;

    const int* conn; int id;
    if (u < Bv)            { conn = q_l_conn + (size_t)u * (Mv*2);            id = query[u*2+0]; }
    else if (u < 2*Bv)     { int v = u - Bv;    conn = q_r_conn + (size_t)v*(Mv*2); id = query[v*2+1]; }
    else if (u < 2*Bv+FEWv){ int v = u - 2*Bv;  conn = s_l_conn + (size_t)v*(Mv*2); id = support[v*2+0]; }
    else                   { int v = u - (2*Bv+FEWv); conn = s_r_conn + (size_t)v*(Mv*2); id = support[v*2+1]; }

    if (tid < 32) {
        float4 cv = __ldg((const float4*)(emb + (size_t)id * Dv) + tid);
        s_center4[tid] = cv;
        float v = cv.x*cv.x + cv.y*cv.y + cv.z*cv.z + cv.w*cv.w;
        #pragma unroll
        for (int o = 16; o; o >>= 1) v += __shfl_xor_sync(0xffffffffu, v, o);
        if (tid == 0) s_cn = sqrtf(v);
    } else if (tid < 64) {
        s_pad4[tid - 32] = __ldg((const float4*)(emb + (size_t)NSYMv * Dv) + (tid - 32));
    } else if (tid < 192) {
        int m = tid - 64;
        int2 rc = ((const int2*)conn)[m];
        s_rel[m] = rc.x; s_ent[m] = rc.y;
    } else {
        int m = tid - 192;
        s_kid[m] = knn[(size_t)id * KTABv + m];
    }
    __syncthreads();
    const float  cn = s_cn;
    const float4 c4 = s_center4[lane];

    // conn sims: warp w handles m in [w*16, w*16+16), 4 rows in flight
    #pragma unroll
    for (int i = 0; i < 16; i += 4) {
        float dt[4], nr[4];
        #pragma unroll
        for (int r = 0; r < 4; ++r) {
            int m = w * 16 + i + r;
            float4 x = __ldg((const float4*)(emb + (size_t)s_ent[m] * Dv) + lane);
            dt[r] = c4.x*x.x + c4.y*x.y + c4.z*x.z + c4.w*x.w;
            nr[r] = x.x*x.x + x.y*x.y + x.z*x.z + x.w*x.w;
        }
        #pragma unroll
        for (int o = 16; o; o >>= 1) {
            #pragma unroll
            for (int r = 0; r < 4; ++r) {
                dt[r] += __shfl_xor_sync(0xffffffffu, dt[r], o);
                nr[r] += __shfl_xor_sync(0xffffffffu, nr[r], o);
            }
        }
        if (lane == 0) {
            #pragma unroll
            for (int r = 0; r < 4; ++r)
                s_sims[w*16 + i + r] = dt[r] / fmaxf(cn * sqrtf(nr[r]), 1e-8f);
        }
    }
    // knn sims: warp w handles m in [w*8, w*8+8), 4 rows in flight
    #pragma unroll
    for (int i = 0; i < 8; i += 4) {
        float dt[4], nr[4];
        #pragma unroll
        for (int r = 0; r < 4; ++r) {
            int m = w * 8 + i + r;
            float4 x = __ldg((const float4*)(emb + (size_t)s_kid[m] * Dv) + lane);
            dt[r] = c4.x*x.x + c4.y*x.y + c4.z*x.z + c4.w*x.w;
            nr[r] = x.x*x.x + x.y*x.y + x.z*x.z + x.w*x.w;
        }
        #pragma unroll
        for (int o = 16; o; o >>= 1) {
            #pragma unroll
            for (int r = 0; r < 4; ++r) {
                dt[r] += __shfl_xor_sync(0xffffffffu, dt[r], o);
                nr[r] += __shfl_xor_sync(0xffffffffu, nr[r], o);
            }
        }
        if (lane == 0) {
            #pragma unroll
            for (int r = 0; r < 4; ++r)
                s_sims2[w*8 + i + r] = dt[r] / fmaxf(cn * sqrtf(nr[r]), 1e-8f);
        }
    }
    __syncthreads();

    // stable top-K (jax.lax.top_k tie-break) with rank-scatter compaction
    if (tid < Mv) {
        float my = s_sims[tid];
        int cnt = 0;
        #pragma unroll 8
        for (int j = 0; j < Mv; ++j) {
            float o = s_sims[j];
            cnt += (o > my) || (o == my && j < tid);
        }
        if (cnt < Kv) s_lst1[cnt] = tid;
    } else if (tid < Mv + KTABv) {
        int m = tid - Mv;
        float my = s_sims2[m];
        int cnt = 0;
        #pragma unroll 8
        for (int j = 0; j < KTABv; ++j) {
            float o = s_sims2[j];
            cnt += (o > my) || (o == my && j < m);
        }
        if (cnt < Kv) s_lst2[cnt] = m;
    }
    __syncthreads();

    // gather means: warps 0-3 accumulate rel+ent over lst1, warps 4-7 knn over lst2
    float4 a1 = make_float4(0.f,0.f,0.f,0.f), a2 = make_float4(0.f,0.f,0.f,0.f);
    if (w < 4) {
        #pragma unroll
        for (int e = 0; e < 8; ++e) {
            int m = s_lst1[w*8 + e];
            float4 xr = __ldg((const float4*)(emb + (size_t)s_rel[m] * Dv) + lane);
            float4 xe = __ldg((const float4*)(emb + (size_t)s_ent[m] * Dv) + lane);
            a1.x += xr.x; a1.y += xr.y; a1.z += xr.z; a1.w += xr.w;
            a2.x += xe.x; a2.y += xe.y; a2.z += xe.z; a2.w += xe.w;
        }
        s_par[w][lane] = a1;
        s_par[4 + w][lane] = a2;
    } else {
        #pragma unroll
        for (int e = 0; e < 8; ++e) {
            int m = s_lst2[(w-4)*8 + e];
            float4 xk = __ldg((const float4*)(emb + (size_t)s_kid[m] * Dv) + lane);
            a1.x += xk.x; a1.y += xk.y; a1.z += xk.z; a1.w += xk.w;
        }
        s_par[4 + w][lane] = a1;   // rows 8..11
    }
    __syncthreads();

    const float inv = 1.f / (float)Kv;
    if (w < 3) {
        int base = w * 4;   // 0: mr (rows 0-3), 1: me (4-7), 2: mk (8-11)
        float4 p0 = s_par[base+0][lane], p1 = s_par[base+1][lane];
        float4 p2 = s_par[base+2][lane], p3 = s_par[base+3][lane];
        float4 s;
        s.x = (p0.x + p1.x + p2.x + p3.x) * inv;
        s.y = (p0.y + p1.y + p2.y + p3.y) * inv;
        s.z = (p0.z + p1.z + p2.z + p3.z) * inv;
        s.w = (p0.w + p1.w + p2.w + p3.w) * inv;
        size_t off;
        if (w == 0)      off = (size_t)(2*u) * DMv;            // mr
        else if (w == 1) off = (size_t)(2*u) * DMv + Dv;       // me
        else             off = (size_t)(2*u + 1) * DMv + Dv;   // mk
        ((float4*)(NA + off))[lane] = s;
    } else if (w == 3) {
        ((float4*)(NA + (size_t)(2*u + 1) * DMv))[lane] = s_pad4[lane]; // pad
    }
}

// ================= fused GCN GEMM + tanh + gate + combine ====================
// C_rows = 2*NUNIT (interleaved struct/knn), N = 128 (single col tile), K = 256
#define AS(b,k,x) s_all[(b)*1088 + (k)*68 + (x)]
#define BS(b,k,x) s_all[2176 + (b)*2112 + (k)*132 + (x)]
#define SG(r,c)   s_all[(r)*132 + (c)]

__global__ __launch_bounds__(256) void gemm_gcn(
    const float* __restrict__ A,       // g_NA
    const float* __restrict__ Bw,      // gcn_w [128,256]
    const float* __restrict__ wb, const float* __restrict__ gb,
    const float* __restrict__ gate_w, const float* __restrict__ gate_b,
    float* __restrict__ X)
{
    __shared__ float s_all[8448];
    const int tid = threadIdx.x;
    const int tx = tid & 15, ty = tid >> 4;
    const int rowBase = blockIdx.x * 64;
    const int Nr = 2 * NUNIT;

    unsigned long long acc[4][4];
    #pragma unroll
    for (int i = 0; i < 4; ++i)
        #pragma unroll
        for (int j = 0; j < 4; ++j) acc[i][j] = 0ull;

    const int arow = tid >> 2, akoff = (tid & 3) * 4;
    const int brow = tid >> 1, bkoff = (tid & 1) * 8;

    float4 pa, pb0, pb1;
    {
        int r = rowBase + arow;
        float4 v = make_float4(0.f,0.f,0.f,0.f);
        if (r < Nr) v = *(const float4*)(A + (size_t)r * DMv + akoff);
        AS(0,akoff+0,arow)=v.x; AS(0,akoff+1,arow)=v.y;
        AS(0,akoff+2,arow)=v.z; AS(0,akoff+3,arow)=v.w;
        const float* p = Bw + (size_t)brow * DMv + bkoff;
        float4 v0 = *(const float4*)p;
        float4 v1 = *(const float4*)(p + 4);
        BS(0,bkoff+0,brow)=v0.x; BS(0,bkoff+1,brow)=v0.y;
        BS(0,bkoff+2,brow)=v0.z; BS(0,bkoff+3,brow)=v0.w;
        BS(0,bkoff+4,brow)=v1.x; BS(0,bkoff+5,brow)=v1.y;
        BS(0,bkoff+6,brow)=v1.z; BS(0,bkoff+7,brow)=v1.w;
    }
    __syncthreads();

    int buf = 0;
    const int nk = DMv >> 4;   // 16
    for (int it = 0; it < nk; ++it) {
        if (it + 1 < nk) {
            int k0 = (it + 1) << 4;
            int r = rowBase + arow;
            pa = make_float4(0.f,0.f,0.f,0.f);
            if (r < Nr) pa = *(const float4*)(A + (size_t)r * DMv + k0 + akoff);
            const float* p = Bw + (size_t)brow * DMv + k0 + bkoff;
            pb0 = *(const float4*)p;
            pb1 = *(const float4*)(p + 4);
        }
        #pragma unroll
        for (int k = 0; k < 16; ++k) {
            float4 a = *(const float4*)&AS(buf,k,ty*4);
            unsigned long long av[4];
            {
                unsigned u0 = __float_as_uint(a.x), u1 = __float_as_uint(a.y);
                unsigned u2 = __float_as_uint(a.z), u3 = __float_as_uint(a.w);
                asm("mov.b64 %0, {%1, %1};" : "=l"(av[0]) : "r"(u0));
                asm("mov.b64 %0, {%1, %1};" : "=l"(av[1]) : "r"(u1));
                asm("mov.b64 %0, {%1, %1};" : "=l"(av[2]) : "r"(u2));
                asm("mov.b64 %0, {%1, %1};" : "=l"(av[3]) : "r"(u3));
            }
            unsigned long long bv[4];
            #pragma unroll
            for (int j2 = 0; j2 < 4; ++j2)
                bv[j2] = *(const unsigned long long*)&BS(buf,k,tx*2+32*j2);
            #pragma unroll
            for (int i = 0; i < 4; ++i)
                #pragma unroll
                for (int j2 = 0; j2 < 4; ++j2)
                    asm("fma.rn.f32x2 %0, %1, %2, %0;" : "+l"(acc[i][j2]) : "l"(av[i]), "l"(bv[j2]));
        }
        if (it + 1 < nk) {
            int nb = buf ^ 1;
            AS(nb,akoff+0,arow)=pa.x; AS(nb,akoff+1,arow)=pa.y;
            AS(nb,akoff+2,arow)=pa.z; AS(nb,akoff+3,arow)=pa.w;
            BS(nb,bkoff+0,brow)=pb0.x; BS(nb,bkoff+1,brow)=pb0.y;
            BS(nb,bkoff+2,brow)=pb0.z; BS(nb,bkoff+3,brow)=pb0.w;
            BS(nb,bkoff+4,brow)=pb1.x; BS(nb,bkoff+5,brow)=pb1.y;
            BS(nb,bkoff+6,brow)=pb1.z; BS(nb,bkoff+7,brow)=pb1.w;
            __syncthreads();
            buf = nb;
        }
    }
    __syncthreads();   // smem reuse barrier

    // tanh epilogue into SG
    #pragma unroll
    for (int i = 0; i < 4; ++i) {
        #pragma unroll
        for (int j2 = 0; j2 < 4; ++j2) {
            unsigned ulo, uhi;
            asm("mov.b64 {%0, %1}, %2;" : "=r"(ulo), "=r"(uhi) : "l"(acc[i][j2]));
            int c0 = tx*2 + 32*j2;
            float lo = tanhf(__uint_as_float(ulo) + wb[c0]   + gb[c0]);
            float hi = tanhf(__uint_as_float(uhi) + wb[c0+1] + gb[c0+1]);
            SG(ty*4+i, c0)   = lo;
            SG(ty*4+i, c0+1) = hi;
        }
    }
    __syncthreads();

    // gate + combine: 8 threads per unit (32 units per block)
    const int t = tid >> 3, sub = tid & 7;
    const int u = (rowBase >> 1) + t;
    if (u < NUNIT) {
        float gv = 0.f;
        #pragma unroll
        for (int k = 0; k < 16; ++k) {
            int c = sub*16 + k;
            gv += SG(2*t, c) * gate_w[c] + SG(2*t+1, c) * gate_w[128 + c];
        }
        gv += __shfl_xor_sync(0xffffffffu, gv, 1);
        gv += __shfl_xor_sync(0xffffffffu, gv, 2);
        gv += __shfl_xor_sync(0xffffffffu, gv, 4);
        float a = sigm(gv + gate_b[0]);
        int row, col;
        if (u < Bv)             { row = u;                      col = 0; }
        else if (u < 2*Bv)      { row = u - Bv;                 col = Dv; }
        else if (u < 2*Bv+FEWv) { row = Bv + (u - 2*Bv);        col = 0; }
        else                    { row = Bv + (u - 2*Bv - FEWv); col = Dv; }
        float* xp = X + (size_t)row * DMv + col;
        #pragma unroll
        for (int k4 = 0; k4 < 4; ++k4) {
            int c = sub*16 + k4*4;
            float4 st = *(const float4*)&SG(2*t, c);
            float4 kn = *(const float4*)&SG(2*t+1, c);
            float4 o;
            o.x = (1.f - a)*st.x + a*kn.x;
            o.y = (1.f - a)*st.y + a*kn.y;
            o.z = (1.f - a)*st.z + a*kn.z;
            o.w = (1.f - a)*st.w + a*kn.w;
            *(float4*)(xp + c) = o;
        }
    }
}

// ================= fused gate GEMM + LSTM cell ===============================
// A [2048,256] @ W4^T [1024,256]; interleaved cols c = 4*j + gate
__global__ __launch_bounds__(256) void gemm_gates(
    const float* __restrict__ A, const float* __restrict__ Bw, int first)
{
    __shared__ float s_all[8448];
    const int tid = threadIdx.x;
    const int tx = tid & 15, ty = tid >> 4;
    const int rowBase = blockIdx.y * 64;
    const int colBase = blockIdx.x * 128;

    unsigned long long acc[4][4];
    #pragma unroll
    for (int i = 0; i < 4; ++i)
        #pragma unroll
        for (int j = 0; j < 4; ++j) acc[i][j] = 0ull;

    const int arow = tid >> 2, akoff = (tid & 3) * 4;
    const int brow = tid >> 1, bkoff = (tid & 1) * 8;

    float4 pa, pb0, pb1;
    {
        float4 v = *(const float4*)(A + (size_t)(rowBase + arow) * DMv + akoff);
        AS(0,akoff+0,arow)=v.x; AS(0,akoff+1,arow)=v.y;
        AS(0,akoff+2,arow)=v.z; AS(0,akoff+3,arow)=v.w;
        const float* p = Bw + (size_t)(colBase + brow) * DMv + bkoff;
        float4 v0 = *(const float4*)p;
        float4 v1 = *(const float4*)(p + 4);
        BS(0,bkoff+0,brow)=v0.x; BS(0,bkoff+1,brow)=v0.y;
        BS(0,bkoff+2,brow)=v0.z; BS(0,bkoff+3,brow)=v0.w;
        BS(0,bkoff+4,brow)=v1.x; BS(0,bkoff+5,brow)=v1.y;
        BS(0,bkoff+6,brow)=v1.z; BS(0,bkoff+7,brow)=v1.w;
    }
    __syncthreads();

    int buf = 0;
    const int nk = DMv >> 4;
    for (int it = 0; it < nk; ++it) {
        if (it + 1 < nk) {
            int k0 = (it + 1) << 4;
            pa = *(const float4*)(A + (size_t)(rowBase + arow) * DMv + k0 + akoff);
            const float* p = Bw + (size_t)(colBase + brow) * DMv + k0 + bkoff;
            pb0 = *(const float4*)p;
            pb1 = *(const float4*)(p + 4);
        }
        #pragma unroll
        for (int k = 0; k < 16; ++k) {
            float4 a = *(const float4*)&AS(buf,k,ty*4);
            unsigned long long av[4];
            {
                unsigned u0 = __float_as_uint(a.x), u1 = __float_as_uint(a.y);
                unsigned u2 = __float_as_uint(a.z), u3 = __float_as_uint(a.w);
                asm("mov.b64 %0, {%1, %1};" : "=l"(av[0]) : "r"(u0));
                asm("mov.b64 %0, {%1, %1};" : "=l"(av[1]) : "r"(u1));
                asm("mov.b64 %0, {%1, %1};" : "=l"(av[2]) : "r"(u2));
                asm("mov.b64 %0, {%1, %1};" : "=l"(av[3]) : "r"(u3));
            }
            unsigned long long bv[4];
            #pragma unroll
            for (int j2 = 0; j2 < 4; ++j2)
                bv[j2] = *(const unsigned long long*)&BS(buf,k,tx*2+32*j2);
            #pragma unroll
            for (int i = 0; i < 4; ++i)
                #pragma unroll
                for (int j2 = 0; j2 < 4; ++j2)
                    asm("fma.rn.f32x2 %0, %1, %2, %0;" : "+l"(acc[i][j2]) : "l"(av[i]), "l"(bv[j2]));
        }
        if (it + 1 < nk) {
            int nb = buf ^ 1;
            AS(nb,akoff+0,arow)=pa.x; AS(nb,akoff+1,arow)=pa.y;
            AS(nb,akoff+2,arow)=pa.z; AS(nb,akoff+3,arow)=pa.w;
            BS(nb,bkoff+0,brow)=pb0.x; BS(nb,bkoff+1,brow)=pb0.y;
            BS(nb,bkoff+2,brow)=pb0.z; BS(nb,bkoff+3,brow)=pb0.w;
            BS(nb,bkoff+4,brow)=pb1.x; BS(nb,bkoff+5,brow)=pb1.y;
            BS(nb,bkoff+6,brow)=pb1.z; BS(nb,bkoff+7,brow)=pb1.w;
            __syncthreads();
            buf = nb;
        }
    }
    __syncthreads();   // smem reuse barrier

    // gate epilogue into SG (+ G0 store/load)
    #pragma unroll
    for (int i = 0; i < 4; ++i) {
        int r = rowBase + ty*4 + i;
        #pragma unroll
        for (int j2 = 0; j2 < 4; ++j2) {
            unsigned ulo, uhi;
            asm("mov.b64 {%0, %1}, %2;" : "=r"(ulo), "=r"(uhi) : "l"(acc[i][j2]));
            float lo = __uint_as_float(ulo), hi = __uint_as_float(uhi);
            int lc = tx*2 + 32*j2;
            int c0 = colBase + lc;
            if (first) {
                lo += g_b4[c0]; hi += g_b4[c0+1];
                *(float2*)&g_G0[(size_t)r * G4 + c0] = make_float2(lo, hi);
            } else {
                float2 g0 = *(const float2*)&g_G0[(size_t)r * G4 + c0];
                lo += g0.x + g_rt4[c0];
                hi += g0.y + g_rt4[c0+1];
            }
            SG(ty*4+i, lc)   = lo;
            SG(ty*4+i, lc+1) = hi;
        }
    }
    __syncthreads();

    // LSTM cell: 64 rows x 32 units in this block
    #pragma unroll
    for (int k = 0; k < 8; ++k) {
        int idx = tid + k*256;
        int row = idx >> 5, jl = idx & 31;
        float4 gv = *(const float4*)&SG(row, jl*4);   // (i, f, g, o)
        int b = rowBase + row;
        int j = (colBase >> 2) + jl;
        int ci = b * DMv + j;
        float cv = first ? 0.f : g_C[ci];
        cv = sigm(gv.y) * cv + sigm(gv.x) * tanhf(gv.z);
        g_C[ci] = cv;
        g_h[ci] = g_X[ci] + sigm(gv.w) * tanhf(cv);
    }
}

// ================= generic fp32x2 GEMM (support encoder) ====================
__global__ __launch_bounds__(256) void gemm_nt(
    const float* __restrict__ A, int lda,
    const float* __restrict__ Bw, int ldb,
    float* __restrict__ C, int ldc,
    int Nr, int Nc, int Kd,
    const float* __restrict__ bias1,
    int act)  // 0 none, 1 relu
{
    __shared__ float As[2][16][68];
    __shared__ float Bs[2][16][132];
    const int tid = threadIdx.x;
    const int tx = tid & 15, ty = tid >> 4;
    const int rowBase = blockIdx.y * 64;
    const int colBase = blockIdx.x * 128;

    unsigned long long acc[4][4];
    #pragma unroll
    for (int i = 0; i < 4; ++i)
        #pragma unroll
        for (int j = 0; j < 4; ++j) acc[i][j] = 0ull;

    const int arow = tid >> 2, akoff = (tid & 3) * 4;
    const int brow = tid >> 1, bkoff = (tid & 1) * 8;
    const int nk = Kd >> 4;

    float4 pa, pb0, pb1;
    {
        int r = rowBase + arow;
        float4 v = make_float4(0.f,0.f,0.f,0.f);
        if (r < Nr) v = *(const float4*)(A + (size_t)r * lda + akoff);
        As[0][akoff+0][arow]=v.x; As[0][akoff+1][arow]=v.y;
        As[0][akoff+2][arow]=v.z; As[0][akoff+3][arow]=v.w;
        const float* p = Bw + (size_t)(colBase + brow) * ldb + bkoff;
        float4 v0 = *(const float4*)p;
        float4 v1 = *(const float4*)(p + 4);
        Bs[0][bkoff+0][brow]=v0.x; Bs[0][bkoff+1][brow]=v0.y;
        Bs[0][bkoff+2][brow]=v0.z; Bs[0][bkoff+3][brow]=v0.w;
        Bs[0][bkoff+4][brow]=v1.x; Bs[0][bkoff+5][brow]=v1.y;
        Bs[0][bkoff+6][brow]=v1.z; Bs[0][bkoff+7][brow]=v1.w;
    }
    __syncthreads();

    int buf = 0;
    for (int it = 0; it < nk; ++it) {
        if (it + 1 < nk) {
            int k0 = (it + 1) << 4;
            int r = rowBase + arow;
            pa = make_float4(0.f,0.f,0.f,0.f);
            if (r < Nr) pa = *(const float4*)(A + (size_t)r * lda + k0 + akoff);
            const float* p = Bw + (size_t)(colBase + brow) * ldb + k0 + bkoff;
            pb0 = *(const float4*)p;
            pb1 = *(const float4*)(p + 4);
        }
        #pragma unroll
        for (int k = 0; k < 16; ++k) {
            float4 a = *(const float4*)&As[buf][k][ty*4];
            unsigned long long av[4];
            {
                unsigned u0 = __float_as_uint(a.x), u1 = __float_as_uint(a.y);
                unsigned u2 = __float_as_uint(a.z), u3 = __float_as_uint(a.w);
                asm("mov.b64 %0, {%1, %1};" : "=l"(av[0]) : "r"(u0));
                asm("mov.b64 %0, {%1, %1};" : "=l"(av[1]) : "r"(u1));
                asm("mov.b64 %0, {%1, %1};" : "=l"(av[2]) : "r"(u2));
                asm("mov.b64 %0, {%1, %1};" : "=l"(av[3]) : "r"(u3));
            }
            unsigned long long bv[4];
            #pragma unroll
            for (int j2 = 0; j2 < 4; ++j2)
                bv[j2] = *(const unsigned long long*)&Bs[buf][k][tx*2+32*j2];
            #pragma unroll
            for (int i = 0; i < 4; ++i)
                #pragma unroll
                for (int j2 = 0; j2 < 4; ++j2)
                    asm("fma.rn.f32x2 %0, %1, %2, %0;" : "+l"(acc[i][j2]) : "l"(av[i]), "l"(bv[j2]));
        }
        if (it + 1 < nk) {
            int nb = buf ^ 1;
            As[nb][akoff+0][arow]=pa.x; As[nb][akoff+1][arow]=pa.y;
            As[nb][akoff+2][arow]=pa.z; As[nb][akoff+3][arow]=pa.w;
            Bs[nb][bkoff+0][brow]=pb0.x; Bs[nb][bkoff+1][brow]=pb0.y;
            Bs[nb][bkoff+2][brow]=pb0.z; Bs[nb][bkoff+3][brow]=pb0.w;
            Bs[nb][bkoff+4][brow]=pb1.x; Bs[nb][bkoff+5][brow]=pb1.y;
            Bs[nb][bkoff+6][brow]=pb1.z; Bs[nb][bkoff+7][brow]=pb1.w;
            __syncthreads();
            buf = nb;
        }
    }

    #pragma unroll
    for (int i = 0; i < 4; ++i) {
        int r = rowBase + ty*4 + i;
        if (r >= Nr) continue;
        #pragma unroll
        for (int j2 = 0; j2 < 4; ++j2) {
            unsigned ulo, uhi;
            asm("mov.b64 {%0, %1}, %2;" : "=r"(ulo), "=r"(uhi) : "l"(acc[i][j2]));
            float lo = __uint_as_float(ulo), hi = __uint_as_float(uhi);
            int c0 = colBase + tx*2 + 32*j2;
            if (bias1) { lo += bias1[c0]; hi += bias1[c0+1]; }
            if (act == 1) { lo = fmaxf(lo, 0.f); hi = fmaxf(hi, 0.f); }
            *(float2*)(C + (size_t)r * ldc + c0) = make_float2(lo, hi);
        }
    }
}

// ---------------- residual + layernorm --------------------------------------
__global__ void posln_kernel(const float* __restrict__ O, float* __restrict__ X,
                             const float* __restrict__ g, const float* __restrict__ b)
{
    __shared__ float s_red[8];
    const int r = blockIdx.x, t = threadIdx.x;
    const int lane = t & 31, w = t >> 5;
    float z = O[(size_t)r * DMv + t] + X[(size_t)r * DMv + t];
    float v = z;
    #pragma unroll
    for (int o = 16; o; o >>= 1) v += __shfl_xor_sync(0xffffffffu, v, o);
    if (lane == 0) s_red[w] = v;
    __syncthreads();
    float mu = 0.f;
    #pragma unroll
    for (int i = 0; i < 8; ++i) mu += s_red[i];
    mu *= (1.f / 256.f);
    __syncthreads();
    float d = z - mu;
    v = d * d;
    #pragma unroll
    for (int o = 16; o; o >>= 1) v += __shfl_xor_sync(0xffffffffu, v, o);
    if (lane == 0) s_red[w] = v;
    __syncthreads();
    float var = 0.f;
    #pragma unroll
    for (int i = 0; i < 8; ++i) var += s_red[i];
    var *= (1.f / 255.f);
    X[(size_t)r * DMv + t] = d / (sqrtf(var) + 1e-3f) * g[t] + b[t];
}

// ---------------- support_g + l2 normalization ------------------------------
__global__ void sg_kernel(const float* __restrict__ X)
{
    __shared__ float s_red[8];
    const int t = threadIdx.x, lane = t & 31, w = t >> 5;
    float s = 0.f;
    #pragma unroll
    for (int i = 0; i < FEWv; ++i) s += X[(size_t)(Bv + i) * DMv + t];
    s *= (1.f / (float)FEWv);
    g_sg[t] = s;
    float v = s * s;
    #pragma unroll
    for (int o = 16; o; o >>= 1) v += __shfl_xor_sync(0xffffffffu, v, o);
    if (lane == 0) s_red[w] = v;
    __syncthreads();
    float nn = 0.f;
    #pragma unroll
    for (int i = 0; i < 8; ++i) nn += s_red[i];
    g_sgn[t] = s / fmaxf(sqrtf(nn), 1e-12f);
}

// ---------------- rt4[4j+g] = w_hh[g*512+j, 256:512] @ support_g ------------
__global__ void rterm_kernel(const float* __restrict__ w_hh)
{
    const int t = threadIdx.x, lane = t & 31, w = t >> 5;
    const int o = blockIdx.x * 8 + w;     // 0..1023 packed index
    const int j = o >> 2, gate = o & 3;
    const float* wr = w_hh + (size_t)(gate * 512 + j) * HIDv + DMv;
    float s = 0.f;
    #pragma unroll
    for (int q = 0; q < 8; ++q) s += g_sg[lane + q * 32] * wr[lane + q * 32];
    #pragma unroll
    for (int off = 16; off; off >>= 1) s += __shfl_xor_sync(0xffffffffu, s, off);
    if (lane == 0) g_rt4[o] = s;
}

// ---------------- final cosine against normalized support_g ----------------
__global__ void final_kernel(float* __restrict__ out)
{
    __shared__ float s_red[16];
    const int b = blockIdx.x, t = threadIdx.x, lane = t & 31, w = t >> 5;
    float hv = g_h[(size_t)b * DMv + t];
    float d = hv * g_sgn[t];
    float ss = hv * hv;
    #pragma unroll
    for (int o = 16; o; o >>= 1) {
        d  += __shfl_xor_sync(0xffffffffu, d,  o);
        ss += __shfl_xor_sync(0xffffffffu, ss, o);
    }
    if (lane == 0) { s_red[w] = d; s_red[8 + w] = ss; }
    __syncthreads();
    if (t == 0) {
        float Dd = 0.f, S = 0.f;
        #pragma unroll
        for (int i = 0; i < 8; ++i) { Dd += s_red[i]; S += s_red[8 + i]; }
        out[b] = Dd / fmaxf(sqrtf(S), 1e-12f);
    }
}

// ---------------- launcher ---------------------------------------------------
extern "C" void kernel_launch(void* const* d_in, const int* in_sizes, int n_in,
                              void* d_out, int out_size)
{
    const int*   query    = (const int*)  d_in[0];
    const int*   support  = (const int*)  d_in[1];
    const int*   q_l_conn = (const int*)  d_in[2];
    const int*   q_r_conn = (const int*)  d_in[4];
    const int*   s_l_conn = (const int*)  d_in[6];
    const int*   s_r_conn = (const int*)  d_in[8];
    const int*   knn      = (const int*)  d_in[10];
    const float* emb      = (const float*)d_in[11];
    const float* gcn_w    = (const float*)d_in[12];
    const float* gcn_wb   = (const float*)d_in[13];
    const float* gcn_b    = (const float*)d_in[14];
    const float* gate_w   = (const float*)d_in[15];
    const float* gate_b   = (const float*)d_in[16];
    const float* p1_w     = (const float*)d_in[17];
    const float* p1_b     = (const float*)d_in[18];
    const float* p2_w     = (const float*)d_in[19];
    const float* p2_b     = (const float*)d_in[20];
    const float* ln_g     = (const float*)d_in[21];
    const float* ln_b     = (const float*)d_in[22];
    const float* w_ih     = (const float*)d_in[23];
    const float* w_hh     = (const float*)d_in[24];
    const float* b_ih     = (const float*)d_in[25];
    const float* b_hh     = (const float*)d_in[26];

    float *pX, *pNA, *pO, *pH, *ph, *pWih4, *pWhh4;
    cudaGetSymbolAddress((void**)&pX,  g_X);
    cudaGetSymbolAddress((void**)&pNA, g_NA);
    cudaGetSymbolAddress((void**)&pO,  g_O);
    cudaGetSymbolAddress((void**)&pH,  g_H);
    cudaGetSymbolAddress((void**)&ph,  g_h);
    cudaGetSymbolAddress((void**)&pWih4, g_Wih4);
    cudaGetSymbolAddress((void**)&pWhh4, g_Whh4);

    // 0) pack interleaved reduced gate weights
    pack_w<<<G4, 256>>>(w_ih, w_hh, b_ih, b_hh);

    // 1) neighbor encoder sims/topk/means -> NA [8212, 256] (interleaved)
    ne_sims<<<NUNIT, 256>>>(query, support, q_l_conn, q_r_conn, s_l_conn, s_r_conn,
                            knn, emb, pNA);
    // 2) fused GCN GEMM + tanh + gate + combine -> X [2053, 256]
    gemm_gcn<<<(2*NUNIT + 63)/64, 256>>>(pNA, gcn_w, gcn_wb, gcn_b,
                                         gate_w, gate_b, pX);

    // 3) support encoder
    gemm_nt<<<dim3(HIDv/128, (NROWS + 63)/64), 256>>>(pX, DMv, p1_w, DMv, pH, HIDv,
                                                      NROWS, HIDv, DMv, p1_b, 1);
    gemm_nt<<<dim3(DMv/128, (NROWS + 63)/64), 256>>>(pH, HIDv, p2_w, HIDv, pO, DMv,
                                                     NROWS, DMv, HIDv, p2_b, 0);
    posln_kernel<<<NROWS, 256>>>(pO, pX, ln_g, ln_b);

    // 4) support_g, normalization, reduced interleaved r-term
    sg_kernel<<<1, 256>>>(pX);
    rterm_kernel<<<G4/8, 256>>>(w_hh);

    // 5) LSTM steps with fused cell (step 1 computes+stores G0, h_r = 0)
    gemm_gates<<<dim3(G4/128, Bv/64), 256>>>(pX, pWih4, 1);
    for (int s = 0; s < 3; ++s)
        gemm_gates<<<dim3(G4/128, Bv/64), 256>>>(ph, pWhh4, 0);

    // 6) out[b] = l2n(h[b]) . l2n(support_g)
    final_kernel<<<Bv, 256>>>((float*)d_out);

    (void)in_sizes; (void)n_in; (void)out_size;
}

// round 7
// speedup vs baseline: 3.8694x; 1.0963x over previous
#include <cuda_runtime.h>
#include <cuda_bf16.h>
#include <math.h>
#include <stdint.h>

#define Dv    128
#define Mv    128
#define KTABv 64
#define Kv    32
#define Bv    2048
#define FEWv  5
#define DMv   256
#define HIDv  512
#define NSYMv 100000
#define NROWS (Bv + FEWv)     /* 2053 */
#define NUNIT (2*Bv + 2*FEWv) /* 4106 */
#define G4    1024            /* packed gate width: 4 gates x 256, interleaved 4j+g */

// ---------------- scratch (device globals) ----------------------------------
__device__ float g_X [NROWS * DMv];
__device__ float g_NA[(size_t)2 * NUNIT * DMv];
__device__ float g_O [NROWS * DMv];
__device__ float g_H [NROWS * HIDv];
__device__ float g_G0[(size_t)Bv * G4];
__device__ float g_C [Bv * DMv];
__device__ float g_h [Bv * DMv];
__device__ float g_sg [DMv];
__device__ float g_sgn[DMv];
__device__ float g_rt4[G4];
__device__ float g_b4[G4];
__device__ __nv_bfloat16 g_Xhi[Bv * DMv], g_Xlo[Bv * DMv];
__device__ __nv_bfloat16 g_hhi[Bv * DMv], g_hlo[Bv * DMv];
__device__ __nv_bfloat16 g_WihHi[G4 * DMv], g_WihLo[G4 * DMv];
__device__ __nv_bfloat16 g_WhhHi[G4 * DMv], g_WhhLo[G4 * DMv];

__device__ __forceinline__ float sigm(float x) { return 1.f / (1.f + expf(-x)); }

// ================= pack gate weights: bf16 hi/lo splits ======================
// packed row r = 4*j + gate  <-  original row m = gate*512 + j (reduced j<256)
__global__ void pack_w(const float* __restrict__ w_ih, const float* __restrict__ w_hh,
                       const float* __restrict__ b_ih, const float* __restrict__ b_hh)
{
    const int r = blockIdx.x, t = threadIdx.x;
    const int j = r >> 2, gate = r & 3;
    const int m = gate * 512 + j;
    float vih = w_ih[(size_t)m * DMv + t];
    __nv_bfloat16 h1 = __float2bfloat16(vih);
    g_WihHi[(size_t)r * DMv + t] = h1;
    g_WihLo[(size_t)r * DMv + t] = __float2bfloat16(vih - __bfloat162float(h1));
    float vhh = w_hh[(size_t)m * HIDv + t];
    __nv_bfloat16 h2 = __float2bfloat16(vhh);
    g_WhhHi[(size_t)r * DMv + t] = h2;
    g_WhhLo[(size_t)r * DMv + t] = __float2bfloat16(vhh - __bfloat162float(h2));
    if (t == 0) g_b4[r] = b_ih[m] + b_hh[m];
}

// ================= neighbor encoder: sims + topk + means (float4) ===========
__global__ __launch_bounds__(256) void ne_sims(
    const int* __restrict__ query, const int* __restrict__ support,
    const int* __restrict__ q_l_conn, const int* __restrict__ q_r_conn,
    const int* __restrict__ s_l_conn, const int* __restrict__ s_r_conn,
    const int* __restrict__ knn, const float* __restrict__ emb,
    float* __restrict__ NA)
{
    __shared__ float4 s_center4[32];
    __shared__ float4 s_pad4[32];
    __shared__ float  s_sims[Mv];
    __shared__ float  s_sims2[KTABv];
    __shared__ int    s_rel[Mv], s_ent[Mv], s_kid[KTABv];
    __shared__ int    s_lst1[Kv], s_lst2[Kv];
    __shared__ float4 s_par[12][32];
    __shared__ float  s_cn;

    const int u   = blockIdx.x;
    const int tid = threadIdx.x;
    const int lane = tid & 31, w = tid >> 5;

    const int* conn; int id;
    if (u < Bv)            { conn = q_l_conn + (size_t)u * (Mv*2);            id = query[u*2+0]; }
    else if (u < 2*Bv)     { int v = u - Bv;    conn = q_r_conn + (size_t)v*(Mv*2); id = query[v*2+1]; }
    else if (u < 2*Bv+FEWv){ int v = u - 2*Bv;  conn = s_l_conn + (size_t)v*(Mv*2); id = support[v*2+0]; }
    else                   { int v = u - (2*Bv+FEWv); conn = s_r_conn + (size_t)v*(Mv*2); id = support[v*2+1]; }

    if (tid < 32) {
        float4 cv = __ldg((const float4*)(emb + (size_t)id * Dv) + tid);
        s_center4[tid] = cv;
        float v = cv.x*cv.x + cv.y*cv.y + cv.z*cv.z + cv.w*cv.w;
        #pragma unroll
        for (int o = 16; o; o >>= 1) v += __shfl_xor_sync(0xffffffffu, v, o);
        if (tid == 0) s_cn = sqrtf(v);
    } else if (tid < 64) {
        s_pad4[tid - 32] = __ldg((const float4*)(emb + (size_t)NSYMv * Dv) + (tid - 32));
    } else if (tid < 192) {
        int m = tid - 64;
        int2 rc = ((const int2*)conn)[m];
        s_rel[m] = rc.x; s_ent[m] = rc.y;
    } else {
        int m = tid - 192;
        s_kid[m] = knn[(size_t)id * KTABv + m];
    }
    __syncthreads();
    const float  cn = s_cn;
    const float4 c4 = s_center4[lane];

    #pragma unroll
    for (int i = 0; i < 16; i += 4) {
        float dt[4], nr[4];
        #pragma unroll
        for (int r = 0; r < 4; ++r) {
            int m = w * 16 + i + r;
            float4 x = __ldg((const float4*)(emb + (size_t)s_ent[m] * Dv) + lane);
            dt[r] = c4.x*x.x + c4.y*x.y + c4.z*x.z + c4.w*x.w;
            nr[r] = x.x*x.x + x.y*x.y + x.z*x.z + x.w*x.w;
        }
        #pragma unroll
        for (int o = 16; o; o >>= 1) {
            #pragma unroll
            for (int r = 0; r < 4; ++r) {
                dt[r] += __shfl_xor_sync(0xffffffffu, dt[r], o);
                nr[r] += __shfl_xor_sync(0xffffffffu, nr[r], o);
            }
        }
        if (lane == 0) {
            #pragma unroll
            for (int r = 0; r < 4; ++r)
                s_sims[w*16 + i + r] = dt[r] / fmaxf(cn * sqrtf(nr[r]), 1e-8f);
        }
    }
    #pragma unroll
    for (int i = 0; i < 8; i += 4) {
        float dt[4], nr[4];
        #pragma unroll
        for (int r = 0; r < 4; ++r) {
            int m = w * 8 + i + r;
            float4 x = __ldg((const float4*)(emb + (size_t)s_kid[m] * Dv) + lane);
            dt[r] = c4.x*x.x + c4.y*x.y + c4.z*x.z + c4.w*x.w;
            nr[r] = x.x*x.x + x.y*x.y + x.z*x.z + x.w*x.w;
        }
        #pragma unroll
        for (int o = 16; o; o >>= 1) {
            #pragma unroll
            for (int r = 0; r < 4; ++r) {
                dt[r] += __shfl_xor_sync(0xffffffffu, dt[r], o);
                nr[r] += __shfl_xor_sync(0xffffffffu, nr[r], o);
            }
        }
        if (lane == 0) {
            #pragma unroll
            for (int r = 0; r < 4; ++r)
                s_sims2[w*8 + i + r] = dt[r] / fmaxf(cn * sqrtf(nr[r]), 1e-8f);
        }
    }
    __syncthreads();

    if (tid < Mv) {
        float my = s_sims[tid];
        int cnt = 0;
        #pragma unroll 8
        for (int j = 0; j < Mv; ++j) {
            float o = s_sims[j];
            cnt += (o > my) || (o == my && j < tid);
        }
        if (cnt < Kv) s_lst1[cnt] = tid;
    } else if (tid < Mv + KTABv) {
        int m = tid - Mv;
        float my = s_sims2[m];
        int cnt = 0;
        #pragma unroll 8
        for (int j = 0; j < KTABv; ++j) {
            float o = s_sims2[j];
            cnt += (o > my) || (o == my && j < m);
        }
        if (cnt < Kv) s_lst2[cnt] = m;
    }
    __syncthreads();

    float4 a1 = make_float4(0.f,0.f,0.f,0.f), a2 = make_float4(0.f,0.f,0.f,0.f);
    if (w < 4) {
        #pragma unroll
        for (int e = 0; e < 8; ++e) {
            int m = s_lst1[w*8 + e];
            float4 xr = __ldg((const float4*)(emb + (size_t)s_rel[m] * Dv) + lane);
            float4 xe = __ldg((const float4*)(emb + (size_t)s_ent[m] * Dv) + lane);
            a1.x += xr.x; a1.y += xr.y; a1.z += xr.z; a1.w += xr.w;
            a2.x += xe.x; a2.y += xe.y; a2.z += xe.z; a2.w += xe.w;
        }
        s_par[w][lane] = a1;
        s_par[4 + w][lane] = a2;
    } else {
        #pragma unroll
        for (int e = 0; e < 8; ++e) {
            int m = s_lst2[(w-4)*8 + e];
            float4 xk = __ldg((const float4*)(emb + (size_t)s_kid[m] * Dv) + lane);
            a1.x += xk.x; a1.y += xk.y; a1.z += xk.z; a1.w += xk.w;
        }
        s_par[4 + w][lane] = a1;
    }
    __syncthreads();

    const float inv = 1.f / (float)Kv;
    if (w < 3) {
        int base = w * 4;
        float4 p0 = s_par[base+0][lane], p1 = s_par[base+1][lane];
        float4 p2 = s_par[base+2][lane], p3 = s_par[base+3][lane];
        float4 s;
        s.x = (p0.x + p1.x + p2.x + p3.x) * inv;
        s.y = (p0.y + p1.y + p2.y + p3.y) * inv;
        s.z = (p0.z + p1.z + p2.z + p3.z) * inv;
        s.w = (p0.w + p1.w + p2.w + p3.w) * inv;
        size_t off;
        if (w == 0)      off = (size_t)(2*u) * DMv;
        else if (w == 1) off = (size_t)(2*u) * DMv + Dv;
        else             off = (size_t)(2*u + 1) * DMv + Dv;
        ((float4*)(NA + off))[lane] = s;
    } else if (w == 3) {
        ((float4*)(NA + (size_t)(2*u + 1) * DMv))[lane] = s_pad4[lane];
    }
}

// ================= fused GCN GEMM + tanh + gate + combine ====================
#define AS(b,k,x) s_all[(b)*1088 + (k)*68 + (x)]
#define BS(b,k,x) s_all[2176 + (b)*2112 + (k)*132 + (x)]
#define SG(r,c)   s_all[(r)*132 + (c)]

__global__ __launch_bounds__(256) void gemm_gcn(
    const float* __restrict__ A, const float* __restrict__ Bw,
    const float* __restrict__ wb, const float* __restrict__ gb,
    const float* __restrict__ gate_w, const float* __restrict__ gate_b,
    float* __restrict__ X)
{
    __shared__ float s_all[8448];
    const int tid = threadIdx.x;
    const int tx = tid & 15, ty = tid >> 4;
    const int rowBase = blockIdx.x * 64;
    const int Nr = 2 * NUNIT;

    unsigned long long acc[4][4];
    #pragma unroll
    for (int i = 0; i < 4; ++i)
        #pragma unroll
        for (int j = 0; j < 4; ++j) acc[i][j] = 0ull;

    const int arow = tid >> 2, akoff = (tid & 3) * 4;
    const int brow = tid >> 1, bkoff = (tid & 1) * 8;

    float4 pa, pb0, pb1;
    {
        int r = rowBase + arow;
        float4 v = make_float4(0.f,0.f,0.f,0.f);
        if (r < Nr) v = *(const float4*)(A + (size_t)r * DMv + akoff);
        AS(0,akoff+0,arow)=v.x; AS(0,akoff+1,arow)=v.y;
        AS(0,akoff+2,arow)=v.z; AS(0,akoff+3,arow)=v.w;
        const float* p = Bw + (size_t)brow * DMv + bkoff;
        float4 v0 = *(const float4*)p;
        float4 v1 = *(const float4*)(p + 4);
        BS(0,bkoff+0,brow)=v0.x; BS(0,bkoff+1,brow)=v0.y;
        BS(0,bkoff+2,brow)=v0.z; BS(0,bkoff+3,brow)=v0.w;
        BS(0,bkoff+4,brow)=v1.x; BS(0,bkoff+5,brow)=v1.y;
        BS(0,bkoff+6,brow)=v1.z; BS(0,bkoff+7,brow)=v1.w;
    }
    __syncthreads();

    int buf = 0;
    const int nk = DMv >> 4;
    for (int it = 0; it < nk; ++it) {
        if (it + 1 < nk) {
            int k0 = (it + 1) << 4;
            int r = rowBase + arow;
            pa = make_float4(0.f,0.f,0.f,0.f);
            if (r < Nr) pa = *(const float4*)(A + (size_t)r * DMv + k0 + akoff);
            const float* p = Bw + (size_t)brow * DMv + k0 + bkoff;
            pb0 = *(const float4*)p;
            pb1 = *(const float4*)(p + 4);
        }
        #pragma unroll
        for (int k = 0; k < 16; ++k) {
            float4 a = *(const float4*)&AS(buf,k,ty*4);
            unsigned long long av[4];
            {
                unsigned u0 = __float_as_uint(a.x), u1 = __float_as_uint(a.y);
                unsigned u2 = __float_as_uint(a.z), u3 = __float_as_uint(a.w);
                asm("mov.b64 %0, {%1, %1};" : "=l"(av[0]) : "r"(u0));
                asm("mov.b64 %0, {%1, %1};" : "=l"(av[1]) : "r"(u1));
                asm("mov.b64 %0, {%1, %1};" : "=l"(av[2]) : "r"(u2));
                asm("mov.b64 %0, {%1, %1};" : "=l"(av[3]) : "r"(u3));
            }
            unsigned long long bv[4];
            #pragma unroll
            for (int j2 = 0; j2 < 4; ++j2)
                bv[j2] = *(const unsigned long long*)&BS(buf,k,tx*2+32*j2);
            #pragma unroll
            for (int i = 0; i < 4; ++i)
                #pragma unroll
                for (int j2 = 0; j2 < 4; ++j2)
                    asm("fma.rn.f32x2 %0, %1, %2, %0;" : "+l"(acc[i][j2]) : "l"(av[i]), "l"(bv[j2]));
        }
        if (it + 1 < nk) {
            int nb = buf ^ 1;
            AS(nb,akoff+0,arow)=pa.x; AS(nb,akoff+1,arow)=pa.y;
            AS(nb,akoff+2,arow)=pa.z; AS(nb,akoff+3,arow)=pa.w;
            BS(nb,bkoff+0,brow)=pb0.x; BS(nb,bkoff+1,brow)=pb0.y;
            BS(nb,bkoff+2,brow)=pb0.z; BS(nb,bkoff+3,brow)=pb0.w;
            BS(nb,bkoff+4,brow)=pb1.x; BS(nb,bkoff+5,brow)=pb1.y;
            BS(nb,bkoff+6,brow)=pb1.z; BS(nb,bkoff+7,brow)=pb1.w;
            __syncthreads();
            buf = nb;
        }
    }
    __syncthreads();

    #pragma unroll
    for (int i = 0; i < 4; ++i) {
        #pragma unroll
        for (int j2 = 0; j2 < 4; ++j2) {
            unsigned ulo, uhi;
            asm("mov.b64 {%0, %1}, %2;" : "=r"(ulo), "=r"(uhi) : "l"(acc[i][j2]));
            int c0 = tx*2 + 32*j2;
            float lo = tanhf(__uint_as_float(ulo) + wb[c0]   + gb[c0]);
            float hi = tanhf(__uint_as_float(uhi) + wb[c0+1] + gb[c0+1]);
            SG(ty*4+i, c0)   = lo;
            SG(ty*4+i, c0+1) = hi;
        }
    }
    __syncthreads();

    const int t = tid >> 3, sub = tid & 7;
    const int u = (rowBase >> 1) + t;
    if (u < NUNIT) {
        float gv = 0.f;
        #pragma unroll
        for (int k = 0; k < 16; ++k) {
            int c = sub*16 + k;
            gv += SG(2*t, c) * gate_w[c] + SG(2*t+1, c) * gate_w[128 + c];
        }
        gv += __shfl_xor_sync(0xffffffffu, gv, 1);
        gv += __shfl_xor_sync(0xffffffffu, gv, 2);
        gv += __shfl_xor_sync(0xffffffffu, gv, 4);
        float a = sigm(gv + gate_b[0]);
        int row, col;
        if (u < Bv)             { row = u;                      col = 0; }
        else if (u < 2*Bv)      { row = u - Bv;                 col = Dv; }
        else if (u < 2*Bv+FEWv) { row = Bv + (u - 2*Bv);        col = 0; }
        else                    { row = Bv + (u - 2*Bv - FEWv); col = Dv; }
        float* xp = X + (size_t)row * DMv + col;
        #pragma unroll
        for (int k4 = 0; k4 < 4; ++k4) {
            int c = sub*16 + k4*4;
            float4 st = *(const float4*)&SG(2*t, c);
            float4 kn = *(const float4*)&SG(2*t+1, c);
            float4 o;
            o.x = (1.f - a)*st.x + a*kn.x;
            o.y = (1.f - a)*st.y + a*kn.y;
            o.z = (1.f - a)*st.z + a*kn.z;
            o.w = (1.f - a)*st.w + a*kn.w;
            *(float4*)(xp + c) = o;
        }
    }
}

// ================= mma.sync bf16 gate GEMM + fused LSTM cell =================
// 64x128 block tile, 8 warps (2x4), warptile 32x32, K steps of 16, 3x split
#define GATES_SMEM 33792
#define MMA16816(c, a, b) \
    asm volatile("mma.sync.aligned.m16n8k16.row.col.f32.bf16.bf16.f32 " \
        "{%0,%1,%2,%3}, {%4,%5,%6,%7}, {%8,%9}, {%0,%1,%2,%3};" \
        : "+f"((c)[0]), "+f"((c)[1]), "+f"((c)[2]), "+f"((c)[3]) \
        : "r"((a)[0]), "r"((a)[1]), "r"((a)[2]), "r"((a)[3]), "r"((b)[0]), "r"((b)[1]))

__global__ __launch_bounds__(256) void gates_mma(
    const __nv_bfloat16* __restrict__ Ahi, const __nv_bfloat16* __restrict__ Alo,
    const __nv_bfloat16* __restrict__ Whi, const __nv_bfloat16* __restrict__ Wlo,
    int first)
{
    extern __shared__ char sm[];
    // mainloop byte offsets (bf16, padded row stride 20 elems):
    //  Ah: buf*2560, Al: 5120+buf*2560, Bh: 10240+buf*5120, Bl: 20480+buf*5120
    const int tid = threadIdx.x;
    const int lane = tid & 31, wid = tid >> 5;
    const int wr = wid >> 2, wc = wid & 3;
    const int rowBase = blockIdx.y * 64;
    const int colBase = blockIdx.x * 128;
    const int jbase = colBase >> 2;
    const int gr = lane >> 2, gk = (lane & 3) * 2;

    float acc[2][4][4];
    #pragma unroll
    for (int mi = 0; mi < 2; ++mi)
        #pragma unroll
        for (int ni = 0; ni < 4; ++ni)
            #pragma unroll
            for (int q = 0; q < 4; ++q) acc[mi][ni][q] = 0.f;

    const int la_row = tid >> 2, la_k = (tid & 3) * 4;

    // prologue: k0 = 0 -> buffer 0
    {
        uint2 vAh = *(const uint2*)(Ahi + (size_t)(rowBase + la_row) * DMv + la_k);
        uint2 vAl = *(const uint2*)(Alo + (size_t)(rowBase + la_row) * DMv + la_k);
        uint2 vBh0 = *(const uint2*)(Whi + (size_t)(colBase + la_row) * DMv + la_k);
        uint2 vBh1 = *(const uint2*)(Whi + (size_t)(colBase + 64 + la_row) * DMv + la_k);
        uint2 vBl0 = *(const uint2*)(Wlo + (size_t)(colBase + la_row) * DMv + la_k);
        uint2 vBl1 = *(const uint2*)(Wlo + (size_t)(colBase + 64 + la_row) * DMv + la_k);
        *(uint2*)(sm + 0     + (la_row*20 + la_k)*2) = vAh;
        *(uint2*)(sm + 5120  + (la_row*20 + la_k)*2) = vAl;
        *(uint2*)(sm + 10240 + (la_row*20 + la_k)*2) = vBh0;
        *(uint2*)(sm + 10240 + ((64+la_row)*20 + la_k)*2) = vBh1;
        *(uint2*)(sm + 20480 + (la_row*20 + la_k)*2) = vBl0;
        *(uint2*)(sm + 20480 + ((64+la_row)*20 + la_k)*2) = vBl1;
    }
    __syncthreads();

    int buf = 0;
    uint2 vAh, vAl, vBh0, vBh1, vBl0, vBl1;
    for (int it = 0; it < 16; ++it) {
        if (it < 15) {
            int k0 = (it + 1) * 16;
            vAh = *(const uint2*)(Ahi + (size_t)(rowBase + la_row) * DMv + k0 + la_k);
            vAl = *(const uint2*)(Alo + (size_t)(rowBase + la_row) * DMv + k0 + la_k);
            vBh0 = *(const uint2*)(Whi + (size_t)(colBase + la_row) * DMv + k0 + la_k);
            vBh1 = *(const uint2*)(Whi + (size_t)(colBase + 64 + la_row) * DMv + k0 + la_k);
            vBl0 = *(const uint2*)(Wlo + (size_t)(colBase + la_row) * DMv + k0 + la_k);
            vBl1 = *(const uint2*)(Wlo + (size_t)(colBase + 64 + la_row) * DMv + k0 + la_k);
        }
        {
            const __nv_bfloat16* A_h = (const __nv_bfloat16*)(sm + buf * 2560);
            const __nv_bfloat16* A_l = (const __nv_bfloat16*)(sm + 5120 + buf * 2560);
            const __nv_bfloat16* B_h = (const __nv_bfloat16*)(sm + 10240 + buf * 5120);
            const __nv_bfloat16* B_l = (const __nv_bfloat16*)(sm + 20480 + buf * 5120);
            uint32_t ah[2][4], al[2][4], bh[4][2], bl[4][2];
            #pragma unroll
            for (int mi = 0; mi < 2; ++mi) {
                int r = wr * 32 + mi * 16 + gr;
                ah[mi][0] = *(const uint32_t*)(A_h + r * 20 + gk);
                ah[mi][1] = *(const uint32_t*)(A_h + (r + 8) * 20 + gk);
                ah[mi][2] = *(const uint32_t*)(A_h + r * 20 + gk + 8);
                ah[mi][3] = *(const uint32_t*)(A_h + (r + 8) * 20 + gk + 8);
                al[mi][0] = *(const uint32_t*)(A_l + r * 20 + gk);
                al[mi][1] = *(const uint32_t*)(A_l + (r + 8) * 20 + gk);
                al[mi][2] = *(const uint32_t*)(A_l + r * 20 + gk + 8);
                al[mi][3] = *(const uint32_t*)(A_l + (r + 8) * 20 + gk + 8);
            }
            #pragma unroll
            for (int ni = 0; ni < 4; ++ni) {
                int n = wc * 32 + ni * 8 + gr;
                bh[ni][0] = *(const uint32_t*)(B_h + n * 20 + gk);
                bh[ni][1] = *(const uint32_t*)(B_h + n * 20 + gk + 8);
                bl[ni][0] = *(const uint32_t*)(B_l + n * 20 + gk);
                bl[ni][1] = *(const uint32_t*)(B_l + n * 20 + gk + 8);
            }
            #pragma unroll
            for (int mi = 0; mi < 2; ++mi)
                #pragma unroll
                for (int ni = 0; ni < 4; ++ni) {
                    MMA16816(acc[mi][ni], ah[mi], bh[ni]);
                    MMA16816(acc[mi][ni], ah[mi], bl[ni]);
                    MMA16816(acc[mi][ni], al[mi], bh[ni]);
                }
        }
        if (it < 15) {
            int nb = buf ^ 1;
            __syncthreads();   // everyone done reading nb from 2 iters ago
            *(uint2*)(sm + 0     + nb * 2560 + (la_row*20 + la_k)*2) = vAh;
            *(uint2*)(sm + 5120  + nb * 2560 + (la_row*20 + la_k)*2) = vAl;
            *(uint2*)(sm + 10240 + nb * 5120 + (la_row*20 + la_k)*2) = vBh0;
            *(uint2*)(sm + 10240 + nb * 5120 + ((64+la_row)*20 + la_k)*2) = vBh1;
            *(uint2*)(sm + 20480 + nb * 5120 + (la_row*20 + la_k)*2) = vBl0;
            *(uint2*)(sm + 20480 + nb * 5120 + ((64+la_row)*20 + la_k)*2) = vBl1;
            __syncthreads();
            buf = nb;
        }
    }
    __syncthreads();   // before overlaying sAcc

    float* sAcc = (float*)sm;   // [64][132]
    #pragma unroll
    for (int mi = 0; mi < 2; ++mi) {
        #pragma unroll
        for (int ni = 0; ni < 4; ++ni) {
            int r0 = wr * 32 + mi * 16 + gr;
            int c0 = wc * 32 + ni * 8 + gk;
            *(float2*)&sAcc[r0 * 132 + c0]       = make_float2(acc[mi][ni][0], acc[mi][ni][1]);
            *(float2*)&sAcc[(r0 + 8) * 132 + c0] = make_float2(acc[mi][ni][2], acc[mi][ni][3]);
        }
    }
    __syncthreads();

    // fused LSTM cell: 64 rows x 32 units
    #pragma unroll
    for (int i = 0; i < 8; ++i) {
        int lin = tid + i * 256;
        int r = lin >> 5, jl = lin & 31;
        float4 gv = *(const float4*)&sAcc[r * 132 + jl * 4];
        int row = rowBase + r;
        int colp = colBase + jl * 4;
        float gi = gv.x, gf = gv.y, gg = gv.z, go = gv.w;
        size_t g0i = (size_t)row * G4 + colp;
        if (first) {
            gi += g_b4[colp]; gf += g_b4[colp+1]; gg += g_b4[colp+2]; go += g_b4[colp+3];
            *(float4*)&g_G0[g0i] = make_float4(gi, gf, gg, go);
        } else {
            float4 g0 = *(const float4*)&g_G0[g0i];
            gi += g0.x + g_rt4[colp];   gf += g0.y + g_rt4[colp+1];
            gg += g0.z + g_rt4[colp+2]; go += g0.w + g_rt4[colp+3];
        }
        size_t ci = (size_t)row * DMv + jbase + jl;
        float cold = first ? 0.f : g_C[ci];
        float cv = sigm(gf) * cold + sigm(gi) * tanhf(gg);
        g_C[ci] = cv;
        float h = g_X[ci] + sigm(go) * tanhf(cv);
        g_h[ci] = h;
        __nv_bfloat16 hb = __float2bfloat16(h);
        g_hhi[ci] = hb;
        g_hlo[ci] = __float2bfloat16(h - __bfloat162float(hb));
    }
}

// ================= generic fp32x2 GEMM (support encoder) ====================
__global__ __launch_bounds__(256) void gemm_nt(
    const float* __restrict__ A, int lda,
    const float* __restrict__ Bw, int ldb,
    float* __restrict__ C, int ldc,
    int Nr, int Nc, int Kd,
    const float* __restrict__ bias1,
    int act)
{
    __shared__ float As[2][16][68];
    __shared__ float Bs[2][16][132];
    const int tid = threadIdx.x;
    const int tx = tid & 15, ty = tid >> 4;
    const int rowBase = blockIdx.y * 64;
    const int colBase = blockIdx.x * 128;

    unsigned long long acc[4][4];
    #pragma unroll
    for (int i = 0; i < 4; ++i)
        #pragma unroll
        for (int j = 0; j < 4; ++j) acc[i][j] = 0ull;

    const int arow = tid >> 2, akoff = (tid & 3) * 4;
    const int brow = tid >> 1, bkoff = (tid & 1) * 8;
    const int nk = Kd >> 4;

    float4 pa, pb0, pb1;
    {
        int r = rowBase + arow;
        float4 v = make_float4(0.f,0.f,0.f,0.f);
        if (r < Nr) v = *(const float4*)(A + (size_t)r * lda + akoff);
        As[0][akoff+0][arow]=v.x; As[0][akoff+1][arow]=v.y;
        As[0][akoff+2][arow]=v.z; As[0][akoff+3][arow]=v.w;
        const float* p = Bw + (size_t)(colBase + brow) * ldb + bkoff;
        float4 v0 = *(const float4*)p;
        float4 v1 = *(const float4*)(p + 4);
        Bs[0][bkoff+0][brow]=v0.x; Bs[0][bkoff+1][brow]=v0.y;
        Bs[0][bkoff+2][brow]=v0.z; Bs[0][bkoff+3][brow]=v0.w;
        Bs[0][bkoff+4][brow]=v1.x; Bs[0][bkoff+5][brow]=v1.y;
        Bs[0][bkoff+6][brow]=v1.z; Bs[0][bkoff+7][brow]=v1.w;
    }
    __syncthreads();

    int buf = 0;
    for (int it = 0; it < nk; ++it) {
        if (it + 1 < nk) {
            int k0 = (it + 1) << 4;
            int r = rowBase + arow;
            pa = make_float4(0.f,0.f,0.f,0.f);
            if (r < Nr) pa = *(const float4*)(A + (size_t)r * lda + k0 + akoff);
            const float* p = Bw + (size_t)(colBase + brow) * ldb + k0 + bkoff;
            pb0 = *(const float4*)p;
            pb1 = *(const float4*)(p + 4);
        }
        #pragma unroll
        for (int k = 0; k < 16; ++k) {
            float4 a = *(const float4*)&As[buf][k][ty*4];
            unsigned long long av[4];
            {
                unsigned u0 = __float_as_uint(a.x), u1 = __float_as_uint(a.y);
                unsigned u2 = __float_as_uint(a.z), u3 = __float_as_uint(a.w);
                asm("mov.b64 %0, {%1, %1};" : "=l"(av[0]) : "r"(u0));
                asm("mov.b64 %0, {%1, %1};" : "=l"(av[1]) : "r"(u1));
                asm("mov.b64 %0, {%1, %1};" : "=l"(av[2]) : "r"(u2));
                asm("mov.b64 %0, {%1, %1};" : "=l"(av[3]) : "r"(u3));
            }
            unsigned long long bv[4];
            #pragma unroll
            for (int j2 = 0; j2 < 4; ++j2)
                bv[j2] = *(const unsigned long long*)&Bs[buf][k][tx*2+32*j2];
            #pragma unroll
            for (int i = 0; i < 4; ++i)
                #pragma unroll
                for (int j2 = 0; j2 < 4; ++j2)
                    asm("fma.rn.f32x2 %0, %1, %2, %0;" : "+l"(acc[i][j2]) : "l"(av[i]), "l"(bv[j2]));
        }
        if (it + 1 < nk) {
            int nb = buf ^ 1;
            As[nb][akoff+0][arow]=pa.x; As[nb][akoff+1][arow]=pa.y;
            As[nb][akoff+2][arow]=pa.z; As[nb][akoff+3][arow]=pa.w;
            Bs[nb][bkoff+0][brow]=pb0.x; Bs[nb][bkoff+1][brow]=pb0.y;
            Bs[nb][bkoff+2][brow]=pb0.z; Bs[nb][bkoff+3][brow]=pb0.w;
            Bs[nb][bkoff+4][brow]=pb1.x; Bs[nb][bkoff+5][brow]=pb1.y;
            Bs[nb][bkoff+6][brow]=pb1.z; Bs[nb][bkoff+7][brow]=pb1.w;
            __syncthreads();
            buf = nb;
        }
    }

    #pragma unroll
    for (int i = 0; i < 4; ++i) {
        int r = rowBase + ty*4 + i;
        if (r >= Nr) continue;
        #pragma unroll
        for (int j2 = 0; j2 < 4; ++j2) {
            unsigned ulo, uhi;
            asm("mov.b64 {%0, %1}, %2;" : "=r"(ulo), "=r"(uhi) : "l"(acc[i][j2]));
            float lo = __uint_as_float(ulo), hi = __uint_as_float(uhi);
            int c0 = colBase + tx*2 + 32*j2;
            if (bias1) { lo += bias1[c0]; hi += bias1[c0+1]; }
            if (act == 1) { lo = fmaxf(lo, 0.f); hi = fmaxf(hi, 0.f); }
            *(float2*)(C + (size_t)r * ldc + c0) = make_float2(lo, hi);
        }
    }
}

// ---------------- residual + layernorm (+ bf16 split emit for query rows) ---
__global__ void posln_kernel(const float* __restrict__ O, float* __restrict__ X,
                             const float* __restrict__ g, const float* __restrict__ b)
{
    __shared__ float s_red[8];
    const int r = blockIdx.x, t = threadIdx.x;
    const int lane = t & 31, w = t >> 5;
    float z = O[(size_t)r * DMv + t] + X[(size_t)r * DMv + t];
    float v = z;
    #pragma unroll
    for (int o = 16; o; o >>= 1) v += __shfl_xor_sync(0xffffffffu, v, o);
    if (lane == 0) s_red[w] = v;
    __syncthreads();
    float mu = 0.f;
    #pragma unroll
    for (int i = 0; i < 8; ++i) mu += s_red[i];
    mu *= (1.f / 256.f);
    __syncthreads();
    float d = z - mu;
    v = d * d;
    #pragma unroll
    for (int o = 16; o; o >>= 1) v += __shfl_xor_sync(0xffffffffu, v, o);
    if (lane == 0) s_red[w] = v;
    __syncthreads();
    float var = 0.f;
    #pragma unroll
    for (int i = 0; i < 8; ++i) var += s_red[i];
    var *= (1.f / 255.f);
    float y = d / (sqrtf(var) + 1e-3f) * g[t] + b[t];
    X[(size_t)r * DMv + t] = y;
    if (r < Bv) {
        __nv_bfloat16 hi = __float2bfloat16(y);
        g_Xhi[(size_t)r * DMv + t] = hi;
        g_Xlo[(size_t)r * DMv + t] = __float2bfloat16(y - __bfloat162float(hi));
    }
}

// ---------------- support_g + l2 normalization ------------------------------
__global__ void sg_kernel(const float* __restrict__ X)
{
    __shared__ float s_red[8];
    const int t = threadIdx.x, lane = t & 31, w = t >> 5;
    float s = 0.f;
    #pragma unroll
    for (int i = 0; i < FEWv; ++i) s += X[(size_t)(Bv + i) * DMv + t];
    s *= (1.f / (float)FEWv);
    g_sg[t] = s;
    float v = s * s;
    #pragma unroll
    for (int o = 16; o; o >>= 1) v += __shfl_xor_sync(0xffffffffu, v, o);
    if (lane == 0) s_red[w] = v;
    __syncthreads();
    float nn = 0.f;
    #pragma unroll
    for (int i = 0; i < 8; ++i) nn += s_red[i];
    g_sgn[t] = s / fmaxf(sqrtf(nn), 1e-12f);
}

// ---------------- rt4[4j+g] = w_hh[g*512+j, 256:512] @ support_g ------------
__global__ void rterm_kernel(const float* __restrict__ w_hh)
{
    const int t = threadIdx.x, lane = t & 31, w = t >> 5;
    const int o = blockIdx.x * 8 + w;
    const int j = o >> 2, gate = o & 3;
    const float* wr = w_hh + (size_t)(gate * 512 + j) * HIDv + DMv;
    float s = 0.f;
    #pragma unroll
    for (int q = 0; q < 8; ++q) s += g_sg[lane + q * 32] * wr[lane + q * 32];
    #pragma unroll
    for (int off = 16; off; off >>= 1) s += __shfl_xor_sync(0xffffffffu, s, off);
    if (lane == 0) g_rt4[o] = s;
}

// ---------------- final cosine against normalized support_g ----------------
__global__ void final_kernel(float* __restrict__ out)
{
    __shared__ float s_red[16];
    const int b = blockIdx.x, t = threadIdx.x, lane = t & 31, w = t >> 5;
    float hv = g_h[(size_t)b * DMv + t];
    float d = hv * g_sgn[t];
    float ss = hv * hv;
    #pragma unroll
    for (int o = 16; o; o >>= 1) {
        d  += __shfl_xor_sync(0xffffffffu, d,  o);
        ss += __shfl_xor_sync(0xffffffffu, ss, o);
    }
    if (lane == 0) { s_red[w] = d; s_red[8 + w] = ss; }
    __syncthreads();
    if (t == 0) {
        float Dd = 0.f, S = 0.f;
        #pragma unroll
        for (int i = 0; i < 8; ++i) { Dd += s_red[i]; S += s_red[8 + i]; }
        out[b] = Dd / fmaxf(sqrtf(S), 1e-12f);
    }
}

// ---------------- launcher ---------------------------------------------------
extern "C" void kernel_launch(void* const* d_in, const int* in_sizes, int n_in,
                              void* d_out, int out_size)
{
    const int*   query    = (const int*)  d_in[0];
    const int*   support  = (const int*)  d_in[1];
    const int*   q_l_conn = (const int*)  d_in[2];
    const int*   q_r_conn = (const int*)  d_in[4];
    const int*   s_l_conn = (const int*)  d_in[6];
    const int*   s_r_conn = (const int*)  d_in[8];
    const int*   knn      = (const int*)  d_in[10];
    const float* emb      = (const float*)d_in[11];
    const float* gcn_w    = (const float*)d_in[12];
    const float* gcn_wb   = (const float*)d_in[13];
    const float* gcn_b    = (const float*)d_in[14];
    const float* gate_w   = (const float*)d_in[15];
    const float* gate_b   = (const float*)d_in[16];
    const float* p1_w     = (const float*)d_in[17];
    const float* p1_b     = (const float*)d_in[18];
    const float* p2_w     = (const float*)d_in[19];
    const float* p2_b     = (const float*)d_in[20];
    const float* ln_g     = (const float*)d_in[21];
    const float* ln_b     = (const float*)d_in[22];
    const float* w_ih     = (const float*)d_in[23];
    const float* w_hh     = (const float*)d_in[24];
    const float* b_ih     = (const float*)d_in[25];
    const float* b_hh     = (const float*)d_in[26];

    float *pX, *pNA, *pO, *pH;
    __nv_bfloat16 *pXhi, *pXlo, *phhi, *phlo, *pWihHi, *pWihLo, *pWhhHi, *pWhhLo;
    cudaGetSymbolAddress((void**)&pX,  g_X);
    cudaGetSymbolAddress((void**)&pNA, g_NA);
    cudaGetSymbolAddress((void**)&pO,  g_O);
    cudaGetSymbolAddress((void**)&pH,  g_H);
    cudaGetSymbolAddress((void**)&pXhi, g_Xhi);
    cudaGetSymbolAddress((void**)&pXlo, g_Xlo);
    cudaGetSymbolAddress((void**)&phhi, g_hhi);
    cudaGetSymbolAddress((void**)&phlo, g_hlo);
    cudaGetSymbolAddress((void**)&pWihHi, g_WihHi);
    cudaGetSymbolAddress((void**)&pWihLo, g_WihLo);
    cudaGetSymbolAddress((void**)&pWhhHi, g_WhhHi);
    cudaGetSymbolAddress((void**)&pWhhLo, g_WhhLo);

    // 0) pack reduced gate weights (bf16 hi/lo splits, interleaved 4j+g)
    pack_w<<<G4, 256>>>(w_ih, w_hh, b_ih, b_hh);

    // 1) neighbor encoder sims/topk/means -> NA [8212, 256]
    ne_sims<<<NUNIT, 256>>>(query, support, q_l_conn, q_r_conn, s_l_conn, s_r_conn,
                            knn, emb, pNA);
    // 2) fused GCN GEMM + tanh + gate + combine -> X [2053, 256]
    gemm_gcn<<<(2*NUNIT + 63)/64, 256>>>(pNA, gcn_w, gcn_wb, gcn_b,
                                         gate_w, gate_b, pX);

    // 3) support encoder
    gemm_nt<<<dim3(HIDv/128, (NROWS + 63)/64), 256>>>(pX, DMv, p1_w, DMv, pH, HIDv,
                                                      NROWS, HIDv, DMv, p1_b, 1);
    gemm_nt<<<dim3(DMv/128, (NROWS + 63)/64), 256>>>(pH, HIDv, p2_w, HIDv, pO, DMv,
                                                     NROWS, DMv, HIDv, p2_b, 0);
    posln_kernel<<<NROWS, 256>>>(pO, pX, ln_g, ln_b);

    // 4) support_g, normalization, reduced interleaved r-term
    sg_kernel<<<1, 256>>>(pX);
    rterm_kernel<<<G4/8, 256>>>(w_hh);

    // 5) LSTM steps on mma.sync bf16 (3x split), fused cell epilogue
    gates_mma<<<dim3(G4/128, Bv/64), 256, GATES_SMEM>>>(pXhi, pXlo, pWihHi, pWihLo, 1);
    for (int s = 0; s < 3; ++s)
        gates_mma<<<dim3(G4/128, Bv/64), 256, GATES_SMEM>>>(phhi, phlo, pWhhHi, pWhhLo, 0);

    // 6) out[b] = l2n(h[b]) . l2n(support_g)
    final_kernel<<<Bv, 256>>>((float*)d_out);

    (void)in_sizes; (void)n_in; (void)out_size;
}

// round 8
// speedup vs baseline: 4.1216x; 1.0652x over previous
#include <cuda_runtime.h>
#include <cuda_bf16.h>
#include <math.h>
#include <stdint.h>

#define Dv    128
#define Mv    128
#define KTABv 64
#define Kv    32
#define Bv    2048
#define FEWv  5
#define DMv   256
#define HIDv  512
#define NSYMv 100000
#define NROWS (Bv + FEWv)     /* 2053 */
#define NUNIT (2*Bv + 2*FEWv) /* 4106 */
#define G4    1024            /* packed gate width: 4 gates x 256, interleaved 4j+g */
#define SMEM_MMA 33792        /* 64*132*4 accumulator staging dominates */

// ---------------- scratch (device globals) ----------------------------------
__device__ float g_X [NROWS * DMv];
__device__ float g_O [NROWS * DMv];
__device__ float g_G0[(size_t)Bv * G4];
__device__ float g_C [Bv * DMv];
__device__ float g_h [Bv * DMv];
__device__ float g_sg [DMv];
__device__ float g_sgn[DMv];
__device__ float g_rt4[G4];
__device__ float g_b4[G4];
__device__ __nv_bfloat16 g_NAhi[(size_t)2 * NUNIT * DMv], g_NAlo[(size_t)2 * NUNIT * DMv];
__device__ __nv_bfloat16 g_XAhi[NROWS * DMv], g_XAlo[NROWS * DMv];   // pre-LN X splits
__device__ __nv_bfloat16 g_Hshi[(size_t)NROWS * HIDv], g_Hslo[(size_t)NROWS * HIDv];
__device__ __nv_bfloat16 g_Xhi[Bv * DMv], g_Xlo[Bv * DMv];           // post-LN X splits
__device__ __nv_bfloat16 g_hhi[Bv * DMv], g_hlo[Bv * DMv];
__device__ __nv_bfloat16 g_WihHi[G4 * DMv], g_WihLo[G4 * DMv];
__device__ __nv_bfloat16 g_WhhHi[G4 * DMv], g_WhhLo[G4 * DMv];
__device__ __nv_bfloat16 g_WgcnHi[Dv * DMv], g_WgcnLo[Dv * DMv];
__device__ __nv_bfloat16 g_Wp1Hi[HIDv * DMv], g_Wp1Lo[HIDv * DMv];
__device__ __nv_bfloat16 g_Wp2Hi[DMv * HIDv], g_Wp2Lo[DMv * HIDv];

__device__ __forceinline__ float sigm(float x) { return 1.f / (1.f + expf(-x)); }

__device__ __forceinline__ void split_store4(float4 v, __nv_bfloat16* hi,
                                             __nv_bfloat16* lo, size_t idx)
{
    __nv_bfloat16 h0 = __float2bfloat16(v.x), h1 = __float2bfloat16(v.y);
    __nv_bfloat16 h2 = __float2bfloat16(v.z), h3 = __float2bfloat16(v.w);
    __nv_bfloat162 a, b, c, d;
    a.x = h0; a.y = h1; b.x = h2; b.y = h3;
    c.x = __float2bfloat16(v.x - __bfloat162float(h0));
    c.y = __float2bfloat16(v.y - __bfloat162float(h1));
    d.x = __float2bfloat16(v.z - __bfloat162float(h2));
    d.y = __float2bfloat16(v.w - __bfloat162float(h3));
    *(__nv_bfloat162*)&hi[idx]     = a;
    *(__nv_bfloat162*)&hi[idx + 2] = b;
    *(__nv_bfloat162*)&lo[idx]     = c;
    *(__nv_bfloat162*)&lo[idx + 2] = d;
}

// ================= pack gate weights (bf16 hi/lo, interleaved 4j+g) =========
__global__ void pack_w(const float* __restrict__ w_ih, const float* __restrict__ w_hh,
                       const float* __restrict__ b_ih, const float* __restrict__ b_hh)
{
    const int r = blockIdx.x, t = threadIdx.x;
    const int j = r >> 2, gate = r & 3;
    const int m = gate * 512 + j;
    float vih = w_ih[(size_t)m * DMv + t];
    __nv_bfloat16 h1 = __float2bfloat16(vih);
    g_WihHi[(size_t)r * DMv + t] = h1;
    g_WihLo[(size_t)r * DMv + t] = __float2bfloat16(vih - __bfloat162float(h1));
    float vhh = w_hh[(size_t)m * HIDv + t];
    __nv_bfloat16 h2 = __float2bfloat16(vhh);
    g_WhhHi[(size_t)r * DMv + t] = h2;
    g_WhhLo[(size_t)r * DMv + t] = __float2bfloat16(vhh - __bfloat162float(h2));
    if (t == 0) g_b4[r] = b_ih[m] + b_hh[m];
}

// ================= pack support-encoder + gcn weights ========================
__global__ void pack_se(const float* __restrict__ gcn_w, const float* __restrict__ p1_w,
                        const float* __restrict__ p2_w)
{
    const int r = blockIdx.x, t = threadIdx.x;
    if (r < Dv) {
        float v = gcn_w[(size_t)r * DMv + t];
        __nv_bfloat16 h = __float2bfloat16(v);
        g_WgcnHi[(size_t)r * DMv + t] = h;
        g_WgcnLo[(size_t)r * DMv + t] = __float2bfloat16(v - __bfloat162float(h));
    } else if (r < Dv + HIDv) {
        int q = r - Dv;
        float v = p1_w[(size_t)q * DMv + t];
        __nv_bfloat16 h = __float2bfloat16(v);
        g_Wp1Hi[(size_t)q * DMv + t] = h;
        g_Wp1Lo[(size_t)q * DMv + t] = __float2bfloat16(v - __bfloat162float(h));
    } else {
        int q = r - Dv - HIDv;
        #pragma unroll
        for (int s = 0; s < 2; ++s) {
            int c = t + s * 256;
            float v = p2_w[(size_t)q * HIDv + c];
            __nv_bfloat16 h = __float2bfloat16(v);
            g_Wp2Hi[(size_t)q * HIDv + c] = h;
            g_Wp2Lo[(size_t)q * HIDv + c] = __float2bfloat16(v - __bfloat162float(h));
        }
    }
}

// ================= neighbor encoder: sims + topk + means (float4) ===========
__global__ __launch_bounds__(256) void ne_sims(
    const int* __restrict__ query, const int* __restrict__ support,
    const int* __restrict__ q_l_conn, const int* __restrict__ q_r_conn,
    const int* __restrict__ s_l_conn, const int* __restrict__ s_r_conn,
    const int* __restrict__ knn, const float* __restrict__ emb)
{
    __shared__ float4 s_center4[32];
    __shared__ float4 s_pad4[32];
    __shared__ float  s_sims[Mv];
    __shared__ float  s_sims2[KTABv];
    __shared__ int    s_rel[Mv], s_ent[Mv], s_kid[KTABv];
    __shared__ int    s_lst1[Kv], s_lst2[Kv];
    __shared__ float4 s_par[12][32];
    __shared__ float  s_cn;

    const int u   = blockIdx.x;
    const int tid = threadIdx.x;
    const int lane = tid & 31, w = tid >> 5;

    const int* conn; int id;
    if (u < Bv)            { conn = q_l_conn + (size_t)u * (Mv*2);            id = query[u*2+0]; }
    else if (u < 2*Bv)     { int v = u - Bv;    conn = q_r_conn + (size_t)v*(Mv*2); id = query[v*2+1]; }
    else if (u < 2*Bv+FEWv){ int v = u - 2*Bv;  conn = s_l_conn + (size_t)v*(Mv*2); id = support[v*2+0]; }
    else                   { int v = u - (2*Bv+FEWv); conn = s_r_conn + (size_t)v*(Mv*2); id = support[v*2+1]; }

    if (tid < 32) {
        float4 cv = __ldg((const float4*)(emb + (size_t)id * Dv) + tid);
        s_center4[tid] = cv;
        float v = cv.x*cv.x + cv.y*cv.y + cv.z*cv.z + cv.w*cv.w;
        #pragma unroll
        for (int o = 16; o; o >>= 1) v += __shfl_xor_sync(0xffffffffu, v, o);
        if (tid == 0) s_cn = sqrtf(v);
    } else if (tid < 64) {
        s_pad4[tid - 32] = __ldg((const float4*)(emb + (size_t)NSYMv * Dv) + (tid - 32));
    } else if (tid < 192) {
        int m = tid - 64;
        int2 rc = ((const int2*)conn)[m];
        s_rel[m] = rc.x; s_ent[m] = rc.y;
    } else {
        int m = tid - 192;
        s_kid[m] = knn[(size_t)id * KTABv + m];
    }
    __syncthreads();
    const float  cn = s_cn;
    const float4 c4 = s_center4[lane];

    #pragma unroll
    for (int i = 0; i < 16; i += 4) {
        float dt[4], nr[4];
        #pragma unroll
        for (int r = 0; r < 4; ++r) {
            int m = w * 16 + i + r;
            float4 x = __ldg((const float4*)(emb + (size_t)s_ent[m] * Dv) + lane);
            dt[r] = c4.x*x.x + c4.y*x.y + c4.z*x.z + c4.w*x.w;
            nr[r] = x.x*x.x + x.y*x.y + x.z*x.z + x.w*x.w;
        }
        #pragma unroll
        for (int o = 16; o; o >>= 1) {
            #pragma unroll
            for (int r = 0; r < 4; ++r) {
                dt[r] += __shfl_xor_sync(0xffffffffu, dt[r], o);
                nr[r] += __shfl_xor_sync(0xffffffffu, nr[r], o);
            }
        }
        if (lane == 0) {
            #pragma unroll
            for (int r = 0; r < 4; ++r)
                s_sims[w*16 + i + r] = dt[r] / fmaxf(cn * sqrtf(nr[r]), 1e-8f);
        }
    }
    #pragma unroll
    for (int i = 0; i < 8; i += 4) {
        float dt[4], nr[4];
        #pragma unroll
        for (int r = 0; r < 4; ++r) {
            int m = w * 8 + i + r;
            float4 x = __ldg((const float4*)(emb + (size_t)s_kid[m] * Dv) + lane);
            dt[r] = c4.x*x.x + c4.y*x.y + c4.z*x.z + c4.w*x.w;
            nr[r] = x.x*x.x + x.y*x.y + x.z*x.z + x.w*x.w;
        }
        #pragma unroll
        for (int o = 16; o; o >>= 1) {
            #pragma unroll
            for (int r = 0; r < 4; ++r) {
                dt[r] += __shfl_xor_sync(0xffffffffu, dt[r], o);
                nr[r] += __shfl_xor_sync(0xffffffffu, nr[r], o);
            }
        }
        if (lane == 0) {
            #pragma unroll
            for (int r = 0; r < 4; ++r)
                s_sims2[w*8 + i + r] = dt[r] / fmaxf(cn * sqrtf(nr[r]), 1e-8f);
        }
    }
    __syncthreads();

    if (tid < Mv) {
        float my = s_sims[tid];
        int cnt = 0;
        #pragma unroll 8
        for (int j = 0; j < Mv; ++j) {
            float o = s_sims[j];
            cnt += (o > my) || (o == my && j < tid);
        }
        if (cnt < Kv) s_lst1[cnt] = tid;
    } else if (tid < Mv + KTABv) {
        int m = tid - Mv;
        float my = s_sims2[m];
        int cnt = 0;
        #pragma unroll 8
        for (int j = 0; j < KTABv; ++j) {
            float o = s_sims2[j];
            cnt += (o > my) || (o == my && j < m);
        }
        if (cnt < Kv) s_lst2[cnt] = m;
    }
    __syncthreads();

    float4 a1 = make_float4(0.f,0.f,0.f,0.f), a2 = make_float4(0.f,0.f,0.f,0.f);
    if (w < 4) {
        #pragma unroll
        for (int e = 0; e < 8; ++e) {
            int m = s_lst1[w*8 + e];
            float4 xr = __ldg((const float4*)(emb + (size_t)s_rel[m] * Dv) + lane);
            float4 xe = __ldg((const float4*)(emb + (size_t)s_ent[m] * Dv) + lane);
            a1.x += xr.x; a1.y += xr.y; a1.z += xr.z; a1.w += xr.w;
            a2.x += xe.x; a2.y += xe.y; a2.z += xe.z; a2.w += xe.w;
        }
        s_par[w][lane] = a1;
        s_par[4 + w][lane] = a2;
    } else {
        #pragma unroll
        for (int e = 0; e < 8; ++e) {
            int m = s_lst2[(w-4)*8 + e];
            float4 xk = __ldg((const float4*)(emb + (size_t)s_kid[m] * Dv) + lane);
            a1.x += xk.x; a1.y += xk.y; a1.z += xk.z; a1.w += xk.w;
        }
        s_par[4 + w][lane] = a1;
    }
    __syncthreads();

    const float inv = 1.f / (float)Kv;
    if (w < 3) {
        int base = w * 4;
        float4 p0 = s_par[base+0][lane], p1 = s_par[base+1][lane];
        float4 p2 = s_par[base+2][lane], p3 = s_par[base+3][lane];
        float4 s;
        s.x = (p0.x + p1.x + p2.x + p3.x) * inv;
        s.y = (p0.y + p1.y + p2.y + p3.y) * inv;
        s.z = (p0.z + p1.z + p2.z + p3.z) * inv;
        s.w = (p0.w + p1.w + p2.w + p3.w) * inv;
        size_t off;
        if (w == 0)      off = (size_t)(2*u) * DMv;
        else if (w == 1) off = (size_t)(2*u) * DMv + Dv;
        else             off = (size_t)(2*u + 1) * DMv + Dv;
        split_store4(s, g_NAhi, g_NAlo, off + lane * 4);
    } else if (w == 3) {
        split_store4(s_pad4[lane], g_NAhi, g_NAlo, (size_t)(2*u + 1) * DMv + lane * 4);
    }
}

// ================= shared mma.sync bf16 3-split mainloop =====================
// 64x128 tile, 8 warps (2x2 x 4), warptile 32x32, K steps of 16.
// Result staged to sAcc = (float*)sm as [64][132].
#define MMA16816(c, a, b) \
    asm volatile("mma.sync.aligned.m16n8k16.row.col.f32.bf16.bf16.f32 " \
        "{%0,%1,%2,%3}, {%4,%5,%6,%7}, {%8,%9}, {%0,%1,%2,%3};" \
        : "+f"((c)[0]), "+f"((c)[1]), "+f"((c)[2]), "+f"((c)[3]) \
        : "r"((a)[0]), "r"((a)[1]), "r"((a)[2]), "r"((a)[3]), "r"((b)[0]), "r"((b)[1]))

__device__ __forceinline__ void mma3s_main(
    char* sm,
    const __nv_bfloat16* __restrict__ Ahi, const __nv_bfloat16* __restrict__ Alo,
    int lda, int maxRow,
    const __nv_bfloat16* __restrict__ Whi, const __nv_bfloat16* __restrict__ Wlo,
    int ldb, int rowBase, int colBase, int nk)
{
    const int tid = threadIdx.x;
    const int lane = tid & 31, wid = tid >> 5;
    const int wr = wid >> 2, wc = wid & 3;
    const int gr = lane >> 2, gk = (lane & 3) * 2;

    float acc[2][4][4];
    #pragma unroll
    for (int mi = 0; mi < 2; ++mi)
        #pragma unroll
        for (int ni = 0; ni < 4; ++ni)
            #pragma unroll
            for (int q = 0; q < 4; ++q) acc[mi][ni][q] = 0.f;

    const int la_row = tid >> 2, la_k = (tid & 3) * 4;
    const int aRow = min(rowBase + la_row, maxRow);

    {
        uint2 vAh = *(const uint2*)(Ahi + (size_t)aRow * lda + la_k);
        uint2 vAl = *(const uint2*)(Alo + (size_t)aRow * lda + la_k);
        uint2 vBh0 = *(const uint2*)(Whi + (size_t)(colBase + la_row) * ldb + la_k);
        uint2 vBh1 = *(const uint2*)(Whi + (size_t)(colBase + 64 + la_row) * ldb + la_k);
        uint2 vBl0 = *(const uint2*)(Wlo + (size_t)(colBase + la_row) * ldb + la_k);
        uint2 vBl1 = *(const uint2*)(Wlo + (size_t)(colBase + 64 + la_row) * ldb + la_k);
        *(uint2*)(sm + 0     + (la_row*20 + la_k)*2) = vAh;
        *(uint2*)(sm + 5120  + (la_row*20 + la_k)*2) = vAl;
        *(uint2*)(sm + 10240 + (la_row*20 + la_k)*2) = vBh0;
        *(uint2*)(sm + 10240 + ((64+la_row)*20 + la_k)*2) = vBh1;
        *(uint2*)(sm + 20480 + (la_row*20 + la_k)*2) = vBl0;
        *(uint2*)(sm + 20480 + ((64+la_row)*20 + la_k)*2) = vBl1;
    }
    __syncthreads();

    int buf = 0;
    uint2 vAh, vAl, vBh0, vBh1, vBl0, vBl1;
    for (int it = 0; it < nk; ++it) {
        if (it < nk - 1) {
            int k0 = (it + 1) * 16;
            vAh = *(const uint2*)(Ahi + (size_t)aRow * lda + k0 + la_k);
            vAl = *(const uint2*)(Alo + (size_t)aRow * lda + k0 + la_k);
            vBh0 = *(const uint2*)(Whi + (size_t)(colBase + la_row) * ldb + k0 + la_k);
            vBh1 = *(const uint2*)(Whi + (size_t)(colBase + 64 + la_row) * ldb + k0 + la_k);
            vBl0 = *(const uint2*)(Wlo + (size_t)(colBase + la_row) * ldb + k0 + la_k);
            vBl1 = *(const uint2*)(Wlo + (size_t)(colBase + 64 + la_row) * ldb + k0 + la_k);
        }
        {
            const __nv_bfloat16* A_h = (const __nv_bfloat16*)(sm + buf * 2560);
            const __nv_bfloat16* A_l = (const __nv_bfloat16*)(sm + 5120 + buf * 2560);
            const __nv_bfloat16* B_h = (const __nv_bfloat16*)(sm + 10240 + buf * 5120);
            const __nv_bfloat16* B_l = (const __nv_bfloat16*)(sm + 20480 + buf * 5120);
            uint32_t ah[2][4], al[2][4], bh[4][2], bl[4][2];
            #pragma unroll
            for (int mi = 0; mi < 2; ++mi) {
                int r = wr * 32 + mi * 16 + gr;
                ah[mi][0] = *(const uint32_t*)(A_h + r * 20 + gk);
                ah[mi][1] = *(const uint32_t*)(A_h + (r + 8) * 20 + gk);
                ah[mi][2] = *(const uint32_t*)(A_h + r * 20 + gk + 8);
                ah[mi][3] = *(const uint32_t*)(A_h + (r + 8) * 20 + gk + 8);
                al[mi][0] = *(const uint32_t*)(A_l + r * 20 + gk);
                al[mi][1] = *(const uint32_t*)(A_l + (r + 8) * 20 + gk);
                al[mi][2] = *(const uint32_t*)(A_l + r * 20 + gk + 8);
                al[mi][3] = *(const uint32_t*)(A_l + (r + 8) * 20 + gk + 8);
            }
            #pragma unroll
            for (int ni = 0; ni < 4; ++ni) {
                int n = wc * 32 + ni * 8 + gr;
                bh[ni][0] = *(const uint32_t*)(B_h + n * 20 + gk);
                bh[ni][1] = *(const uint32_t*)(B_h + n * 20 + gk + 8);
                bl[ni][0] = *(const uint32_t*)(B_l + n * 20 + gk);
                bl[ni][1] = *(const uint32_t*)(B_l + n * 20 + gk + 8);
            }
            #pragma unroll
            for (int mi = 0; mi < 2; ++mi)
                #pragma unroll
                for (int ni = 0; ni < 4; ++ni) {
                    MMA16816(acc[mi][ni], ah[mi], bh[ni]);
                    MMA16816(acc[mi][ni], ah[mi], bl[ni]);
                    MMA16816(acc[mi][ni], al[mi], bh[ni]);
                }
        }
        if (it < nk - 1) {
            int nb = buf ^ 1;
            __syncthreads();
            *(uint2*)(sm + 0     + nb * 2560 + (la_row*20 + la_k)*2) = vAh;
            *(uint2*)(sm + 5120  + nb * 2560 + (la_row*20 + la_k)*2) = vAl;
            *(uint2*)(sm + 10240 + nb * 5120 + (la_row*20 + la_k)*2) = vBh0;
            *(uint2*)(sm + 10240 + nb * 5120 + ((64+la_row)*20 + la_k)*2) = vBh1;
            *(uint2*)(sm + 20480 + nb * 5120 + (la_row*20 + la_k)*2) = vBl0;
            *(uint2*)(sm + 20480 + nb * 5120 + ((64+la_row)*20 + la_k)*2) = vBl1;
            __syncthreads();
            buf = nb;
        }
    }
    __syncthreads();   // mainloop buffers dead; overlay sAcc

    float* sAcc = (float*)sm;
    #pragma unroll
    for (int mi = 0; mi < 2; ++mi) {
        #pragma unroll
        for (int ni = 0; ni < 4; ++ni) {
            int r0 = wr * 32 + mi * 16 + gr;
            int c0 = wc * 32 + ni * 8 + gk;
            *(float2*)&sAcc[r0 * 132 + c0]       = make_float2(acc[mi][ni][0], acc[mi][ni][1]);
            *(float2*)&sAcc[(r0 + 8) * 132 + c0] = make_float2(acc[mi][ni][2], acc[mi][ni][3]);
        }
    }
    __syncthreads();
}

// ================= GCN GEMM (mma) + tanh + gate + combine ====================
__global__ __launch_bounds__(256) void gcn_mma(
    const float* __restrict__ wb, const float* __restrict__ gb,
    const float* __restrict__ gate_w, const float* __restrict__ gate_b,
    float* __restrict__ X)
{
    extern __shared__ char sm[];
    const int tid = threadIdx.x;
    const int rowBase = blockIdx.x * 64;
    mma3s_main(sm, g_NAhi, g_NAlo, DMv, 2*NUNIT - 1,
               g_WgcnHi, g_WgcnLo, DMv, rowBase, 0, 16);
    float* sAcc = (float*)sm;

    // tanh(+biases) in place
    #pragma unroll
    for (int i = 0; i < 8; ++i) {
        int lin = tid + i * 256;
        int r = lin >> 5, c = (lin & 31) * 4;
        float4 v = *(const float4*)&sAcc[r * 132 + c];
        v.x = tanhf(v.x + wb[c]   + gb[c]);
        v.y = tanhf(v.y + wb[c+1] + gb[c+1]);
        v.z = tanhf(v.z + wb[c+2] + gb[c+2]);
        v.w = tanhf(v.w + wb[c+3] + gb[c+3]);
        *(float4*)&sAcc[r * 132 + c] = v;
    }
    __syncthreads();

    // gate + combine: 8 threads per unit (32 units per block)
    const int t = tid >> 3, sub = tid & 7;
    const int u = (rowBase >> 1) + t;
    if (u < NUNIT) {
        float gv = 0.f;
        #pragma unroll
        for (int k = 0; k < 16; ++k) {
            int c = sub*16 + k;
            gv += sAcc[(2*t) * 132 + c] * gate_w[c] + sAcc[(2*t+1) * 132 + c] * gate_w[128 + c];
        }
        gv += __shfl_xor_sync(0xffffffffu, gv, 1);
        gv += __shfl_xor_sync(0xffffffffu, gv, 2);
        gv += __shfl_xor_sync(0xffffffffu, gv, 4);
        float a = sigm(gv + gate_b[0]);
        int row, col;
        if (u < Bv)             { row = u;                      col = 0; }
        else if (u < 2*Bv)      { row = u - Bv;                 col = Dv; }
        else if (u < 2*Bv+FEWv) { row = Bv + (u - 2*Bv);        col = 0; }
        else                    { row = Bv + (u - 2*Bv - FEWv); col = Dv; }
        size_t xo = (size_t)row * DMv + col;
        #pragma unroll
        for (int k4 = 0; k4 < 4; ++k4) {
            int c = sub*16 + k4*4;
            float4 st = *(const float4*)&sAcc[(2*t) * 132 + c];
            float4 kn = *(const float4*)&sAcc[(2*t+1) * 132 + c];
            float4 o;
            o.x = (1.f - a)*st.x + a*kn.x;
            o.y = (1.f - a)*st.y + a*kn.y;
            o.z = (1.f - a)*st.z + a*kn.z;
            o.w = (1.f - a)*st.w + a*kn.w;
            *(float4*)(X + xo + c) = o;
            split_store4(o, g_XAhi, g_XAlo, xo + c);
        }
    }
}

// ================= p1 GEMM (mma) + relu, emit H splits =======================
__global__ __launch_bounds__(256) void p1_mma(const float* __restrict__ p1_b)
{
    extern __shared__ char sm[];
    const int tid = threadIdx.x;
    const int rowBase = blockIdx.y * 64;
    const int colBase = blockIdx.x * 128;
    mma3s_main(sm, g_XAhi, g_XAlo, DMv, NROWS - 1,
               g_Wp1Hi, g_Wp1Lo, DMv, rowBase, colBase, 16);
    float* sAcc = (float*)sm;
    #pragma unroll
    for (int i = 0; i < 8; ++i) {
        int lin = tid + i * 256;
        int r = lin >> 5, cl = (lin & 31) * 4;
        int row = rowBase + r;
        if (row >= NROWS) continue;
        int c = colBase + cl;
        float4 v = *(const float4*)&sAcc[r * 132 + cl];
        v.x = fmaxf(v.x + p1_b[c],   0.f);
        v.y = fmaxf(v.y + p1_b[c+1], 0.f);
        v.z = fmaxf(v.z + p1_b[c+2], 0.f);
        v.w = fmaxf(v.w + p1_b[c+3], 0.f);
        split_store4(v, g_Hshi, g_Hslo, (size_t)row * HIDv + c);
    }
}

// ================= p2 GEMM (mma) + bias -> O fp32 ============================
__global__ __launch_bounds__(256) void p2_mma(const float* __restrict__ p2_b)
{
    extern __shared__ char sm[];
    const int tid = threadIdx.x;
    const int rowBase = blockIdx.y * 64;
    const int colBase = blockIdx.x * 128;
    mma3s_main(sm, g_Hshi, g_Hslo, HIDv, NROWS - 1,
               g_Wp2Hi, g_Wp2Lo, HIDv, rowBase, colBase, 32);
    float* sAcc = (float*)sm;
    #pragma unroll
    for (int i = 0; i < 8; ++i) {
        int lin = tid + i * 256;
        int r = lin >> 5, cl = (lin & 31) * 4;
        int row = rowBase + r;
        if (row >= NROWS) continue;
        int c = colBase + cl;
        float4 v = *(const float4*)&sAcc[r * 132 + cl];
        v.x += p2_b[c]; v.y += p2_b[c+1]; v.z += p2_b[c+2]; v.w += p2_b[c+3];
        *(float4*)&g_O[(size_t)row * DMv + c] = v;
    }
}

// ================= gate GEMM (mma) + fused LSTM cell =========================
__global__ __launch_bounds__(256) void gates_mma(
    const __nv_bfloat16* __restrict__ Ahi, const __nv_bfloat16* __restrict__ Alo,
    const __nv_bfloat16* __restrict__ Whi, const __nv_bfloat16* __restrict__ Wlo,
    int first)
{
    extern __shared__ char sm[];
    const int tid = threadIdx.x;
    const int rowBase = blockIdx.y * 64;
    const int colBase = blockIdx.x * 128;
    const int jbase = colBase >> 2;
    mma3s_main(sm, Ahi, Alo, DMv, Bv - 1, Whi, Wlo, DMv, rowBase, colBase, 16);
    float* sAcc = (float*)sm;

    #pragma unroll
    for (int i = 0; i < 8; ++i) {
        int lin = tid + i * 256;
        int r = lin >> 5, jl = lin & 31;
        float4 gv = *(const float4*)&sAcc[r * 132 + jl * 4];
        int row = rowBase + r;
        int colp = colBase + jl * 4;
        float gi = gv.x, gf = gv.y, gg = gv.z, go = gv.w;
        size_t g0i = (size_t)row * G4 + colp;
        if (first) {
            gi += g_b4[colp]; gf += g_b4[colp+1]; gg += g_b4[colp+2]; go += g_b4[colp+3];
            *(float4*)&g_G0[g0i] = make_float4(gi, gf, gg, go);
        } else {
            float4 g0 = *(const float4*)&g_G0[g0i];
            gi += g0.x + g_rt4[colp];   gf += g0.y + g_rt4[colp+1];
            gg += g0.z + g_rt4[colp+2]; go += g0.w + g_rt4[colp+3];
        }
        size_t ci = (size_t)row * DMv + jbase + jl;
        float cold = first ? 0.f : g_C[ci];
        float cv = sigm(gf) * cold + sigm(gi) * tanhf(gg);
        g_C[ci] = cv;
        float h = g_X[ci] + sigm(go) * tanhf(cv);
        g_h[ci] = h;
        __nv_bfloat16 hb = __float2bfloat16(h);
        g_hhi[ci] = hb;
        g_hlo[ci] = __float2bfloat16(h - __bfloat162float(hb));
    }
}

// ---------------- residual + layernorm (+ bf16 split emit for query rows) ---
__global__ void posln_kernel(const float* __restrict__ O, float* __restrict__ X,
                             const float* __restrict__ g, const float* __restrict__ b)
{
    __shared__ float s_red[8];
    const int r = blockIdx.x, t = threadIdx.x;
    const int lane = t & 31, w = t >> 5;
    float z = O[(size_t)r * DMv + t] + X[(size_t)r * DMv + t];
    float v = z;
    #pragma unroll
    for (int o = 16; o; o >>= 1) v += __shfl_xor_sync(0xffffffffu, v, o);
    if (lane == 0) s_red[w] = v;
    __syncthreads();
    float mu = 0.f;
    #pragma unroll
    for (int i = 0; i < 8; ++i) mu += s_red[i];
    mu *= (1.f / 256.f);
    __syncthreads();
    float d = z - mu;
    v = d * d;
    #pragma unroll
    for (int o = 16; o; o >>= 1) v += __shfl_xor_sync(0xffffffffu, v, o);
    if (lane == 0) s_red[w] = v;
    __syncthreads();
    float var = 0.f;
    #pragma unroll
    for (int i = 0; i < 8; ++i) var += s_red[i];
    var *= (1.f / 255.f);
    float y = d / (sqrtf(var) + 1e-3f) * g[t] + b[t];
    X[(size_t)r * DMv + t] = y;
    if (r < Bv) {
        __nv_bfloat16 hi = __float2bfloat16(y);
        g_Xhi[(size_t)r * DMv + t] = hi;
        g_Xlo[(size_t)r * DMv + t] = __float2bfloat16(y - __bfloat162float(hi));
    }
}

// ---------------- support_g + l2 normalization ------------------------------
__global__ void sg_kernel(const float* __restrict__ X)
{
    __shared__ float s_red[8];
    const int t = threadIdx.x, lane = t & 31, w = t >> 5;
    float s = 0.f;
    #pragma unroll
    for (int i = 0; i < FEWv; ++i) s += X[(size_t)(Bv + i) * DMv + t];
    s *= (1.f / (float)FEWv);
    g_sg[t] = s;
    float v = s * s;
    #pragma unroll
    for (int o = 16; o; o >>= 1) v += __shfl_xor_sync(0xffffffffu, v, o);
    if (lane == 0) s_red[w] = v;
    __syncthreads();
    float nn = 0.f;
    #pragma unroll
    for (int i = 0; i < 8; ++i) nn += s_red[i];
    g_sgn[t] = s / fmaxf(sqrtf(nn), 1e-12f);
}

// ---------------- rt4[4j+g] = w_hh[g*512+j, 256:512] @ support_g ------------
__global__ void rterm_kernel(const float* __restrict__ w_hh)
{
    const int t = threadIdx.x, lane = t & 31, w = t >> 5;
    const int o = blockIdx.x * 8 + w;
    const int j = o >> 2, gate = o & 3;
    const float* wr = w_hh + (size_t)(gate * 512 + j) * HIDv + DMv;
    float s = 0.f;
    #pragma unroll
    for (int q = 0; q < 8; ++q) s += g_sg[lane + q * 32] * wr[lane + q * 32];
    #pragma unroll
    for (int off = 16; off; off >>= 1) s += __shfl_xor_sync(0xffffffffu, s, off);
    if (lane == 0) g_rt4[o] = s;
}

// ---------------- final cosine against normalized support_g ----------------
__global__ void final_kernel(float* __restrict__ out)
{
    __shared__ float s_red[16];
    const int b = blockIdx.x, t = threadIdx.x, lane = t & 31, w = t >> 5;
    float hv = g_h[(size_t)b * DMv + t];
    float d = hv * g_sgn[t];
    float ss = hv * hv;
    #pragma unroll
    for (int o = 16; o; o >>= 1) {
        d  += __shfl_xor_sync(0xffffffffu, d,  o);
        ss += __shfl_xor_sync(0xffffffffu, ss, o);
    }
    if (lane == 0) { s_red[w] = d; s_red[8 + w] = ss; }
    __syncthreads();
    if (t == 0) {
        float Dd = 0.f, S = 0.f;
        #pragma unroll
        for (int i = 0; i < 8; ++i) { Dd += s_red[i]; S += s_red[8 + i]; }
        out[b] = Dd / fmaxf(sqrtf(S), 1e-12f);
    }
}

// ---------------- launcher ---------------------------------------------------
extern "C" void kernel_launch(void* const* d_in, const int* in_sizes, int n_in,
                              void* d_out, int out_size)
{
    const int*   query    = (const int*)  d_in[0];
    const int*   support  = (const int*)  d_in[1];
    const int*   q_l_conn = (const int*)  d_in[2];
    const int*   q_r_conn = (const int*)  d_in[4];
    const int*   s_l_conn = (const int*)  d_in[6];
    const int*   s_r_conn = (const int*)  d_in[8];
    const int*   knn      = (const int*)  d_in[10];
    const float* emb      = (const float*)d_in[11];
    const float* gcn_w    = (const float*)d_in[12];
    const float* gcn_wb   = (const float*)d_in[13];
    const float* gcn_b    = (const float*)d_in[14];
    const float* gate_w   = (const float*)d_in[15];
    const float* gate_b   = (const float*)d_in[16];
    const float* p1_w     = (const float*)d_in[17];
    const float* p1_b     = (const float*)d_in[18];
    const float* p2_w     = (const float*)d_in[19];
    const float* p2_b     = (const float*)d_in[20];
    const float* ln_g     = (const float*)d_in[21];
    const float* ln_b     = (const float*)d_in[22];
    const float* w_ih     = (const float*)d_in[23];
    const float* w_hh     = (const float*)d_in[24];
    const float* b_ih     = (const float*)d_in[25];
    const float* b_hh     = (const float*)d_in[26];

    float *pX, *pO;
    __nv_bfloat16 *pXhi, *pXlo, *phhi, *phlo, *pWihHi, *pWihLo, *pWhhHi, *pWhhLo;
    cudaGetSymbolAddress((void**)&pX,  g_X);
    cudaGetSymbolAddress((void**)&pO,  g_O);
    cudaGetSymbolAddress((void**)&pXhi, g_Xhi);
    cudaGetSymbolAddress((void**)&pXlo, g_Xlo);
    cudaGetSymbolAddress((void**)&phhi, g_hhi);
    cudaGetSymbolAddress((void**)&phlo, g_hlo);
    cudaGetSymbolAddress((void**)&pWihHi, g_WihHi);
    cudaGetSymbolAddress((void**)&pWihLo, g_WihLo);
    cudaGetSymbolAddress((void**)&pWhhHi, g_WhhHi);
    cudaGetSymbolAddress((void**)&pWhhLo, g_WhhLo);

    // 0) weight packing (independent)
    pack_w<<<G4, 256>>>(w_ih, w_hh, b_ih, b_hh);
    pack_se<<<Dv + HIDv + DMv, 256>>>(gcn_w, p1_w, p2_w);

    // 1) neighbor encoder sims/topk/means -> NA bf16 splits [8212, 256]
    ne_sims<<<NUNIT, 256>>>(query, support, q_l_conn, q_r_conn, s_l_conn, s_r_conn,
                            knn, emb);
    // 2) GCN GEMM (mma) + tanh + gate + combine -> X fp32 + X splits
    gcn_mma<<<(2*NUNIT + 63)/64, 256, SMEM_MMA>>>(gcn_wb, gcn_b, gate_w, gate_b, pX);

    // 3) support encoder: p1 (mma, relu -> H splits), p2 (mma -> O), LN
    p1_mma<<<dim3(HIDv/128, (NROWS + 63)/64), 256, SMEM_MMA>>>(p1_b);
    p2_mma<<<dim3(DMv/128, (NROWS + 63)/64), 256, SMEM_MMA>>>(p2_b);
    posln_kernel<<<NROWS, 256>>>(pO, pX, ln_g, ln_b);

    // 4) support_g, normalization, reduced interleaved r-term
    sg_kernel<<<1, 256>>>(pX);
    rterm_kernel<<<G4/8, 256>>>(w_hh);

    // 5) LSTM steps on mma.sync bf16 (3x split), fused cell epilogue
    gates_mma<<<dim3(G4/128, Bv/64), 256, SMEM_MMA>>>(pXhi, pXlo, pWihHi, pWihLo, 1);
    for (int s = 0; s < 3; ++s)
        gates_mma<<<dim3(G4/128, Bv/64), 256, SMEM_MMA>>>(phhi, phlo, pWhhHi, pWhhLo, 0);

    // 6) out[b] = l2n(h[b]) . l2n(support_g)
    final_kernel<<<Bv, 256>>>((float*)d_out);

    (void)in_sizes; (void)n_in; (void)out_size;
}

// round 13
// speedup vs baseline: 4.6939x; 1.1389x over previous
#include <cuda_runtime.h>
#include <cuda_bf16.h>
#include <math.h>
#include <stdint.h>

#define Dv    128
#define Mv    128
#define KTABv 64
#define Kv    32
#define Bv    2048
#define FEWv  5
#define DMv   256
#define HIDv  512
#define NSYMv 100000
#define NROWS (Bv + FEWv)     /* 2053 */
#define NUNIT (2*Bv + 2*FEWv) /* 4106 */
#define G4    1024            /* packed gate width: 4 gates x 256, interleaved 4j+g */
#define SMEM_MMA 36864        /* mainloop tiles (36.9KB) >= acc staging (33.8KB) */

// ---------------- scratch (device globals) ----------------------------------
__device__ float g_X [NROWS * DMv];
__device__ float g_O [NROWS * DMv];
__device__ float g_G0[(size_t)Bv * G4];
__device__ float g_C [Bv * DMv];
__device__ float g_h [Bv * DMv];
__device__ float g_sg [DMv];
__device__ float g_sgn[DMv];
__device__ float g_rt4[G4];
__device__ float g_b4[G4];
__device__ __nv_bfloat16 g_NAhi[(size_t)2 * NUNIT * DMv], g_NAlo[(size_t)2 * NUNIT * DMv];
__device__ __nv_bfloat16 g_XAhi[NROWS * DMv], g_XAlo[NROWS * DMv];
__device__ __nv_bfloat16 g_Hshi[(size_t)NROWS * HIDv], g_Hslo[(size_t)NROWS * HIDv];
__device__ __nv_bfloat16 g_Xhi[Bv * DMv], g_Xlo[Bv * DMv];
__device__ __nv_bfloat16 g_hhi[Bv * DMv], g_hlo[Bv * DMv];
__device__ __nv_bfloat16 g_WihHi[G4 * DMv], g_WihLo[G4 * DMv];
__device__ __nv_bfloat16 g_WhhHi[G4 * DMv], g_WhhLo[G4 * DMv];
__device__ __nv_bfloat16 g_WgcnHi[Dv * DMv], g_WgcnLo[Dv * DMv];
__device__ __nv_bfloat16 g_Wp1Hi[HIDv * DMv], g_Wp1Lo[HIDv * DMv];
__device__ __nv_bfloat16 g_Wp2Hi[DMv * HIDv], g_Wp2Lo[DMv * HIDv];

__device__ __forceinline__ float sigm(float x) { return 1.f / (1.f + expf(-x)); }

__device__ __forceinline__ uint32_t smem_u32(const void* p) {
    uint32_t a;
    asm("{ .reg .u64 t; cvta.to.shared.u64 t, %1; cvt.u32.u64 %0, t; }" : "=r"(a) : "l"(p));
    return a;
}
__device__ __forceinline__ void ldsm_x4(uint32_t* r, uint32_t addr) {
    asm volatile("ldmatrix.sync.aligned.m8n8.x4.shared.b16 {%0,%1,%2,%3}, [%4];"
        : "=r"(r[0]), "=r"(r[1]), "=r"(r[2]), "=r"(r[3]) : "r"(addr));
}

__device__ __forceinline__ void split_store4(float4 v, __nv_bfloat16* hi,
                                             __nv_bfloat16* lo, size_t idx)
{
    __nv_bfloat16 h0 = __float2bfloat16(v.x), h1 = __float2bfloat16(v.y);
    __nv_bfloat16 h2 = __float2bfloat16(v.z), h3 = __float2bfloat16(v.w);
    __nv_bfloat162 a, b, c, d;
    a.x = h0; a.y = h1; b.x = h2; b.y = h3;
    c.x = __float2bfloat16(v.x - __bfloat162float(h0));
    c.y = __float2bfloat16(v.y - __bfloat162float(h1));
    d.x = __float2bfloat16(v.z - __bfloat162float(h2));
    d.y = __float2bfloat16(v.w - __bfloat162float(h3));
    *(__nv_bfloat162*)&hi[idx]     = a;
    *(__nv_bfloat162*)&hi[idx + 2] = b;
    *(__nv_bfloat162*)&lo[idx]     = c;
    *(__nv_bfloat162*)&lo[idx + 2] = d;
}

// ================= pack gate weights (bf16 hi/lo, interleaved 4j+g) =========
__global__ void pack_w(const float* __restrict__ w_ih, const float* __restrict__ w_hh,
                       const float* __restrict__ b_ih, const float* __restrict__ b_hh)
{
    const int r = blockIdx.x, t = threadIdx.x;
    const int j = r >> 2, gate = r & 3;
    const int m = gate * 512 + j;
    float vih = w_ih[(size_t)m * DMv + t];
    __nv_bfloat16 h1 = __float2bfloat16(vih);
    g_WihHi[(size_t)r * DMv + t] = h1;
    g_WihLo[(size_t)r * DMv + t] = __float2bfloat16(vih - __bfloat162float(h1));
    float vhh = w_hh[(size_t)m * HIDv + t];
    __nv_bfloat16 h2 = __float2bfloat16(vhh);
    g_WhhHi[(size_t)r * DMv + t] = h2;
    g_WhhLo[(size_t)r * DMv + t] = __float2bfloat16(vhh - __bfloat162float(h2));
    if (t == 0) g_b4[r] = b_ih[m] + b_hh[m];
}

// ================= pack support-encoder + gcn weights ========================
__global__ void pack_se(const float* __restrict__ gcn_w, const float* __restrict__ p1_w,
                        const float* __restrict__ p2_w)
{
    const int r = blockIdx.x, t = threadIdx.x;
    if (r < Dv) {
        float v = gcn_w[(size_t)r * DMv + t];
        __nv_bfloat16 h = __float2bfloat16(v);
        g_WgcnHi[(size_t)r * DMv + t] = h;
        g_WgcnLo[(size_t)r * DMv + t] = __float2bfloat16(v - __bfloat162float(h));
    } else if (r < Dv + HIDv) {
        int q = r - Dv;
        float v = p1_w[(size_t)q * DMv + t];
        __nv_bfloat16 h = __float2bfloat16(v);
        g_Wp1Hi[(size_t)q * DMv + t] = h;
        g_Wp1Lo[(size_t)q * DMv + t] = __float2bfloat16(v - __bfloat162float(h));
    } else {
        int q = r - Dv - HIDv;
        #pragma unroll
        for (int s = 0; s < 2; ++s) {
            int c = t + s * 256;
            float v = p2_w[(size_t)q * HIDv + c];
            __nv_bfloat16 h = __float2bfloat16(v);
            g_Wp2Hi[(size_t)q * HIDv + c] = h;
            g_Wp2Lo[(size_t)q * HIDv + c] = __float2bfloat16(v - __bfloat162float(h));
        }
    }
}

// ================= neighbor encoder: sims + topk + means (float4) ===========
__global__ __launch_bounds__(256) void ne_sims(
    const int* __restrict__ query, const int* __restrict__ support,
    const int* __restrict__ q_l_conn, const int* __restrict__ q_r_conn,
    const int* __restrict__ s_l_conn, const int* __restrict__ s_r_conn,
    const int* __restrict__ knn, const float* __restrict__ emb)
{
    __shared__ float4 s_center4[32];
    __shared__ float4 s_pad4[32];
    __shared__ float  s_sims[Mv];
    __shared__ float  s_sims2[KTABv];
    __shared__ int    s_rel[Mv], s_ent[Mv], s_kid[KTABv];
    __shared__ int    s_lst1[Kv], s_lst2[Kv];
    __shared__ float4 s_par[12][32];
    __shared__ float  s_cn;

    const int u   = blockIdx.x;
    const int tid = threadIdx.x;
    const int lane = tid & 31, w = tid >> 5;

    const int* conn; int id;
    if (u < Bv)            { conn = q_l_conn + (size_t)u * (Mv*2);            id = query[u*2+0]; }
    else if (u < 2*Bv)     { int v = u - Bv;    conn = q_r_conn + (size_t)v*(Mv*2); id = query[v*2+1]; }
    else if (u < 2*Bv+FEWv){ int v = u - 2*Bv;  conn = s_l_conn + (size_t)v*(Mv*2); id = support[v*2+0]; }
    else                   { int v = u - (2*Bv+FEWv); conn = s_r_conn + (size_t)v*(Mv*2); id = support[v*2+1]; }

    if (tid < 32) {
        float4 cv = __ldg((const float4*)(emb + (size_t)id * Dv) + tid);
        s_center4[tid] = cv;
        float v = cv.x*cv.x + cv.y*cv.y + cv.z*cv.z + cv.w*cv.w;
        #pragma unroll
        for (int o = 16; o; o >>= 1) v += __shfl_xor_sync(0xffffffffu, v, o);
        if (tid == 0) s_cn = sqrtf(v);
    } else if (tid < 64) {
        s_pad4[tid - 32] = __ldg((const float4*)(emb + (size_t)NSYMv * Dv) + (tid - 32));
    } else if (tid < 192) {
        int m = tid - 64;
        int2 rc = ((const int2*)conn)[m];
        s_rel[m] = rc.x; s_ent[m] = rc.y;
    } else {
        int m = tid - 192;
        s_kid[m] = knn[(size_t)id * KTABv + m];
    }
    __syncthreads();
    const float  cn = s_cn;
    const float4 c4 = s_center4[lane];

    #pragma unroll
    for (int i = 0; i < 16; i += 4) {
        float dt[4], nr[4];
        #pragma unroll
        for (int r = 0; r < 4; ++r) {
            int m = w * 16 + i + r;
            float4 x = __ldg((const float4*)(emb + (size_t)s_ent[m] * Dv) + lane);
            dt[r] = c4.x*x.x + c4.y*x.y + c4.z*x.z + c4.w*x.w;
            nr[r] = x.x*x.x + x.y*x.y + x.z*x.z + x.w*x.w;
        }
        #pragma unroll
        for (int o = 16; o; o >>= 1) {
            #pragma unroll
            for (int r = 0; r < 4; ++r) {
                dt[r] += __shfl_xor_sync(0xffffffffu, dt[r], o);
                nr[r] += __shfl_xor_sync(0xffffffffu, nr[r], o);
            }
        }
        if (lane == 0) {
            #pragma unroll
            for (int r = 0; r < 4; ++r)
                s_sims[w*16 + i + r] = dt[r] / fmaxf(cn * sqrtf(nr[r]), 1e-8f);
        }
    }
    #pragma unroll
    for (int i = 0; i < 8; i += 4) {
        float dt[4], nr[4];
        #pragma unroll
        for (int r = 0; r < 4; ++r) {
            int m = w * 8 + i + r;
            float4 x = __ldg((const float4*)(emb + (size_t)s_kid[m] * Dv) + lane);
            dt[r] = c4.x*x.x + c4.y*x.y + c4.z*x.z + c4.w*x.w;
            nr[r] = x.x*x.x + x.y*x.y + x.z*x.z + x.w*x.w;
        }
        #pragma unroll
        for (int o = 16; o; o >>= 1) {
            #pragma unroll
            for (int r = 0; r < 4; ++r) {
                dt[r] += __shfl_xor_sync(0xffffffffu, dt[r], o);
                nr[r] += __shfl_xor_sync(0xffffffffu, nr[r], o);
            }
        }
        if (lane == 0) {
            #pragma unroll
            for (int r = 0; r < 4; ++r)
                s_sims2[w*8 + i + r] = dt[r] / fmaxf(cn * sqrtf(nr[r]), 1e-8f);
        }
    }
    __syncthreads();

    if (tid < Mv) {
        float my = s_sims[tid];
        int cnt = 0;
        #pragma unroll 8
        for (int j = 0; j < Mv; ++j) {
            float o = s_sims[j];
            cnt += (o > my) || (o == my && j < tid);
        }
        if (cnt < Kv) s_lst1[cnt] = tid;
    } else if (tid < Mv + KTABv) {
        int m = tid - Mv;
        float my = s_sims2[m];
        int cnt = 0;
        #pragma unroll 8
        for (int j = 0; j < KTABv; ++j) {
            float o = s_sims2[j];
            cnt += (o > my) || (o == my && j < m);
        }
        if (cnt < Kv) s_lst2[cnt] = m;
    }
    __syncthreads();

    float4 a1 = make_float4(0.f,0.f,0.f,0.f), a2 = make_float4(0.f,0.f,0.f,0.f);
    if (w < 4) {
        #pragma unroll
        for (int e = 0; e < 8; ++e) {
            int m = s_lst1[w*8 + e];
            float4 xr = __ldg((const float4*)(emb + (size_t)s_rel[m] * Dv) + lane);
            float4 xe = __ldg((const float4*)(emb + (size_t)s_ent[m] * Dv) + lane);
            a1.x += xr.x; a1.y += xr.y; a1.z += xr.z; a1.w += xr.w;
            a2.x += xe.x; a2.y += xe.y; a2.z += xe.z; a2.w += xe.w;
        }
        s_par[w][lane] = a1;
        s_par[4 + w][lane] = a2;
    } else {
        #pragma unroll
        for (int e = 0; e < 8; ++e) {
            int m = s_lst2[(w-4)*8 + e];
            float4 xk = __ldg((const float4*)(emb + (size_t)s_kid[m] * Dv) + lane);
            a1.x += xk.x; a1.y += xk.y; a1.z += xk.z; a1.w += xk.w;
        }
        s_par[4 + w][lane] = a1;
    }
    __syncthreads();

    const float inv = 1.f / (float)Kv;
    if (w < 3) {
        int base = w * 4;
        float4 p0 = s_par[base+0][lane], p1 = s_par[base+1][lane];
        float4 p2 = s_par[base+2][lane], p3 = s_par[base+3][lane];
        float4 s;
        s.x = (p0.x + p1.x + p2.x + p3.x) * inv;
        s.y = (p0.y + p1.y + p2.y + p3.y) * inv;
        s.z = (p0.z + p1.z + p2.z + p3.z) * inv;
        s.w = (p0.w + p1.w + p2.w + p3.w) * inv;
        size_t off;
        if (w == 0)      off = (size_t)(2*u) * DMv;
        else if (w == 1) off = (size_t)(2*u) * DMv + Dv;
        else             off = (size_t)(2*u + 1) * DMv + Dv;
        split_store4(s, g_NAhi, g_NAlo, off + lane * 4);
    } else if (w == 3) {
        split_store4(s_pad4[lane], g_NAhi, g_NAlo, (size_t)(2*u + 1) * DMv + lane * 4);
    }
}

// ================= shared mma.sync bf16 3-split mainloop (ldmatrix) ==========
// 64x128 tile, 8 warps (2x4), warptile 32x32, K steps of 16.
// smem: row stride 24 bf16 (48B, 16B-aligned rows; bank-conflict-free ldmatrix)
//  Ah: buf*3072  Al: 6144+buf*3072  Bh: 12288+buf*6144  Bl: 24576+buf*6144
// Result staged to sAcc = (float*)sm as [64][132].
#define MMA16816(c, a, b) \
    asm volatile("mma.sync.aligned.m16n8k16.row.col.f32.bf16.bf16.f32 " \
        "{%0,%1,%2,%3}, {%4,%5,%6,%7}, {%8,%9}, {%0,%1,%2,%3};" \
        : "+f"((c)[0]), "+f"((c)[1]), "+f"((c)[2]), "+f"((c)[3]) \
        : "r"((a)[0]), "r"((a)[1]), "r"((a)[2]), "r"((a)[3]), "r"((b)[0]), "r"((b)[1]))

__device__ __forceinline__ void mma3s_main(
    char* sm,
    const __nv_bfloat16* __restrict__ Ahi, const __nv_bfloat16* __restrict__ Alo,
    int lda, int maxRow,
    const __nv_bfloat16* __restrict__ Whi, const __nv_bfloat16* __restrict__ Wlo,
    int ldb, int rowBase, int colBase, int nk)
{
    const int tid = threadIdx.x;
    const int lane = tid & 31, wid = tid >> 5;
    const int wr = wid >> 2, wc = wid & 3;
    const uint32_t sbase = smem_u32(sm);

    float acc[2][4][4];
    #pragma unroll
    for (int mi = 0; mi < 2; ++mi)
        #pragma unroll
        for (int ni = 0; ni < 4; ++ni)
            #pragma unroll
            for (int q = 0; q < 4; ++q) acc[mi][ni][q] = 0.f;

    const int la_row = tid >> 2, la_k = (tid & 3) * 4;
    const int aRow = min(rowBase + la_row, maxRow);
    const int sOff = (la_row * 24 + la_k) * 2;
    const int sOff2 = ((64 + la_row) * 24 + la_k) * 2;

    // ldmatrix lane addressing precompute
    const int lp = lane >> 3, lq = lane & 7;
    const int aRowSel = (lp & 1) * 8 + lq, aKSel = (lp >> 1) * 8;
    const int bRowSel = (lp >> 1) * 8 + lq, bKSel = (lp & 1) * 8;

    {
        uint2 vAh = *(const uint2*)(Ahi + (size_t)aRow * lda + la_k);
        uint2 vAl = *(const uint2*)(Alo + (size_t)aRow * lda + la_k);
        uint2 vBh0 = *(const uint2*)(Whi + (size_t)(colBase + la_row) * ldb + la_k);
        uint2 vBh1 = *(const uint2*)(Whi + (size_t)(colBase + 64 + la_row) * ldb + la_k);
        uint2 vBl0 = *(const uint2*)(Wlo + (size_t)(colBase + la_row) * ldb + la_k);
        uint2 vBl1 = *(const uint2*)(Wlo + (size_t)(colBase + 64 + la_row) * ldb + la_k);
        *(uint2*)(sm + 0     + sOff) = vAh;
        *(uint2*)(sm + 6144  + sOff) = vAl;
        *(uint2*)(sm + 12288 + sOff) = vBh0;
        *(uint2*)(sm + 12288 + sOff2) = vBh1;
        *(uint2*)(sm + 24576 + sOff) = vBl0;
        *(uint2*)(sm + 24576 + sOff2) = vBl1;
    }
    __syncthreads();

    int buf = 0;
    uint2 vAh, vAl, vBh0, vBh1, vBl0, vBl1;
    for (int it = 0; it < nk; ++it) {
        if (it < nk - 1) {
            int k0 = (it + 1) * 16;
            vAh = *(const uint2*)(Ahi + (size_t)aRow * lda + k0 + la_k);
            vAl = *(const uint2*)(Alo + (size_t)aRow * lda + k0 + la_k);
            vBh0 = *(const uint2*)(Whi + (size_t)(colBase + la_row) * ldb + k0 + la_k);
            vBh1 = *(const uint2*)(Whi + (size_t)(colBase + 64 + la_row) * ldb + k0 + la_k);
            vBl0 = *(const uint2*)(Wlo + (size_t)(colBase + la_row) * ldb + k0 + la_k);
            vBl1 = *(const uint2*)(Wlo + (size_t)(colBase + 64 + la_row) * ldb + k0 + la_k);
        }
        {
            const uint32_t aH = sbase + buf * 3072;
            const uint32_t aL = sbase + 6144 + buf * 3072;
            const uint32_t bH = sbase + 12288 + buf * 6144;
            const uint32_t bL = sbase + 24576 + buf * 6144;
            uint32_t ah[2][4], al[2][4], bh[4][2], bl[4][2];
            #pragma unroll
            for (int mi = 0; mi < 2; ++mi) {
                uint32_t off = ((wr * 32 + mi * 16 + aRowSel) * 24 + aKSel) * 2;
                ldsm_x4(ah[mi], aH + off);
                ldsm_x4(al[mi], aL + off);
            }
            #pragma unroll
            for (int hf = 0; hf < 2; ++hf) {
                uint32_t off = ((wc * 32 + hf * 16 + bRowSel) * 24 + bKSel) * 2;
                uint32_t rh[4], rl[4];
                ldsm_x4(rh, bH + off);
                ldsm_x4(rl, bL + off);
                bh[hf*2][0] = rh[0]; bh[hf*2][1] = rh[1];
                bh[hf*2+1][0] = rh[2]; bh[hf*2+1][1] = rh[3];
                bl[hf*2][0] = rl[0]; bl[hf*2][1] = rl[1];
                bl[hf*2+1][0] = rl[2]; bl[hf*2+1][1] = rl[3];
            }
            #pragma unroll
            for (int mi = 0; mi < 2; ++mi)
                #pragma unroll
                for (int ni = 0; ni < 4; ++ni) {
                    MMA16816(acc[mi][ni], ah[mi], bh[ni]);
                    MMA16816(acc[mi][ni], ah[mi], bl[ni]);
                    MMA16816(acc[mi][ni], al[mi], bh[ni]);
                }
        }
        if (it < nk - 1) {
            int nb = buf ^ 1;
            __syncthreads();
            *(uint2*)(sm + 0     + nb * 3072 + sOff) = vAh;
            *(uint2*)(sm + 6144  + nb * 3072 + sOff) = vAl;
            *(uint2*)(sm + 12288 + nb * 6144 + sOff) = vBh0;
            *(uint2*)(sm + 12288 + nb * 6144 + sOff2) = vBh1;
            *(uint2*)(sm + 24576 + nb * 6144 + sOff) = vBl0;
            *(uint2*)(sm + 24576 + nb * 6144 + sOff2) = vBl1;
            __syncthreads();
            buf = nb;
        }
    }
    __syncthreads();   // mainloop buffers dead; overlay sAcc

    const int gr = lane >> 2, gk = (lane & 3) * 2;
    float* sAcc = (float*)sm;
    #pragma unroll
    for (int mi = 0; mi < 2; ++mi) {
        #pragma unroll
        for (int ni = 0; ni < 4; ++ni) {
            int r0 = wr * 32 + mi * 16 + gr;
            int c0 = wc * 32 + ni * 8 + gk;
            *(float2*)&sAcc[r0 * 132 + c0]       = make_float2(acc[mi][ni][0], acc[mi][ni][1]);
            *(float2*)&sAcc[(r0 + 8) * 132 + c0] = make_float2(acc[mi][ni][2], acc[mi][ni][3]);
        }
    }
    __syncthreads();
}

// ================= GCN GEMM (mma) + tanh + gate + combine ====================
__global__ __launch_bounds__(256) void gcn_mma(
    const float* __restrict__ wb, const float* __restrict__ gb,
    const float* __restrict__ gate_w, const float* __restrict__ gate_b,
    float* __restrict__ X)
{
    extern __shared__ char sm[];
    const int tid = threadIdx.x;
    const int rowBase = blockIdx.x * 64;
    mma3s_main(sm, g_NAhi, g_NAlo, DMv, 2*NUNIT - 1,
               g_WgcnHi, g_WgcnLo, DMv, rowBase, 0, 16);
    float* sAcc = (float*)sm;

    #pragma unroll
    for (int i = 0; i < 8; ++i) {
        int lin = tid + i * 256;
        int r = lin >> 5, c = (lin & 31) * 4;
        float4 v = *(const float4*)&sAcc[r * 132 + c];
        v.x = tanhf(v.x + wb[c]   + gb[c]);
        v.y = tanhf(v.y + wb[c+1] + gb[c+1]);
        v.z = tanhf(v.z + wb[c+2] + gb[c+2]);
        v.w = tanhf(v.w + wb[c+3] + gb[c+3]);
        *(float4*)&sAcc[r * 132 + c] = v;
    }
    __syncthreads();

    const int t = tid >> 3, sub = tid & 7;
    const int u = (rowBase >> 1) + t;
    if (u < NUNIT) {
        float gv = 0.f;
        #pragma unroll
        for (int k = 0; k < 16; ++k) {
            int c = sub*16 + k;
            gv += sAcc[(2*t) * 132 + c] * gate_w[c] + sAcc[(2*t+1) * 132 + c] * gate_w[128 + c];
        }
        gv += __shfl_xor_sync(0xffffffffu, gv, 1);
        gv += __shfl_xor_sync(0xffffffffu, gv, 2);
        gv += __shfl_xor_sync(0xffffffffu, gv, 4);
        float a = sigm(gv + gate_b[0]);
        int row, col;
        if (u < Bv)             { row = u;                      col = 0; }
        else if (u < 2*Bv)      { row = u - Bv;                 col = Dv; }
        else if (u < 2*Bv+FEWv) { row = Bv + (u - 2*Bv);        col = 0; }
        else                    { row = Bv + (u - 2*Bv - FEWv); col = Dv; }
        size_t xo = (size_t)row * DMv + col;
        #pragma unroll
        for (int k4 = 0; k4 < 4; ++k4) {
            int c = sub*16 + k4*4;
            float4 st = *(const float4*)&sAcc[(2*t) * 132 + c];
            float4 kn = *(const float4*)&sAcc[(2*t+1) * 132 + c];
            float4 o;
            o.x = (1.f - a)*st.x + a*kn.x;
            o.y = (1.f - a)*st.y + a*kn.y;
            o.z = (1.f - a)*st.z + a*kn.z;
            o.w = (1.f - a)*st.w + a*kn.w;
            *(float4*)(X + xo + c) = o;
            split_store4(o, g_XAhi, g_XAlo, xo + c);
        }
    }
}

// ================= p1 GEMM (mma) + relu, emit H splits =======================
__global__ __launch_bounds__(256) void p1_mma(const float* __restrict__ p1_b)
{
    extern __shared__ char sm[];
    const int tid = threadIdx.x;
    const int rowBase = blockIdx.y * 64;
    const int colBase = blockIdx.x * 128;
    mma3s_main(sm, g_XAhi, g_XAlo, DMv, NROWS - 1,
               g_Wp1Hi, g_Wp1Lo, DMv, rowBase, colBase, 16);
    float* sAcc = (float*)sm;
    #pragma unroll
    for (int i = 0; i < 8; ++i) {
        int lin = tid + i * 256;
        int r = lin >> 5, cl = (lin & 31) * 4;
        int row = rowBase + r;
        if (row >= NROWS) continue;
        int c = colBase + cl;
        float4 v = *(const float4*)&sAcc[r * 132 + cl];
        v.x = fmaxf(v.x + p1_b[c],   0.f);
        v.y = fmaxf(v.y + p1_b[c+1], 0.f);
        v.z = fmaxf(v.z + p1_b[c+2], 0.f);
        v.w = fmaxf(v.w + p1_b[c+3], 0.f);
        split_store4(v, g_Hshi, g_Hslo, (size_t)row * HIDv + c);
    }
}

// ================= p2 GEMM (mma) + bias -> O fp32 ============================
__global__ __launch_bounds__(256) void p2_mma(const float* __restrict__ p2_b)
{
    extern __shared__ char sm[];
    const int tid = threadIdx.x;
    const int rowBase = blockIdx.y * 64;
    const int colBase = blockIdx.x * 128;
    mma3s_main(sm, g_Hshi, g_Hslo, HIDv, NROWS - 1,
               g_Wp2Hi, g_Wp2Lo, HIDv, rowBase, colBase, 32);
    float* sAcc = (float*)sm;
    #pragma unroll
    for (int i = 0; i < 8; ++i) {
        int lin = tid + i * 256;
        int r = lin >> 5, cl = (lin & 31) * 4;
        int row = rowBase + r;
        if (row >= NROWS) continue;
        int c = colBase + cl;
        float4 v = *(const float4*)&sAcc[r * 132 + cl];
        v.x += p2_b[c]; v.y += p2_b[c+1]; v.z += p2_b[c+2]; v.w += p2_b[c+3];
        *(float4*)&g_O[(size_t)row * DMv + c] = v;
    }
}

// ================= gate GEMM (mma) + fused LSTM cell =========================
__global__ __launch_bounds__(256) void gates_mma(
    const __nv_bfloat16* __restrict__ Ahi, const __nv_bfloat16* __restrict__ Alo,
    const __nv_bfloat16* __restrict__ Whi, const __nv_bfloat16* __restrict__ Wlo,
    int first)
{
    extern __shared__ char sm[];
    const int tid = threadIdx.x;
    const int rowBase = blockIdx.y * 64;
    const int colBase = blockIdx.x * 128;
    const int jbase = colBase >> 2;
    mma3s_main(sm, Ahi, Alo, DMv, Bv - 1, Whi, Wlo, DMv, rowBase, colBase, 16);
    float* sAcc = (float*)sm;

    #pragma unroll
    for (int i = 0; i < 8; ++i) {
        int lin = tid + i * 256;
        int r = lin >> 5, jl = lin & 31;
        float4 gv = *(const float4*)&sAcc[r * 132 + jl * 4];
        int row = rowBase + r;
        int colp = colBase + jl * 4;
        float gi = gv.x, gf = gv.y, gg = gv.z, go = gv.w;
        size_t g0i = (size_t)row * G4 + colp;
        if (first) {
            gi += g_b4[colp]; gf += g_b4[colp+1]; gg += g_b4[colp+2]; go += g_b4[colp+3];
            *(float4*)&g_G0[g0i] = make_float4(gi, gf, gg, go);
        } else {
            float4 g0 = *(const float4*)&g_G0[g0i];
            gi += g0.x + g_rt4[colp];   gf += g0.y + g_rt4[colp+1];
            gg += g0.z + g_rt4[colp+2]; go += g0.w + g_rt4[colp+3];
        }
        size_t ci = (size_t)row * DMv + jbase + jl;
        float cold = first ? 0.f : g_C[ci];
        float cv = sigm(gf) * cold + sigm(gi) * tanhf(gg);
        g_C[ci] = cv;
        float h = g_X[ci] + sigm(go) * tanhf(cv);
        g_h[ci] = h;
        __nv_bfloat16 hb = __float2bfloat16(h);
        g_hhi[ci] = hb;
        g_hlo[ci] = __float2bfloat16(h - __bfloat162float(hb));
    }
}

// ---------------- residual + layernorm (+ bf16 split emit for query rows) ---
__global__ void posln_kernel(const float* __restrict__ O, float* __restrict__ X,
                             const float* __restrict__ g, const float* __restrict__ b)
{
    __shared__ float s_red[8];
    const int r = blockIdx.x, t = threadIdx.x;
    const int lane = t & 31, w = t >> 5;
    float z = O[(size_t)r * DMv + t] + X[(size_t)r * DMv + t];
    float v = z;
    #pragma unroll
    for (int o = 16; o; o >>= 1) v += __shfl_xor_sync(0xffffffffu, v, o);
    if (lane == 0) s_red[w] = v;
    __syncthreads();
    float mu = 0.f;
    #pragma unroll
    for (int i = 0; i < 8; ++i) mu += s_red[i];
    mu *= (1.f / 256.f);
    __syncthreads();
    float d = z - mu;
    v = d * d;
    #pragma unroll
    for (int o = 16; o; o >>= 1) v += __shfl_xor_sync(0xffffffffu, v, o);
    if (lane == 0) s_red[w] = v;
    __syncthreads();
    float var = 0.f;
    #pragma unroll
    for (int i = 0; i < 8; ++i) var += s_red[i];
    var *= (1.f / 255.f);
    float y = d / (sqrtf(var) + 1e-3f) * g[t] + b[t];
    X[(size_t)r * DMv + t] = y;
    if (r < Bv) {
        __nv_bfloat16 hi = __float2bfloat16(y);
        g_Xhi[(size_t)r * DMv + t] = hi;
        g_Xlo[(size_t)r * DMv + t] = __float2bfloat16(y - __bfloat162float(hi));
    }
}

// ---------------- support_g + l2 normalization ------------------------------
__global__ void sg_kernel(const float* __restrict__ X)
{
    __shared__ float s_red[8];
    const int t = threadIdx.x, lane = t & 31, w = t >> 5;
    float s = 0.f;
    #pragma unroll
    for (int i = 0; i < FEWv; ++i) s += X[(size_t)(Bv + i) * DMv + t];
    s *= (1.f / (float)FEWv);
    g_sg[t] = s;
    float v = s * s;
    #pragma unroll
    for (int o = 16; o; o >>= 1) v += __shfl_xor_sync(0xffffffffu, v, o);
    if (lane == 0) s_red[w] = v;
    __syncthreads();
    float nn = 0.f;
    #pragma unroll
    for (int i = 0; i < 8; ++i) nn += s_red[i];
    g_sgn[t] = s / fmaxf(sqrtf(nn), 1e-12f);
}

// ---------------- rt4[4j+g] = w_hh[g*512+j, 256:512] @ support_g ------------
__global__ void rterm_kernel(const float* __restrict__ w_hh)
{
    const int t = threadIdx.x, lane = t & 31, w = t >> 5;
    const int o = blockIdx.x * 8 + w;
    const int j = o >> 2, gate = o & 3;
    const float* wr = w_hh + (size_t)(gate * 512 + j) * HIDv + DMv;
    float s = 0.f;
    #pragma unroll
    for (int q = 0; q < 8; ++q) s += g_sg[lane + q * 32] * wr[lane + q * 32];
    #pragma unroll
    for (int off = 16; off; off >>= 1) s += __shfl_xor_sync(0xffffffffu, s, off);
    if (lane == 0) g_rt4[o] = s;
}

// ---------------- final cosine against normalized support_g ----------------
__global__ void final_kernel(float* __restrict__ out)
{
    __shared__ float s_red[16];
    const int b = blockIdx.x, t = threadIdx.x, lane = t & 31, w = t >> 5;
    float hv = g_h[(size_t)b * DMv + t];
    float d = hv * g_sgn[t];
    float ss = hv * hv;
    #pragma unroll
    for (int o = 16; o; o >>= 1) {
        d  += __shfl_xor_sync(0xffffffffu, d,  o);
        ss += __shfl_xor_sync(0xffffffffu, ss, o);
    }
    if (lane == 0) { s_red[w] = d; s_red[8 + w] = ss; }
    __syncthreads();
    if (t == 0) {
        float Dd = 0.f, S = 0.f;
        #pragma unroll
        for (int i = 0; i < 8; ++i) { Dd += s_red[i]; S += s_red[8 + i]; }
        out[b] = Dd / fmaxf(sqrtf(S), 1e-12f);
    }
}

// ---------------- launcher ---------------------------------------------------
extern "C" void kernel_launch(void* const* d_in, const int* in_sizes, int n_in,
                              void* d_out, int out_size)
{
    const int*   query    = (const int*)  d_in[0];
    const int*   support  = (const int*)  d_in[1];
    const int*   q_l_conn = (const int*)  d_in[2];
    const int*   q_r_conn = (const int*)  d_in[4];
    const int*   s_l_conn = (const int*)  d_in[6];
    const int*   s_r_conn = (const int*)  d_in[8];
    const int*   knn      = (const int*)  d_in[10];
    const float* emb      = (const float*)d_in[11];
    const float* gcn_w    = (const float*)d_in[12];
    const float* gcn_wb   = (const float*)d_in[13];
    const float* gcn_b    = (const float*)d_in[14];
    const float* gate_w   = (const float*)d_in[15];
    const float* gate_b   = (const float*)d_in[16];
    const float* p1_w     = (const float*)d_in[17];
    const float* p1_b     = (const float*)d_in[18];
    const float* p2_w     = (const float*)d_in[19];
    const float* p2_b     = (const float*)d_in[20];
    const float* ln_g     = (const float*)d_in[21];
    const float* ln_b     = (const float*)d_in[22];
    const float* w_ih     = (const float*)d_in[23];
    const float* w_hh     = (const float*)d_in[24];
    const float* b_ih     = (const float*)d_in[25];
    const float* b_hh     = (const float*)d_in[26];

    float *pX, *pO;
    __nv_bfloat16 *pXhi, *pXlo, *phhi, *phlo, *pWihHi, *pWihLo, *pWhhHi, *pWhhLo;
    cudaGetSymbolAddress((void**)&pX,  g_X);
    cudaGetSymbolAddress((void**)&pO,  g_O);
    cudaGetSymbolAddress((void**)&pXhi, g_Xhi);
    cudaGetSymbolAddress((void**)&pXlo, g_Xlo);
    cudaGetSymbolAddress((void**)&phhi, g_hhi);
    cudaGetSymbolAddress((void**)&phlo, g_hlo);
    cudaGetSymbolAddress((void**)&pWihHi, g_WihHi);
    cudaGetSymbolAddress((void**)&pWihLo, g_WihLo);
    cudaGetSymbolAddress((void**)&pWhhHi, g_WhhHi);
    cudaGetSymbolAddress((void**)&pWhhLo, g_WhhLo);

    // 0) weight packing (independent)
    pack_w<<<G4, 256>>>(w_ih, w_hh, b_ih, b_hh);
    pack_se<<<Dv + HIDv + DMv, 256>>>(gcn_w, p1_w, p2_w);

    // 1) neighbor encoder sims/topk/means -> NA bf16 splits [8212, 256]
    ne_sims<<<NUNIT, 256>>>(query, support, q_l_conn, q_r_conn, s_l_conn, s_r_conn,
                            knn, emb);
    // 2) GCN GEMM (mma/ldmatrix) + tanh + gate + combine -> X fp32 + X splits
    gcn_mma<<<(2*NUNIT + 63)/64, 256, SMEM_MMA>>>(gcn_wb, gcn_b, gate_w, gate_b, pX);

    // 3) support encoder: p1 (mma, relu -> H splits), p2 (mma -> O), LN
    p1_mma<<<dim3(HIDv/128, (NROWS + 63)/64), 256, SMEM_MMA>>>(p1_b);
    p2_mma<<<dim3(DMv/128, (NROWS + 63)/64), 256, SMEM_MMA>>>(p2_b);
    posln_kernel<<<NROWS, 256>>>(pO, pX, ln_g, ln_b);

    // 4) support_g, normalization, reduced interleaved r-term
    sg_kernel<<<1, 256>>>(pX);
    rterm_kernel<<<G4/8, 256>>>(w_hh);

    // 5) LSTM steps on mma.sync bf16 (3x split), fused cell epilogue
    gates_mma<<<dim3(G4/128, Bv/64), 256, SMEM_MMA>>>(pXhi, pXlo, pWihHi, pWihLo, 1);
    for (int s = 0; s < 3; ++s)
        gates_mma<<<dim3(G4/128, Bv/64), 256, SMEM_MMA>>>(phhi, phlo, pWhhHi, pWhhLo, 0);

    // 6) out[b] = l2n(h[b]) . l2n(support_g)
    final_kernel<<<Bv, 256>>>((float*)d_out);

    (void)in_sizes; (void)n_in; (void)out_size;
}